// round 1
// baseline (speedup 1.0000x reference)
#include <cuda_runtime.h>

namespace {

constexpr int Bn = 2, Tn = 2111, Qn = 2048, Cn = 64, Hn = 8, Dn = 64, DMn = 512;

// Scratch (device globals: allocation-free per harness rules)
__device__ float g_kv[Bn * Tn * 1024];     // k_all | v_all packed, 17.3 MB
__device__ float g_hq[Bn * Qn * 512];      // 8.4 MB
__device__ float g_hr[Cn * 512];
__device__ float g_att[Bn * Qn * 512];     // 8.4 MB
__device__ unsigned char g_mask[Bn * (Cn - 1)];

// ---------------------------------------------------------------------------
// pad mask: x[b,t,:] all-zero for t < C-1
// ---------------------------------------------------------------------------
__global__ void mask_kernel(const float* __restrict__ x) {
    int t = blockIdx.x, b = blockIdx.y;
    const float* row = x + ((size_t)b * Tn + t) * DMn;
    int zero = 1;
    for (int i = threadIdx.x; i < DMn; i += blockDim.x)
        if (row[i] != 0.f) zero = 0;
    int all = __syncthreads_and(zero);
    if (threadIdx.x == 0) g_mask[b * (Cn - 1) + t] = (unsigned char)(all != 0);
}

// ---------------------------------------------------------------------------
// Generic fp32 SGEMM: C[M,N] = A[M,K] * B[K,N] (+bias). 128x128x16 tiles,
// 256 threads, 8x8 microtile. ROWMAP remaps A row m -> x row b*T + 63 + q
// (used for hq which reads x[:, C-1:]).
// ---------------------------------------------------------------------------
constexpr int BM = 128, BN = 128, BK = 16, TM = 8, TN = 8;

template <bool ROWMAP, bool BIAS>
__global__ __launch_bounds__(256) void sgemm_kernel(
    const float* __restrict__ A, const float* __restrict__ Bw,
    const float* __restrict__ bias, float* __restrict__ Co,
    int M, int N, int K)
{
    __shared__ __align__(16) float As[BK][BM + 4];  // transposed, padded
    __shared__ __align__(16) float Bs[BK][BN];
    int row0 = blockIdx.y * BM, col0 = blockIdx.x * BN;
    int tid = threadIdx.x;
    int tr = tid >> 4, tc = tid & 15;
    float acc[TM][TN] = {};

    for (int k0 = 0; k0 < K; k0 += BK) {
#pragma unroll
        for (int i = 0; i < 2; i++) {
            int li = tid + i * 256;
            int m = li >> 2, k4 = (li & 3) << 2;
            float4 v = make_float4(0.f, 0.f, 0.f, 0.f);
            int gm = row0 + m;
            if (gm < M) {
                int ar = ROWMAP ? ((gm >> 11) * Tn + (Cn - 1) + (gm & (Qn - 1))) : gm;
                v = *(const float4*)(A + (size_t)ar * K + k0 + k4);
            }
            As[k4 + 0][m] = v.x; As[k4 + 1][m] = v.y;
            As[k4 + 2][m] = v.z; As[k4 + 3][m] = v.w;
        }
#pragma unroll
        for (int i = 0; i < 2; i++) {
            int li = tid + i * 256;
            int kk = li >> 5, n4 = (li & 31) << 2;
            *(float4*)(&Bs[kk][n4]) = *(const float4*)(Bw + (size_t)(k0 + kk) * N + col0 + n4);
        }
        __syncthreads();
#pragma unroll
        for (int kk = 0; kk < BK; kk++) {
            float a[TM], bb[TN];
            float4 v;
            v = *(const float4*)(&As[kk][tr * TM]);     a[0]=v.x; a[1]=v.y; a[2]=v.z; a[3]=v.w;
            v = *(const float4*)(&As[kk][tr * TM + 4]); a[4]=v.x; a[5]=v.y; a[6]=v.z; a[7]=v.w;
            v = *(const float4*)(&Bs[kk][tc * TN]);     bb[0]=v.x; bb[1]=v.y; bb[2]=v.z; bb[3]=v.w;
            v = *(const float4*)(&Bs[kk][tc * TN + 4]); bb[4]=v.x; bb[5]=v.y; bb[6]=v.z; bb[7]=v.w;
#pragma unroll
            for (int i = 0; i < TM; i++)
#pragma unroll
                for (int j = 0; j < TN; j++)
                    acc[i][j] = fmaf(a[i], bb[j], acc[i][j]);
        }
        __syncthreads();
    }

#pragma unroll
    for (int i = 0; i < TM; i++) {
        int gm = row0 + tr * TM + i;
        if (gm >= M) continue;
#pragma unroll
        for (int j = 0; j < TN; j += 4) {
            int gn = col0 + tc * TN + j;
            float4 v = make_float4(acc[i][j], acc[i][j + 1], acc[i][j + 2], acc[i][j + 3]);
            if (BIAS) {
                v.x += bias[gn]; v.y += bias[gn + 1];
                v.z += bias[gn + 2]; v.w += bias[gn + 3];
            }
            *(float4*)(Co + (size_t)gm * N + gn) = v;
        }
    }
}

// ---------------------------------------------------------------------------
// Sliding-window attention. One block per (b, h, 64-query tile).
// Band trick: S[q][c] = Hq[q]·K[q+c] -> dense 64x128 GEMM over j=q+c, with
// the 64 hr columns appended (total 64x192x64 GEMM). Softmax per row (warp),
// weights stored transposed sWT[j][q] (zero outside band), then the output
// O[q][d] = sum_j W[q][j] V[j][d] is a dense 64x64x128 GEMM.
// ---------------------------------------------------------------------------
constexpr int S_HQ = 0;                      // sHqT [64][68]  (d-major)
constexpr int S_KT = S_HQ + 64 * 68;         // sKT  [64][196] cols 0..126 K, 128..191 hr
constexpr int S_V  = S_KT + 64 * 196;        // sV   [128][68] (j-major)
constexpr int S_S  = S_V + 128 * 68;         // sS   [64][196] raw scores
constexpr int S_WT = S_S + 64 * 196;         // sWT  [128][68] softmax weights^T
constexpr int ATT_SMEM_FLOATS = S_WT + 128 * 68;   // 46848 floats = 183 KB

__global__ __launch_bounds__(256) void attn_kernel() {
    extern __shared__ __align__(16) float sm[];
    float* sHqT = sm + S_HQ;
    float* sKT  = sm + S_KT;
    float* sV   = sm + S_V;
    float* sS   = sm + S_S;
    float* sWT  = sm + S_WT;

    int q0 = blockIdx.x * 64;
    int h = blockIdx.y, b = blockIdx.z;
    int tid = threadIdx.x;

    // zero weight matrix (only band entries get filled later)
    for (int i = tid; i < 128 * 68; i += 256) sWT[i] = 0.f;

    // Hq tile -> transposed [d][q]
    for (int li = tid; li < 1024; li += 256) {
        int q = li >> 4, d4 = (li & 15) << 2;
        float4 v = *(const float4*)(g_hq + (size_t)(b * Qn + q0 + q) * 512 + h * 64 + d4);
        sHqT[(d4 + 0) * 68 + q] = v.x; sHqT[(d4 + 1) * 68 + q] = v.y;
        sHqT[(d4 + 2) * 68 + q] = v.z; sHqT[(d4 + 3) * 68 + q] = v.w;
    }
    // K window rows j=0..126 -> sKT[d][j]; j=127 zero pad
    for (int li = tid; li < 2048; li += 256) {
        int j = li >> 4, d4 = (li & 15) << 2;
        float4 v = make_float4(0.f, 0.f, 0.f, 0.f);
        if (j < 127) v = *(const float4*)(g_kv + (size_t)(b * Tn + q0 + j) * 1024 + h * 64 + d4);
        sKT[(d4 + 0) * 196 + j] = v.x; sKT[(d4 + 1) * 196 + j] = v.y;
        sKT[(d4 + 2) * 196 + j] = v.z; sKT[(d4 + 3) * 196 + j] = v.w;
    }
    // hr -> sKT[d][128+c]
    for (int li = tid; li < 1024; li += 256) {
        int c = li >> 4, d4 = (li & 15) << 2;
        float4 v = *(const float4*)(g_hr + (size_t)c * 512 + h * 64 + d4);
        sKT[(d4 + 0) * 196 + 128 + c] = v.x; sKT[(d4 + 1) * 196 + 128 + c] = v.y;
        sKT[(d4 + 2) * 196 + 128 + c] = v.z; sKT[(d4 + 3) * 196 + 128 + c] = v.w;
    }
    // V window rows j=0..126 row-major
    for (int li = tid; li < 2048; li += 256) {
        int j = li >> 4, d4 = (li & 15) << 2;
        float4 v = make_float4(0.f, 0.f, 0.f, 0.f);
        if (j < 127) v = *(const float4*)(g_kv + (size_t)(b * Tn + q0 + j) * 1024 + 512 + h * 64 + d4);
        *(float4*)(sV + j * 68 + d4) = v;
    }
    __syncthreads();

    int tr = tid >> 4, tc = tid & 15;   // 16x16 thread grid

    // Score GEMM: 64(q) x 192(j|c) x 64(d); per-thread 4x12 microtile
    {
        float acc[4][12] = {};
#pragma unroll 4
        for (int d = 0; d < 64; d++) {
            float4 av = *(const float4*)(sHqT + d * 68 + tr * 4);
            float a[4] = {av.x, av.y, av.z, av.w};
            float bb[12];
#pragma unroll
            for (int m = 0; m < 3; m++) {
                float4 bv = *(const float4*)(sKT + d * 196 + tc * 12 + m * 4);
                bb[m * 4 + 0] = bv.x; bb[m * 4 + 1] = bv.y;
                bb[m * 4 + 2] = bv.z; bb[m * 4 + 3] = bv.w;
            }
#pragma unroll
            for (int i = 0; i < 4; i++)
#pragma unroll
                for (int j = 0; j < 12; j++)
                    acc[i][j] = fmaf(a[i], bb[j], acc[i][j]);
        }
#pragma unroll
        for (int i = 0; i < 4; i++)
#pragma unroll
            for (int m = 0; m < 3; m++)
                *(float4*)(sS + (tr * 4 + i) * 196 + tc * 12 + m * 4) =
                    make_float4(acc[i][m * 4 + 0], acc[i][m * 4 + 1],
                                acc[i][m * 4 + 2], acc[i][m * 4 + 3]);
    }
    __syncthreads();

    // Softmax: warp w owns rows q = w*8 .. w*8+7; lane handles c and c+32
    {
        int lane = tid & 31, w = tid >> 5;
#pragma unroll
        for (int r = 0; r < 8; r++) {
            int q = w * 8 + r;
            int c0 = lane, c1 = lane + 32;
            float s0 = (sS[q * 196 + q + c0] + sS[q * 196 + 128 + c0]) * 0.125f;
            float s1 = (sS[q * 196 + q + c1] + sS[q * 196 + 128 + c1]) * 0.125f;
            int jg0 = q0 + q + c0, jg1 = q0 + q + c1;
            if (jg0 < Cn - 1 && g_mask[b * (Cn - 1) + jg0]) s0 = -1e30f;
            if (jg1 < Cn - 1 && g_mask[b * (Cn - 1) + jg1]) s1 = -1e30f;
            float mx = fmaxf(s0, s1);
#pragma unroll
            for (int o = 16; o; o >>= 1) mx = fmaxf(mx, __shfl_xor_sync(0xffffffffu, mx, o));
            float e0 = __expf(s0 - mx), e1 = __expf(s1 - mx);
            float sum = e0 + e1;
#pragma unroll
            for (int o = 16; o; o >>= 1) sum += __shfl_xor_sync(0xffffffffu, sum, o);
            float inv = 1.f / sum;
            sWT[(q + c0) * 68 + q] = e0 * inv;
            sWT[(q + c1) * 68 + q] = e1 * inv;
        }
    }
    __syncthreads();

    // Output GEMM: O[64 q][64 d] = W^T-band * V, K-dim = 128 j; 4x4 microtile
    {
        float o[4][4] = {};
#pragma unroll 4
        for (int j = 0; j < 128; j++) {
            float4 av = *(const float4*)(sWT + j * 68 + tr * 4);
            float4 bv = *(const float4*)(sV + j * 68 + tc * 4);
            float a[4] = {av.x, av.y, av.z, av.w};
            float bb[4] = {bv.x, bv.y, bv.z, bv.w};
#pragma unroll
            for (int i = 0; i < 4; i++)
#pragma unroll
                for (int jj = 0; jj < 4; jj++)
                    o[i][jj] = fmaf(a[i], bb[jj], o[i][jj]);
        }
#pragma unroll
        for (int i = 0; i < 4; i++) {
            int q = tr * 4 + i;
            *(float4*)(g_att + (size_t)(b * Qn + q0 + q) * 512 + h * 64 + tc * 4) =
                make_float4(o[i][0], o[i][1], o[i][2], o[i][3]);
        }
    }
}

}  // namespace

// ---------------------------------------------------------------------------
extern "C" void kernel_launch(void* const* d_in, const int* in_sizes, int n_in,
                              void* d_out, int out_size) {
    const float* x   = (const float*)d_in[0];
    const float* r   = (const float*)d_in[1];
    const float* Wkv = (const float*)d_in[2];
    const float* Wq  = (const float*)d_in[3];
    const float* bq  = (const float*)d_in[4];
    const float* Wr  = (const float*)d_in[5];
    const float* Wo  = (const float*)d_in[6];
    float* out = (float*)d_out;

    float *kvp, *hqp, *hrp, *attp;
    cudaGetSymbolAddress((void**)&kvp,  g_kv);
    cudaGetSymbolAddress((void**)&hqp,  g_hq);
    cudaGetSymbolAddress((void**)&hrp,  g_hr);
    cudaGetSymbolAddress((void**)&attp, g_att);

    cudaFuncSetAttribute(attn_kernel, cudaFuncAttributeMaxDynamicSharedMemorySize,
                         ATT_SMEM_FLOATS * (int)sizeof(float));

    // 1. pad mask
    mask_kernel<<<dim3(Cn - 1, Bn), 128>>>(x);
    // 2. kv = x @ Wkv                     [4222 x 512 x 1024]
    sgemm_kernel<false, false><<<dim3(1024 / BN, (Bn * Tn + BM - 1) / BM), 256>>>(
        x, Wkv, nullptr, kvp, Bn * Tn, 1024, 512);
    // 3. hq = x[:,63:] @ Wq + bq          [4096 x 512 x 512]
    sgemm_kernel<true, true><<<dim3(512 / BN, (Bn * Qn) / BM), 256>>>(
        x, Wq, bq, hqp, Bn * Qn, 512, 512);
    // 4. hr = r @ Wr                      [64 x 512 x 512]
    sgemm_kernel<false, false><<<dim3(512 / BN, 1), 256>>>(
        r, Wr, nullptr, hrp, Cn, 512, 512);
    // 5. attention                        [512 blocks]
    attn_kernel<<<dim3(Qn / 64, Hn, Bn), 256, ATT_SMEM_FLOATS * sizeof(float)>>>();
    // 6. out = att @ Wo                   [4096 x 512 x 512]
    sgemm_kernel<false, false><<<dim3(512 / BN, (Bn * Qn) / BM), 256>>>(
        attp, Wo, nullptr, out, Bn * Qn, 512, 512);
}

// round 3
// speedup vs baseline: 1.1723x; 1.1723x over previous
#include <cuda_runtime.h>
#include <cuda_fp16.h>
#include <cstdint>

namespace {

constexpr int Bn = 2, Tn = 2111, Qn = 2048, Cn = 64, Hn = 8, DMn = 512;
constexpr int K2 = 1536;   // 3 * 512 (split-K trick)

// Scratch (device globals)
__device__ float g_kv[Bn * Tn * 1024];
__device__ float g_hq[Bn * Qn * 512];
__device__ float g_hr[Cn * 512];
__device__ unsigned char g_mask[Bn * (Cn - 1)];
__device__ __half g_xh[(size_t)Bn * Tn * K2];
__device__ __half g_rh[Cn * K2];
__device__ __half g_atth[(size_t)Bn * Qn * K2];
__device__ __half g_Wkvh[K2 * 1024];
__device__ __half g_Wqh[K2 * 512];
__device__ __half g_Wrh[K2 * 512];
__device__ __half g_Woh[K2 * 512];

// ===========================================================================
// PTX helpers
// ===========================================================================
__device__ __forceinline__ uint32_t smem_u32(const void* p) {
    uint32_t a;
    asm("{ .reg .u64 t; cvta.to.shared.u64 t, %1; cvt.u32.u64 %0, t; }" : "=r"(a) : "l"(p));
    return a;
}
__device__ __forceinline__ void cpa16(uint32_t d, const void* s, int sz) {
    asm volatile("cp.async.cg.shared.global [%0], [%1], 16, %2;" :: "r"(d), "l"(s), "r"(sz));
}
__device__ __forceinline__ void cp_commit() { asm volatile("cp.async.commit_group;"); }
template <int N> __device__ __forceinline__ void cp_wait() {
    asm volatile("cp.async.wait_group %0;" :: "n"(N));
}
__device__ __forceinline__ void ldsm4(uint32_t* r, uint32_t a) {
    asm volatile("ldmatrix.sync.aligned.m8n8.x4.shared.b16 {%0,%1,%2,%3}, [%4];"
                 : "=r"(r[0]), "=r"(r[1]), "=r"(r[2]), "=r"(r[3]) : "r"(a));
}
__device__ __forceinline__ void ldsm4t(uint32_t* r, uint32_t a) {
    asm volatile("ldmatrix.sync.aligned.m8n8.x4.trans.shared.b16 {%0,%1,%2,%3}, [%4];"
                 : "=r"(r[0]), "=r"(r[1]), "=r"(r[2]), "=r"(r[3]) : "r"(a));
}
__device__ __forceinline__ void mma16816(float* d, const uint32_t* a, uint32_t b0, uint32_t b1) {
    asm volatile(
        "mma.sync.aligned.m16n8k16.row.col.f32.f16.f16.f32 "
        "{%0,%1,%2,%3}, {%4,%5,%6,%7}, {%8,%9}, {%0,%1,%2,%3};"
        : "+f"(d[0]), "+f"(d[1]), "+f"(d[2]), "+f"(d[3])
        : "r"(a[0]), "r"(a[1]), "r"(a[2]), "r"(a[3]), "r"(b0), "r"(b1));
}

// ===========================================================================
// HGEMM: C[M,N] = A''[M,K2] @ B''[K2,N] (+bias), fp16 in, fp32 out.
// 128x128x32 tile, 256 threads (8 warps 4x2), 3-stage cp.async pipeline.
// ===========================================================================
constexpr int ASTG = 128 * 128;   // bytes per A stage (128 rows x 128B, swizzled)
constexpr int BSTG = 32 * 256;    // bytes per B stage (32 rows x 256B, swizzled)
constexpr int STG = ASTG + BSTG;  // 24576
constexpr int NSTAGE = 3;
constexpr int HG_SMEM = STG * NSTAGE;  // 73728

template <bool ROWMAP, bool BIAS>
__global__ __launch_bounds__(256, 2) void hgemm_kernel(
    const __half* __restrict__ A, const __half* __restrict__ Bw,
    const float* __restrict__ bias, float* __restrict__ C, int M, int N)
{
    extern __shared__ char smm[];
    uint32_t sb = smem_u32(smm);
    int tid = threadIdx.x, lane = tid & 31, wid = tid >> 5;
    int wm = wid >> 1, wn = wid & 1;
    int row0 = blockIdx.y * 128, col0 = blockIdx.x * 128;

    // ---- per-thread cp.async coordinates (2 A chunks, 2 B chunks / stage) ----
    int c0 = tid, c1 = tid + 256;
    int rA0 = c0 >> 2, cA0 = c0 & 3;
    int rA1 = c1 >> 2, cA1 = c1 & 3;
    int gm0 = row0 + rA0, gm1 = row0 + rA1;
    int av0 = (gm0 < M) ? 16 : 0, av1 = (gm1 < M) ? 16 : 0;
    size_t arow0 = 0, arow1 = 0;
    if (gm0 < M) arow0 = ROWMAP ? (size_t)((gm0 >> 11) * Tn + (Cn - 1) + (gm0 & (Qn - 1))) : (size_t)gm0;
    if (gm1 < M) arow1 = ROWMAP ? (size_t)((gm1 >> 11) * Tn + (Cn - 1) + (gm1 & (Qn - 1))) : (size_t)gm1;
    const __half* asrc0 = A + arow0 * K2 + cA0 * 8;
    const __half* asrc1 = A + arow1 * K2 + cA1 * 8;
    uint32_t adst0 = rA0 * 128 + (((cA0 + rA0) & 7) << 4);
    uint32_t adst1 = rA1 * 128 + (((cA1 + rA1) & 7) << 4);

    int rB0 = c0 >> 4, cB0 = c0 & 15;
    int rB1 = c1 >> 4, cB1 = c1 & 15;
    const __half* bsrc0 = Bw + (size_t)rB0 * N + col0 + cB0 * 8;
    const __half* bsrc1 = Bw + (size_t)rB1 * N + col0 + cB1 * 8;
    uint32_t bdst0 = ASTG + rB0 * 256 + ((cB0 ^ (rB0 & 7)) << 4);
    uint32_t bdst1 = ASTG + rB1 * 256 + ((cB1 ^ (rB1 & 7)) << 4);

    auto load_stage = [&](int s, int kt) {
        int k0 = kt * 32;
        uint32_t base = sb + s * STG;
        cpa16(base + adst0, asrc0 + k0, av0);
        cpa16(base + adst1, asrc1 + k0, av1);
        cpa16(base + bdst0, bsrc0 + (size_t)k0 * N, 16);
        cpa16(base + bdst1, bsrc1 + (size_t)k0 * N, 16);
        cp_commit();
    };

    constexpr int KT = K2 / 32;  // 48
    load_stage(0, 0);
    load_stage(1, 1);

    float acc[2][8][4] = {};

    // precompute ldsm base offsets (loop-invariant parts)
    int la_r0 = wm * 32 + (lane & 15);          // mf adds +16
    int la_cbase = (lane >> 4);                 // kk adds +2
    int lb_rbase = (lane & 15);                 // kk adds +16
    int lb_cbase = wn * 8 + (lane >> 4);        // nf adds +2

    for (int kt = 0; kt < KT; kt++) {
        cp_wait<1>();
        __syncthreads();
        int s = kt % NSTAGE;
        uint32_t aB = sb + s * STG;
        uint32_t bB = aB + ASTG;
#pragma unroll
        for (int kk = 0; kk < 2; kk++) {
            uint32_t a[2][4];
#pragma unroll
            for (int mf = 0; mf < 2; mf++) {
                int r = la_r0 + mf * 16;
                int c = la_cbase + kk * 2;
                ldsm4(a[mf], aB + r * 128 + (((c + r) & 7) << 4));
            }
            uint32_t b[4][4];
#pragma unroll
            for (int nf = 0; nf < 4; nf++) {
                int r = lb_rbase + kk * 16;
                int c = lb_cbase + nf * 2;
                ldsm4t(b[nf], bB + r * 256 + ((c ^ (r & 7)) << 4));
            }
#pragma unroll
            for (int mf = 0; mf < 2; mf++)
#pragma unroll
                for (int nf = 0; nf < 4; nf++) {
                    mma16816(acc[mf][nf * 2],     a[mf], b[nf][0], b[nf][1]);
                    mma16816(acc[mf][nf * 2 + 1], a[mf], b[nf][2], b[nf][3]);
                }
        }
        if (kt + 2 < KT) load_stage((kt + 2) % NSTAGE, kt + 2);
        else cp_commit();   // keep group count consistent for cp_wait<1>
        __syncthreads();
    }

    // ---- epilogue ----
#pragma unroll
    for (int mf = 0; mf < 2; mf++) {
        int rb = row0 + wm * 32 + mf * 16 + (lane >> 2);
#pragma unroll
        for (int nf = 0; nf < 8; nf++) {
            int cb = col0 + wn * 64 + nf * 8 + (lane & 3) * 2;
            float* a4 = acc[mf][nf];
            float bx = 0.f, by = 0.f;
            if (BIAS) { bx = bias[cb]; by = bias[cb + 1]; }
            if (rb < M)
                *(float2*)(C + (size_t)rb * N + cb) = make_float2(a4[0] + bx, a4[1] + by);
            if (rb + 8 < M)
                *(float2*)(C + (size_t)(rb + 8) * N + cb) = make_float2(a4[2] + bx, a4[3] + by);
        }
    }
}

// ===========================================================================
// split-fp16 conversion kernels
// A'' layout: [hi(512) | lo(512) | hi(512)]; B'' rows: [hi | hi | lo]
// ===========================================================================
__global__ void convA_kernel(const float* __restrict__ src, __half* __restrict__ dst, int rows) {
    int idx = blockIdx.x * 256 + threadIdx.x;
    if (idx >= rows * 128) return;
    int m = idx >> 7, k4 = (idx & 127) << 2;
    float4 v = *(const float4*)(src + (size_t)m * 512 + k4);
    __half2 h0 = __floats2half2_rn(v.x, v.y);
    __half2 h1 = __floats2half2_rn(v.z, v.w);
    __half2 l0 = __floats2half2_rn(v.x - __low2float(h0), v.y - __high2float(h0));
    __half2 l1 = __floats2half2_rn(v.z - __low2float(h1), v.w - __high2float(h1));
    __half* rb = dst + (size_t)m * K2;
    *(__half2*)(rb + k4) = h0;        *(__half2*)(rb + k4 + 2) = h1;
    *(__half2*)(rb + 512 + k4) = l0;  *(__half2*)(rb + 512 + k4 + 2) = l1;
    *(__half2*)(rb + 1024 + k4) = h0; *(__half2*)(rb + 1024 + k4 + 2) = h1;
}

__global__ void convB_kernel(const float* __restrict__ W, __half* __restrict__ dst, int N) {
    int idx = blockIdx.x * 256 + threadIdx.x;
    int nq = N >> 2;
    if (idx >= 512 * nq) return;
    int k = idx / nq, n4 = (idx - k * nq) << 2;
    float4 v = *(const float4*)(W + (size_t)k * N + n4);
    __half2 h0 = __floats2half2_rn(v.x, v.y);
    __half2 h1 = __floats2half2_rn(v.z, v.w);
    __half2 l0 = __floats2half2_rn(v.x - __low2float(h0), v.y - __high2float(h0));
    __half2 l1 = __floats2half2_rn(v.z - __low2float(h1), v.w - __high2float(h1));
    __half* d0 = dst + (size_t)k * N + n4;
    __half* d1 = dst + (size_t)(512 + k) * N + n4;
    __half* d2 = dst + (size_t)(1024 + k) * N + n4;
    *(__half2*)(d0) = h0; *(__half2*)(d0 + 2) = h1;
    *(__half2*)(d1) = h0; *(__half2*)(d1 + 2) = h1;
    *(__half2*)(d2) = l0; *(__half2*)(d2 + 2) = l1;
}

// ---------------------------------------------------------------------------
// pad mask
// ---------------------------------------------------------------------------
__global__ void mask_kernel(const float* __restrict__ x) {
    int t = blockIdx.x, b = blockIdx.y;
    const float* row = x + ((size_t)b * Tn + t) * DMn;
    int zero = 1;
    for (int i = threadIdx.x; i < DMn; i += blockDim.x)
        if (row[i] != 0.f) zero = 0;
    int all = __syncthreads_and(zero);
    if (threadIdx.x == 0) g_mask[b * (Cn - 1) + t] = (unsigned char)(all != 0);
}

// ---------------------------------------------------------------------------
// Sliding-window attention (SIMT fp32); epilogue writes split-fp16 directly.
// ---------------------------------------------------------------------------
constexpr int S_HQ = 0;
constexpr int S_KT = S_HQ + 64 * 68;
constexpr int S_V  = S_KT + 64 * 196;
constexpr int S_S  = S_V + 128 * 68;
constexpr int S_WT = S_S + 64 * 196;
constexpr int ATT_SMEM_FLOATS = S_WT + 128 * 68;

__global__ __launch_bounds__(256) void attn_kernel() {
    extern __shared__ __align__(16) float sm[];
    float* sHqT = sm + S_HQ;
    float* sKT  = sm + S_KT;
    float* sV   = sm + S_V;
    float* sS   = sm + S_S;
    float* sWT  = sm + S_WT;

    int q0 = blockIdx.x * 64;
    int h = blockIdx.y, b = blockIdx.z;
    int tid = threadIdx.x;

    for (int i = tid; i < 128 * 68; i += 256) sWT[i] = 0.f;

    for (int li = tid; li < 1024; li += 256) {
        int q = li >> 4, d4 = (li & 15) << 2;
        float4 v = *(const float4*)(g_hq + (size_t)(b * Qn + q0 + q) * 512 + h * 64 + d4);
        sHqT[(d4 + 0) * 68 + q] = v.x; sHqT[(d4 + 1) * 68 + q] = v.y;
        sHqT[(d4 + 2) * 68 + q] = v.z; sHqT[(d4 + 3) * 68 + q] = v.w;
    }
    for (int li = tid; li < 2048; li += 256) {
        int j = li >> 4, d4 = (li & 15) << 2;
        float4 v = make_float4(0.f, 0.f, 0.f, 0.f);
        if (j < 127) v = *(const float4*)(g_kv + (size_t)(b * Tn + q0 + j) * 1024 + h * 64 + d4);
        sKT[(d4 + 0) * 196 + j] = v.x; sKT[(d4 + 1) * 196 + j] = v.y;
        sKT[(d4 + 2) * 196 + j] = v.z; sKT[(d4 + 3) * 196 + j] = v.w;
    }
    for (int li = tid; li < 1024; li += 256) {
        int c = li >> 4, d4 = (li & 15) << 2;
        float4 v = *(const float4*)(g_hr + (size_t)c * 512 + h * 64 + d4);
        sKT[(d4 + 0) * 196 + 128 + c] = v.x; sKT[(d4 + 1) * 196 + 128 + c] = v.y;
        sKT[(d4 + 2) * 196 + 128 + c] = v.z; sKT[(d4 + 3) * 196 + 128 + c] = v.w;
    }
    for (int li = tid; li < 2048; li += 256) {
        int j = li >> 4, d4 = (li & 15) << 2;
        float4 v = make_float4(0.f, 0.f, 0.f, 0.f);
        if (j < 127) v = *(const float4*)(g_kv + (size_t)(b * Tn + q0 + j) * 1024 + 512 + h * 64 + d4);
        *(float4*)(sV + j * 68 + d4) = v;
    }
    __syncthreads();

    int tr = tid >> 4, tc = tid & 15;

    {
        float acc[4][12] = {};
#pragma unroll 4
        for (int d = 0; d < 64; d++) {
            float4 av = *(const float4*)(sHqT + d * 68 + tr * 4);
            float a[4] = {av.x, av.y, av.z, av.w};
            float bb[12];
#pragma unroll
            for (int m = 0; m < 3; m++) {
                float4 bv = *(const float4*)(sKT + d * 196 + tc * 12 + m * 4);
                bb[m * 4 + 0] = bv.x; bb[m * 4 + 1] = bv.y;
                bb[m * 4 + 2] = bv.z; bb[m * 4 + 3] = bv.w;
            }
#pragma unroll
            for (int i = 0; i < 4; i++)
#pragma unroll
                for (int j = 0; j < 12; j++)
                    acc[i][j] = fmaf(a[i], bb[j], acc[i][j]);
        }
#pragma unroll
        for (int i = 0; i < 4; i++)
#pragma unroll
            for (int m = 0; m < 3; m++)
                *(float4*)(sS + (tr * 4 + i) * 196 + tc * 12 + m * 4) =
                    make_float4(acc[i][m * 4 + 0], acc[i][m * 4 + 1],
                                acc[i][m * 4 + 2], acc[i][m * 4 + 3]);
    }
    __syncthreads();

    {
        int lane = tid & 31, w = tid >> 5;
#pragma unroll
        for (int r = 0; r < 8; r++) {
            int q = w * 8 + r;
            int c0 = lane, c1 = lane + 32;
            float s0 = (sS[q * 196 + q + c0] + sS[q * 196 + 128 + c0]) * 0.125f;
            float s1 = (sS[q * 196 + q + c1] + sS[q * 196 + 128 + c1]) * 0.125f;
            int jg0 = q0 + q + c0, jg1 = q0 + q + c1;
            if (jg0 < Cn - 1 && g_mask[b * (Cn - 1) + jg0]) s0 = -1e30f;
            if (jg1 < Cn - 1 && g_mask[b * (Cn - 1) + jg1]) s1 = -1e30f;
            float mx = fmaxf(s0, s1);
#pragma unroll
            for (int o = 16; o; o >>= 1) mx = fmaxf(mx, __shfl_xor_sync(0xffffffffu, mx, o));
            float e0 = __expf(s0 - mx), e1 = __expf(s1 - mx);
            float sum = e0 + e1;
#pragma unroll
            for (int o = 16; o; o >>= 1) sum += __shfl_xor_sync(0xffffffffu, sum, o);
            float inv = 1.f / sum;
            sWT[(q + c0) * 68 + q] = e0 * inv;
            sWT[(q + c1) * 68 + q] = e1 * inv;
        }
    }
    __syncthreads();

    {
        float o[4][4] = {};
#pragma unroll 4
        for (int j = 0; j < 128; j++) {
            float4 av = *(const float4*)(sWT + j * 68 + tr * 4);
            float4 bv = *(const float4*)(sV + j * 68 + tc * 4);
            float a[4] = {av.x, av.y, av.z, av.w};
            float bb[4] = {bv.x, bv.y, bv.z, bv.w};
#pragma unroll
            for (int i = 0; i < 4; i++)
#pragma unroll
                for (int jj = 0; jj < 4; jj++)
                    o[i][jj] = fmaf(a[i], bb[jj], o[i][jj]);
        }
        // epilogue: write split-fp16 [hi | lo | hi] directly into g_atth
#pragma unroll
        for (int i = 0; i < 4; i++) {
            int q = tr * 4 + i;
            __half2 h0 = __floats2half2_rn(o[i][0], o[i][1]);
            __half2 h1 = __floats2half2_rn(o[i][2], o[i][3]);
            __half2 l0 = __floats2half2_rn(o[i][0] - __low2float(h0), o[i][1] - __high2float(h0));
            __half2 l1 = __floats2half2_rn(o[i][2] - __low2float(h1), o[i][3] - __high2float(h1));
            __half* rb = g_atth + (size_t)(b * Qn + q0 + q) * K2 + h * 64 + tc * 4;
            *(__half2*)(rb) = h0;        *(__half2*)(rb + 2) = h1;
            *(__half2*)(rb + 512) = l0;  *(__half2*)(rb + 512 + 2) = l1;
            *(__half2*)(rb + 1024) = h0; *(__half2*)(rb + 1024 + 2) = h1;
        }
    }
}

}  // namespace

// ---------------------------------------------------------------------------
extern "C" void kernel_launch(void* const* d_in, const int* in_sizes, int n_in,
                              void* d_out, int out_size) {
    const float* x   = (const float*)d_in[0];
    const float* r   = (const float*)d_in[1];
    const float* Wkv = (const float*)d_in[2];
    const float* Wq  = (const float*)d_in[3];
    const float* bq  = (const float*)d_in[4];
    const float* Wr  = (const float*)d_in[5];
    const float* Wo  = (const float*)d_in[6];
    float* out = (float*)d_out;

    float *kvp, *hqp, *hrp;
    __half *xh, *rh, *atth, *Wkvh, *Wqh, *Wrh, *Woh;
    cudaGetSymbolAddress((void**)&kvp,  g_kv);
    cudaGetSymbolAddress((void**)&hqp,  g_hq);
    cudaGetSymbolAddress((void**)&hrp,  g_hr);
    cudaGetSymbolAddress((void**)&xh,   g_xh);
    cudaGetSymbolAddress((void**)&rh,   g_rh);
    cudaGetSymbolAddress((void**)&atth, g_atth);
    cudaGetSymbolAddress((void**)&Wkvh, g_Wkvh);
    cudaGetSymbolAddress((void**)&Wqh,  g_Wqh);
    cudaGetSymbolAddress((void**)&Wrh,  g_Wrh);
    cudaGetSymbolAddress((void**)&Woh,  g_Woh);

    cudaFuncSetAttribute(attn_kernel, cudaFuncAttributeMaxDynamicSharedMemorySize,
                         ATT_SMEM_FLOATS * (int)sizeof(float));
    cudaFuncSetAttribute(hgemm_kernel<false, false>,
                         cudaFuncAttributeMaxDynamicSharedMemorySize, HG_SMEM);
    cudaFuncSetAttribute(hgemm_kernel<true, true>,
                         cudaFuncAttributeMaxDynamicSharedMemorySize, HG_SMEM);

    // 0. conversions + mask
    mask_kernel<<<dim3(Cn - 1, Bn), 128>>>(x);
    convA_kernel<<<(Bn * Tn * 128 + 255) / 256, 256>>>(x, xh, Bn * Tn);
    convA_kernel<<<(Cn * 128 + 255) / 256, 256>>>(r, rh, Cn);
    convB_kernel<<<(512 * 256 + 255) / 256, 256>>>(Wkv, Wkvh, 1024);
    convB_kernel<<<(512 * 128 + 255) / 256, 256>>>(Wq, Wqh, 512);
    convB_kernel<<<(512 * 128 + 255) / 256, 256>>>(Wr, Wrh, 512);
    convB_kernel<<<(512 * 128 + 255) / 256, 256>>>(Wo, Woh, 512);

    // 1. kv = x @ Wkv            [4222 x 1536 x 1024]
    hgemm_kernel<false, false><<<dim3(1024 / 128, (Bn * Tn + 127) / 128), 256, HG_SMEM>>>(
        xh, Wkvh, nullptr, kvp, Bn * Tn, 1024);
    // 2. hq = x[:,63:] @ Wq + bq [4096 x 1536 x 512]
    hgemm_kernel<true, true><<<dim3(512 / 128, (Bn * Qn) / 128), 256, HG_SMEM>>>(
        xh, Wqh, bq, hqp, Bn * Qn, 512);
    // 3. hr = r @ Wr             [64 x 1536 x 512]
    hgemm_kernel<false, false><<<dim3(512 / 128, 1), 256, HG_SMEM>>>(
        rh, Wrh, nullptr, hrp, Cn, 512);
    // 4. attention -> split-fp16 att''
    attn_kernel<<<dim3(Qn / 64, Hn, Bn), 256, ATT_SMEM_FLOATS * sizeof(float)>>>();
    // 5. out = att @ Wo          [4096 x 1536 x 512]
    hgemm_kernel<false, false><<<dim3(512 / 128, (Bn * Qn) / 128), 256, HG_SMEM>>>(
        atth, Woh, nullptr, out, Bn * Qn, 512);
}

// round 4
// speedup vs baseline: 1.5081x; 1.2865x over previous
#include <cuda_runtime.h>
#include <cuda_fp16.h>
#include <cstdint>

namespace {

constexpr int Bn = 2, Tn = 2111, Qn = 2048, Cn = 64, Hn = 8, DMn = 512;
constexpr int KS = 1024;   // stored K width: [hi(512) | lo*2048(512)]
constexpr float INV_SCALE = 1.0f / 2048.0f;

// Scratch (device globals)
__device__ float g_kv[Bn * Tn * 1024];
__device__ float g_hq[Bn * Qn * 512];
__device__ float g_hr[Cn * 512];
__device__ float g_hrp[8 * Cn * 512];
__device__ unsigned char g_mask[Bn * (Cn - 1)];
__device__ __half g_xh[(size_t)Bn * Tn * KS];
__device__ __half g_atth[(size_t)Bn * Qn * KS];
__device__ __half g_Wkvh[KS * 1024];
__device__ __half g_Wqh[KS * 512];
__device__ __half g_Woh[KS * 512];

// ===========================================================================
// PTX helpers
// ===========================================================================
__device__ __forceinline__ uint32_t smem_u32(const void* p) {
    uint32_t a;
    asm("{ .reg .u64 t; cvta.to.shared.u64 t, %1; cvt.u32.u64 %0, t; }" : "=r"(a) : "l"(p));
    return a;
}
__device__ __forceinline__ void cpa16(uint32_t d, const void* s, int sz) {
    asm volatile("cp.async.cg.shared.global [%0], [%1], 16, %2;" :: "r"(d), "l"(s), "r"(sz));
}
__device__ __forceinline__ void cp_commit() { asm volatile("cp.async.commit_group;"); }
template <int N> __device__ __forceinline__ void cp_wait() {
    asm volatile("cp.async.wait_group %0;" :: "n"(N));
}
__device__ __forceinline__ void ldsm4(uint32_t* r, uint32_t a) {
    asm volatile("ldmatrix.sync.aligned.m8n8.x4.shared.b16 {%0,%1,%2,%3}, [%4];"
                 : "=r"(r[0]), "=r"(r[1]), "=r"(r[2]), "=r"(r[3]) : "r"(a));
}
__device__ __forceinline__ void ldsm4t(uint32_t* r, uint32_t a) {
    asm volatile("ldmatrix.sync.aligned.m8n8.x4.trans.shared.b16 {%0,%1,%2,%3}, [%4];"
                 : "=r"(r[0]), "=r"(r[1]), "=r"(r[2]), "=r"(r[3]) : "r"(a));
}
__device__ __forceinline__ void mma_f32(float* d, const uint32_t* a, uint32_t b0, uint32_t b1) {
    asm volatile(
        "mma.sync.aligned.m16n8k16.row.col.f32.f16.f16.f32 "
        "{%0,%1,%2,%3}, {%4,%5,%6,%7}, {%8,%9}, {%0,%1,%2,%3};"
        : "+f"(d[0]), "+f"(d[1]), "+f"(d[2]), "+f"(d[3])
        : "r"(a[0]), "r"(a[1]), "r"(a[2]), "r"(a[3]), "r"(b0), "r"(b1));
}
__device__ __forceinline__ void mma_f16(uint32_t* d, const uint32_t* a, uint32_t b0, uint32_t b1) {
    asm volatile(
        "mma.sync.aligned.m16n8k16.row.col.f16.f16.f16.f16 "
        "{%0,%1}, {%2,%3,%4,%5}, {%6,%7}, {%0,%1};"
        : "+r"(d[0]), "+r"(d[1])
        : "r"(a[0]), "r"(a[1]), "r"(a[2]), "r"(a[3]), "r"(b0), "r"(b1));
}

// ===========================================================================
// HGEMM passes over split-fp16 data.
//   PASS 0: C = Ahi @ Bhi          (K=512,  fp32 accum, writes C [+bias])
//   PASS 1: C += (Alo'@Bhi + Ahi@Blo') / 2048   (K=1024, fp16 accum, RMW)
// A stored [M][1024] = [hi | lo*2048]; B stored [1024][N] = [hi ; lo*2048].
// Pass-1 A column j maps to stored column (j+512)&1023 (lo first, then hi).
// 128x128x32 tile, 256 threads, 4-stage cp.async pipeline, 1 sync/iter.
// ===========================================================================
constexpr int ASTG = 128 * 128;
constexpr int BSTG = 32 * 256;
constexpr int STG = ASTG + BSTG;       // 24576
constexpr int NSTAGE = 4;
constexpr int HG_SMEM = STG * NSTAGE;  // 98304

template <int PASS, bool ROWMAP, bool BIAS>
__global__ __launch_bounds__(256, 2) void hgemm_kernel(
    const __half* __restrict__ A, const __half* __restrict__ Bw,
    const float* __restrict__ bias, float* __restrict__ C, int M, int N)
{
    extern __shared__ char smm[];
    uint32_t sb = smem_u32(smm);
    int tid = threadIdx.x, lane = tid & 31, wid = tid >> 5;
    int wm = wid >> 1, wn = wid & 1;
    int row0 = blockIdx.y * 128, col0 = blockIdx.x * 128;

    int c0 = tid, c1 = tid + 256;
    int rA0 = c0 >> 2, cA0 = c0 & 3;
    int rA1 = c1 >> 2, cA1 = c1 & 3;
    int gm0 = row0 + rA0, gm1 = row0 + rA1;
    int av0 = (gm0 < M) ? 16 : 0, av1 = (gm1 < M) ? 16 : 0;
    size_t arow0 = 0, arow1 = 0;
    if (gm0 < M) arow0 = ROWMAP ? (size_t)((gm0 >> 11) * Tn + (Cn - 1) + (gm0 & (Qn - 1))) : (size_t)gm0;
    if (gm1 < M) arow1 = ROWMAP ? (size_t)((gm1 >> 11) * Tn + (Cn - 1) + (gm1 & (Qn - 1))) : (size_t)gm1;
    const __half* asrc0 = A + arow0 * KS + cA0 * 8;
    const __half* asrc1 = A + arow1 * KS + cA1 * 8;
    uint32_t adst0 = rA0 * 128 + (((cA0 + rA0) & 7) << 4);
    uint32_t adst1 = rA1 * 128 + (((cA1 + rA1) & 7) << 4);

    int rB0 = c0 >> 4, cB0 = c0 & 15;
    int rB1 = c1 >> 4, cB1 = c1 & 15;
    const __half* bsrc0 = Bw + (size_t)rB0 * N + col0 + cB0 * 8;
    const __half* bsrc1 = Bw + (size_t)rB1 * N + col0 + cB1 * 8;
    uint32_t bdst0 = ASTG + rB0 * 256 + ((cB0 ^ (rB0 & 7)) << 4);
    uint32_t bdst1 = ASTG + rB1 * 256 + ((cB1 ^ (rB1 & 7)) << 4);

    auto load_stage = [&](int s, int kt) {
        int k0 = kt * 32;
        int ka = PASS ? ((k0 + 512) & 1023) : k0;
        uint32_t base = sb + s * STG;
        cpa16(base + adst0, asrc0 + ka, av0);
        cpa16(base + adst1, asrc1 + ka, av1);
        cpa16(base + bdst0, bsrc0 + (size_t)k0 * N, 16);
        cpa16(base + bdst1, bsrc1 + (size_t)k0 * N, 16);
        cp_commit();
    };

    constexpr int KT = (PASS ? 1024 : 512) / 32;
    load_stage(0, 0);
    load_stage(1, 1);
    load_stage(2, 2);

    float accf[2][8][4] = {};
    uint32_t acch[2][8][2] = {};

    int la_r0 = wm * 32 + (lane & 15);
    int la_cbase = (lane >> 4);
    int lb_rbase = (lane & 15);
    int lb_cbase = wn * 8 + (lane >> 4);

    for (int kt = 0; kt < KT; kt++) {
        cp_wait<2>();
        __syncthreads();
        int s = kt & (NSTAGE - 1);
        uint32_t aB = sb + s * STG;
        uint32_t bB = aB + ASTG;
#pragma unroll
        for (int kk = 0; kk < 2; kk++) {
            uint32_t a[2][4];
#pragma unroll
            for (int mf = 0; mf < 2; mf++) {
                int r = la_r0 + mf * 16;
                int c = la_cbase + kk * 2;
                ldsm4(a[mf], aB + r * 128 + (((c + r) & 7) << 4));
            }
            uint32_t b[4][4];
#pragma unroll
            for (int nf = 0; nf < 4; nf++) {
                int r = lb_rbase + kk * 16;
                int c = lb_cbase + nf * 2;
                ldsm4t(b[nf], bB + r * 256 + ((c ^ (r & 7)) << 4));
            }
#pragma unroll
            for (int mf = 0; mf < 2; mf++)
#pragma unroll
                for (int nf = 0; nf < 4; nf++) {
                    if (PASS == 0) {
                        mma_f32(accf[mf][nf * 2],     a[mf], b[nf][0], b[nf][1]);
                        mma_f32(accf[mf][nf * 2 + 1], a[mf], b[nf][2], b[nf][3]);
                    } else {
                        mma_f16(acch[mf][nf * 2],     a[mf], b[nf][0], b[nf][1]);
                        mma_f16(acch[mf][nf * 2 + 1], a[mf], b[nf][2], b[nf][3]);
                    }
                }
        }
        if (kt + 3 < KT) load_stage((kt + 3) & (NSTAGE - 1), kt + 3);
        else cp_commit();
    }

    // ---- epilogue ----
#pragma unroll
    for (int mf = 0; mf < 2; mf++) {
        int rb = row0 + wm * 32 + mf * 16 + (lane >> 2);
#pragma unroll
        for (int nf = 0; nf < 8; nf++) {
            int cb = col0 + wn * 64 + nf * 8 + (lane & 3) * 2;
            if (PASS == 0) {
                float* a4 = accf[mf][nf];
                float bx = 0.f, by = 0.f;
                if (BIAS) { bx = bias[cb]; by = bias[cb + 1]; }
                if (rb < M)
                    *(float2*)(C + (size_t)rb * N + cb) = make_float2(a4[0] + bx, a4[1] + by);
                if (rb + 8 < M)
                    *(float2*)(C + (size_t)(rb + 8) * N + cb) = make_float2(a4[2] + bx, a4[3] + by);
            } else {
                float2 lo = __half22float2(*(__half2*)&acch[mf][nf][0]);
                float2 hi = __half22float2(*(__half2*)&acch[mf][nf][1]);
                if (rb < M) {
                    float2 cur = *(float2*)(C + (size_t)rb * N + cb);
                    cur.x += lo.x * INV_SCALE; cur.y += lo.y * INV_SCALE;
                    *(float2*)(C + (size_t)rb * N + cb) = cur;
                }
                if (rb + 8 < M) {
                    float2 cur = *(float2*)(C + (size_t)(rb + 8) * N + cb);
                    cur.x += hi.x * INV_SCALE; cur.y += hi.y * INV_SCALE;
                    *(float2*)(C + (size_t)(rb + 8) * N + cb) = cur;
                }
            }
        }
    }
}

// ===========================================================================
// split-fp16 conversion kernels: [hi | lo*2048]
// ===========================================================================
__global__ void convX_kernel(const float* __restrict__ src, __half* __restrict__ dst, int rows) {
    int idx = blockIdx.x * 256 + threadIdx.x;
    if (idx >= rows * 128) return;
    int m = idx >> 7, k4 = (idx & 127) << 2;
    float4 v = *(const float4*)(src + (size_t)m * 512 + k4);
    __half2 h0 = __floats2half2_rn(v.x, v.y);
    __half2 h1 = __floats2half2_rn(v.z, v.w);
    __half2 l0 = __floats2half2_rn((v.x - __low2float(h0)) * 2048.f, (v.y - __high2float(h0)) * 2048.f);
    __half2 l1 = __floats2half2_rn((v.z - __low2float(h1)) * 2048.f, (v.w - __high2float(h1)) * 2048.f);
    __half* rb = dst + (size_t)m * KS;
    *(__half2*)(rb + k4) = h0;        *(__half2*)(rb + k4 + 2) = h1;
    *(__half2*)(rb + 512 + k4) = l0;  *(__half2*)(rb + 512 + k4 + 2) = l1;
}

__global__ void convW_kernel(const float* __restrict__ W, __half* __restrict__ dst, int N) {
    int idx = blockIdx.x * 256 + threadIdx.x;
    int nq = N >> 2;
    if (idx >= 512 * nq) return;
    int k = idx / nq, n4 = (idx - k * nq) << 2;
    float4 v = *(const float4*)(W + (size_t)k * N + n4);
    __half2 h0 = __floats2half2_rn(v.x, v.y);
    __half2 h1 = __floats2half2_rn(v.z, v.w);
    __half2 l0 = __floats2half2_rn((v.x - __low2float(h0)) * 2048.f, (v.y - __high2float(h0)) * 2048.f);
    __half2 l1 = __floats2half2_rn((v.z - __low2float(h1)) * 2048.f, (v.w - __high2float(h1)) * 2048.f);
    __half* d0 = dst + (size_t)k * N + n4;
    __half* d1 = dst + (size_t)(512 + k) * N + n4;
    *(__half2*)(d0) = h0; *(__half2*)(d0 + 2) = h1;
    *(__half2*)(d1) = l0; *(__half2*)(d1 + 2) = l1;
}

// ---------------------------------------------------------------------------
// hr = r @ Wr in fp32 SIMT, split-K 8, deterministic two-phase.
// ---------------------------------------------------------------------------
__global__ void hr_partial_kernel(const float* __restrict__ r, const float* __restrict__ Wr) {
    int cb = blockIdx.x;          // col block of 128
    int ks = blockIdx.y;          // k split of 64
    int t = threadIdx.x;
    int row = t & 63, cg = t >> 6;
    int k0 = ks * 64;
    float acc[32] = {};
    const float* rrow = r + row * 512 + k0;
    const float* wbase = Wr + (size_t)k0 * 512 + cb * 128 + cg * 32;
#pragma unroll 4
    for (int k = 0; k < 64; k++) {
        float a = __ldg(rrow + k);
        const float* wr = wbase + (size_t)k * 512;
#pragma unroll
        for (int c = 0; c < 32; c++) acc[c] = fmaf(a, __ldg(wr + c), acc[c]);
    }
    float* dst = g_hrp + ((size_t)ks * 64 + row) * 512 + cb * 128 + cg * 32;
#pragma unroll
    for (int c = 0; c < 32; c++) dst[c] = acc[c];
}

__global__ void hr_reduce_kernel() {
    int idx = blockIdx.x * 256 + threadIdx.x;
    if (idx >= 64 * 512) return;
    float s = 0.f;
#pragma unroll
    for (int k = 0; k < 8; k++) s += g_hrp[k * 64 * 512 + idx];
    g_hr[idx] = s;
}

// ---------------------------------------------------------------------------
// pad mask
// ---------------------------------------------------------------------------
__global__ void mask_kernel(const float* __restrict__ x) {
    int t = blockIdx.x, b = blockIdx.y;
    const float* row = x + ((size_t)b * Tn + t) * DMn;
    int zero = 1;
    for (int i = threadIdx.x; i < DMn; i += blockDim.x)
        if (row[i] != 0.f) zero = 0;
    int all = __syncthreads_and(zero);
    if (threadIdx.x == 0) g_mask[b * (Cn - 1) + t] = (unsigned char)(all != 0);
}

// ---------------------------------------------------------------------------
// Sliding-window attention (SIMT fp32); epilogue writes split-fp16 directly.
// ---------------------------------------------------------------------------
constexpr int S_HQ = 0;
constexpr int S_KT = S_HQ + 64 * 68;
constexpr int S_V  = S_KT + 64 * 196;
constexpr int S_S  = S_V + 128 * 68;
constexpr int S_WT = S_S + 64 * 196;
constexpr int ATT_SMEM_FLOATS = S_WT + 128 * 68;

__global__ __launch_bounds__(256) void attn_kernel() {
    extern __shared__ __align__(16) float sm[];
    float* sHqT = sm + S_HQ;
    float* sKT  = sm + S_KT;
    float* sV   = sm + S_V;
    float* sS   = sm + S_S;
    float* sWT  = sm + S_WT;

    int q0 = blockIdx.x * 64;
    int h = blockIdx.y, b = blockIdx.z;
    int tid = threadIdx.x;

    for (int i = tid; i < 128 * 68; i += 256) sWT[i] = 0.f;

    for (int li = tid; li < 1024; li += 256) {
        int q = li >> 4, d4 = (li & 15) << 2;
        float4 v = *(const float4*)(g_hq + (size_t)(b * Qn + q0 + q) * 512 + h * 64 + d4);
        sHqT[(d4 + 0) * 68 + q] = v.x; sHqT[(d4 + 1) * 68 + q] = v.y;
        sHqT[(d4 + 2) * 68 + q] = v.z; sHqT[(d4 + 3) * 68 + q] = v.w;
    }
    for (int li = tid; li < 2048; li += 256) {
        int j = li >> 4, d4 = (li & 15) << 2;
        float4 v = make_float4(0.f, 0.f, 0.f, 0.f);
        if (j < 127) v = *(const float4*)(g_kv + (size_t)(b * Tn + q0 + j) * 1024 + h * 64 + d4);
        sKT[(d4 + 0) * 196 + j] = v.x; sKT[(d4 + 1) * 196 + j] = v.y;
        sKT[(d4 + 2) * 196 + j] = v.z; sKT[(d4 + 3) * 196 + j] = v.w;
    }
    for (int li = tid; li < 1024; li += 256) {
        int c = li >> 4, d4 = (li & 15) << 2;
        float4 v = *(const float4*)(g_hr + (size_t)c * 512 + h * 64 + d4);
        sKT[(d4 + 0) * 196 + 128 + c] = v.x; sKT[(d4 + 1) * 196 + 128 + c] = v.y;
        sKT[(d4 + 2) * 196 + 128 + c] = v.z; sKT[(d4 + 3) * 196 + 128 + c] = v.w;
    }
    for (int li = tid; li < 2048; li += 256) {
        int j = li >> 4, d4 = (li & 15) << 2;
        float4 v = make_float4(0.f, 0.f, 0.f, 0.f);
        if (j < 127) v = *(const float4*)(g_kv + (size_t)(b * Tn + q0 + j) * 1024 + 512 + h * 64 + d4);
        *(float4*)(sV + j * 68 + d4) = v;
    }
    __syncthreads();

    int tr = tid >> 4, tc = tid & 15;

    {
        float acc[4][12] = {};
#pragma unroll 4
        for (int d = 0; d < 64; d++) {
            float4 av = *(const float4*)(sHqT + d * 68 + tr * 4);
            float a[4] = {av.x, av.y, av.z, av.w};
            float bb[12];
#pragma unroll
            for (int m = 0; m < 3; m++) {
                float4 bv = *(const float4*)(sKT + d * 196 + tc * 12 + m * 4);
                bb[m * 4 + 0] = bv.x; bb[m * 4 + 1] = bv.y;
                bb[m * 4 + 2] = bv.z; bb[m * 4 + 3] = bv.w;
            }
#pragma unroll
            for (int i = 0; i < 4; i++)
#pragma unroll
                for (int j = 0; j < 12; j++)
                    acc[i][j] = fmaf(a[i], bb[j], acc[i][j]);
        }
#pragma unroll
        for (int i = 0; i < 4; i++)
#pragma unroll
            for (int m = 0; m < 3; m++)
                *(float4*)(sS + (tr * 4 + i) * 196 + tc * 12 + m * 4) =
                    make_float4(acc[i][m * 4 + 0], acc[i][m * 4 + 1],
                                acc[i][m * 4 + 2], acc[i][m * 4 + 3]);
    }
    __syncthreads();

    {
        int lane = tid & 31, w = tid >> 5;
#pragma unroll
        for (int r = 0; r < 8; r++) {
            int q = w * 8 + r;
            int c0 = lane, c1 = lane + 32;
            float s0 = (sS[q * 196 + q + c0] + sS[q * 196 + 128 + c0]) * 0.125f;
            float s1 = (sS[q * 196 + q + c1] + sS[q * 196 + 128 + c1]) * 0.125f;
            int jg0 = q0 + q + c0, jg1 = q0 + q + c1;
            if (jg0 < Cn - 1 && g_mask[b * (Cn - 1) + jg0]) s0 = -1e30f;
            if (jg1 < Cn - 1 && g_mask[b * (Cn - 1) + jg1]) s1 = -1e30f;
            float mx = fmaxf(s0, s1);
#pragma unroll
            for (int o = 16; o; o >>= 1) mx = fmaxf(mx, __shfl_xor_sync(0xffffffffu, mx, o));
            float e0 = __expf(s0 - mx), e1 = __expf(s1 - mx);
            float sum = e0 + e1;
#pragma unroll
            for (int o = 16; o; o >>= 1) sum += __shfl_xor_sync(0xffffffffu, sum, o);
            float inv = 1.f / sum;
            sWT[(q + c0) * 68 + q] = e0 * inv;
            sWT[(q + c1) * 68 + q] = e1 * inv;
        }
    }
    __syncthreads();

    {
        float o[4][4] = {};
#pragma unroll 4
        for (int j = 0; j < 128; j++) {
            float4 av = *(const float4*)(sWT + j * 68 + tr * 4);
            float4 bv = *(const float4*)(sV + j * 68 + tc * 4);
            float a[4] = {av.x, av.y, av.z, av.w};
            float bb[4] = {bv.x, bv.y, bv.z, bv.w};
#pragma unroll
            for (int i = 0; i < 4; i++)
#pragma unroll
                for (int jj = 0; jj < 4; jj++)
                    o[i][jj] = fmaf(a[i], bb[jj], o[i][jj]);
        }
#pragma unroll
        for (int i = 0; i < 4; i++) {
            int q = tr * 4 + i;
            __half2 h0 = __floats2half2_rn(o[i][0], o[i][1]);
            __half2 h1 = __floats2half2_rn(o[i][2], o[i][3]);
            __half2 l0 = __floats2half2_rn((o[i][0] - __low2float(h0)) * 2048.f,
                                           (o[i][1] - __high2float(h0)) * 2048.f);
            __half2 l1 = __floats2half2_rn((o[i][2] - __low2float(h1)) * 2048.f,
                                           (o[i][3] - __high2float(h1)) * 2048.f);
            __half* rb = g_atth + (size_t)(b * Qn + q0 + q) * KS + h * 64 + tc * 4;
            *(__half2*)(rb) = h0;        *(__half2*)(rb + 2) = h1;
            *(__half2*)(rb + 512) = l0;  *(__half2*)(rb + 512 + 2) = l1;
        }
    }
}

}  // namespace

// ---------------------------------------------------------------------------
extern "C" void kernel_launch(void* const* d_in, const int* in_sizes, int n_in,
                              void* d_out, int out_size) {
    const float* x   = (const float*)d_in[0];
    const float* r   = (const float*)d_in[1];
    const float* Wkv = (const float*)d_in[2];
    const float* Wq  = (const float*)d_in[3];
    const float* bq  = (const float*)d_in[4];
    const float* Wr  = (const float*)d_in[5];
    const float* Wo  = (const float*)d_in[6];
    float* out = (float*)d_out;

    float *kvp, *hqp;
    __half *xh, *atth, *Wkvh, *Wqh, *Woh;
    cudaGetSymbolAddress((void**)&kvp,  g_kv);
    cudaGetSymbolAddress((void**)&hqp,  g_hq);
    cudaGetSymbolAddress((void**)&xh,   g_xh);
    cudaGetSymbolAddress((void**)&atth, g_atth);
    cudaGetSymbolAddress((void**)&Wkvh, g_Wkvh);
    cudaGetSymbolAddress((void**)&Wqh,  g_Wqh);
    cudaGetSymbolAddress((void**)&Woh,  g_Woh);

    cudaFuncSetAttribute(attn_kernel, cudaFuncAttributeMaxDynamicSharedMemorySize,
                         ATT_SMEM_FLOATS * (int)sizeof(float));
    cudaFuncSetAttribute(hgemm_kernel<0, false, false>, cudaFuncAttributeMaxDynamicSharedMemorySize, HG_SMEM);
    cudaFuncSetAttribute(hgemm_kernel<1, false, false>, cudaFuncAttributeMaxDynamicSharedMemorySize, HG_SMEM);
    cudaFuncSetAttribute(hgemm_kernel<0, true, true>,   cudaFuncAttributeMaxDynamicSharedMemorySize, HG_SMEM);
    cudaFuncSetAttribute(hgemm_kernel<1, true, false>,  cudaFuncAttributeMaxDynamicSharedMemorySize, HG_SMEM);

    // 1-5: mask, hr (fp32 split-K), conversions for kv
    mask_kernel<<<dim3(Cn - 1, Bn), 128>>>(x);
    hr_partial_kernel<<<dim3(4, 8), 256>>>(r, Wr);
    hr_reduce_kernel<<<128, 256>>>();
    convX_kernel<<<(Bn * Tn * 128 + 255) / 256, 256>>>(x, xh, Bn * Tn);
    convW_kernel<<<(512 * 256 + 255) / 256, 256>>>(Wkv, Wkvh, 1024);
    // 6-7: kv = x @ Wkv  (pass A profiled by ncu at -s 5)
    hgemm_kernel<0, false, false><<<dim3(8, 33), 256, HG_SMEM>>>(xh, Wkvh, nullptr, kvp, Bn * Tn, 1024);
    hgemm_kernel<1, false, false><<<dim3(8, 33), 256, HG_SMEM>>>(xh, Wkvh, nullptr, kvp, Bn * Tn, 1024);
    // 8-10: hq = x[:,63:] @ Wq + bq
    convW_kernel<<<(512 * 128 + 255) / 256, 256>>>(Wq, Wqh, 512);
    hgemm_kernel<0, true, true><<<dim3(4, 32), 256, HG_SMEM>>>(xh, Wqh, bq, hqp, Bn * Qn, 512);
    hgemm_kernel<1, true, false><<<dim3(4, 32), 256, HG_SMEM>>>(xh, Wqh, nullptr, hqp, Bn * Qn, 512);
    // 11: attention -> split-fp16 att
    attn_kernel<<<dim3(Qn / 64, Hn, Bn), 256, ATT_SMEM_FLOATS * sizeof(float)>>>();
    // 12-14: out = att @ Wo
    convW_kernel<<<(512 * 128 + 255) / 256, 256>>>(Wo, Woh, 512);
    hgemm_kernel<0, false, false><<<dim3(4, 32), 256, HG_SMEM>>>(atth, Woh, nullptr, out, Bn * Qn, 512);
    hgemm_kernel<1, false, false><<<dim3(4, 32), 256, HG_SMEM>>>(atth, Woh, nullptr, out, Bn * Qn, 512);
}

// round 5
// speedup vs baseline: 1.7159x; 1.1377x over previous
#include <cuda_runtime.h>
#include <cuda_fp16.h>
#include <cstdint>

namespace {

constexpr int Bn = 2, Tn = 2111, Qn = 2048, Cn = 64, Hn = 8, DMn = 512;
constexpr int KS = 1024;   // stored K width: [hi(512) | lo*2048(512)]
constexpr float INV_SCALE = 1.0f / 2048.0f;

// Scratch (device globals)
__device__ float g_kv[Bn * Tn * 1024];
__device__ float g_hq[Bn * Qn * 512];
__device__ float g_hr[Cn * 512];
__device__ float g_hrp[8 * Cn * 512];
__device__ unsigned char g_mask[Bn * (Cn - 1)];
__device__ __half g_xh[(size_t)Bn * Tn * KS];
__device__ __half g_atth[(size_t)Bn * Qn * KS];
__device__ __half g_Wkvh[KS * 1024];
__device__ __half g_Wqh[KS * 512];
__device__ __half g_Woh[KS * 512];

// ===========================================================================
// PTX helpers
// ===========================================================================
__device__ __forceinline__ uint32_t smem_u32(const void* p) {
    uint32_t a;
    asm("{ .reg .u64 t; cvta.to.shared.u64 t, %1; cvt.u32.u64 %0, t; }" : "=r"(a) : "l"(p));
    return a;
}
__device__ __forceinline__ void cpa16(uint32_t d, const void* s, int sz) {
    asm volatile("cp.async.cg.shared.global [%0], [%1], 16, %2;" :: "r"(d), "l"(s), "r"(sz));
}
__device__ __forceinline__ void cp_commit() { asm volatile("cp.async.commit_group;"); }
template <int N> __device__ __forceinline__ void cp_wait() {
    asm volatile("cp.async.wait_group %0;" :: "n"(N));
}
__device__ __forceinline__ void ldsm4(uint32_t* r, uint32_t a) {
    asm volatile("ldmatrix.sync.aligned.m8n8.x4.shared.b16 {%0,%1,%2,%3}, [%4];"
                 : "=r"(r[0]), "=r"(r[1]), "=r"(r[2]), "=r"(r[3]) : "r"(a));
}
__device__ __forceinline__ void ldsm4t(uint32_t* r, uint32_t a) {
    asm volatile("ldmatrix.sync.aligned.m8n8.x4.trans.shared.b16 {%0,%1,%2,%3}, [%4];"
                 : "=r"(r[0]), "=r"(r[1]), "=r"(r[2]), "=r"(r[3]) : "r"(a));
}
__device__ __forceinline__ void mma_f32(float* d, const uint32_t* a, uint32_t b0, uint32_t b1) {
    asm volatile(
        "mma.sync.aligned.m16n8k16.row.col.f32.f16.f16.f32 "
        "{%0,%1,%2,%3}, {%4,%5,%6,%7}, {%8,%9}, {%0,%1,%2,%3};"
        : "+f"(d[0]), "+f"(d[1]), "+f"(d[2]), "+f"(d[3])
        : "r"(a[0]), "r"(a[1]), "r"(a[2]), "r"(a[3]), "r"(b0), "r"(b1));
}
__device__ __forceinline__ void mma_f16(uint32_t* d, const uint32_t* a, uint32_t b0, uint32_t b1) {
    asm volatile(
        "mma.sync.aligned.m16n8k16.row.col.f16.f16.f16.f16 "
        "{%0,%1}, {%2,%3,%4,%5}, {%6,%7}, {%0,%1};"
        : "+r"(d[0]), "+r"(d[1])
        : "r"(a[0]), "r"(a[1]), "r"(a[2]), "r"(a[3]), "r"(b0), "r"(b1));
}

// ===========================================================================
// Fused split-fp16 HGEMM:
//   C = Ahi@Bhi  (fp32 acc)  +  (Alo'@Bhi + Ahi@Blo') / 2048  (fp16 acc)
// computed in ONE pass over K=512 logical chunks of 32, sharing all frags.
// A stored [M][1024] = [hi | lo*2048]; B stored [1024][N] = [hi ; lo*2048].
// 128x128 tile, 256 threads (8 warps 4x2), 4-stage cp.async, 1 sync/iter.
// ===========================================================================
constexpr int OFF_AH = 0;          // 128 rows x 128B (half-filled, proven swizzle)
constexpr int OFF_AL = 16384;
constexpr int OFF_BH = 32768;      // 32 rows x 256B
constexpr int OFF_BL = 40960;
constexpr int STG = 49152;
constexpr int NSTAGE = 4;
constexpr int HG_SMEM = STG * NSTAGE;  // 196608

template <bool ROWMAP, bool BIAS>
__global__ __launch_bounds__(256) void hgemm_fused_kernel(
    const __half* __restrict__ A, const __half* __restrict__ Bw,
    const float* __restrict__ bias, float* __restrict__ C, int M, int N)
{
    extern __shared__ char smm[];
    uint32_t sb = smem_u32(smm);
    int tid = threadIdx.x, lane = tid & 31, wid = tid >> 5;
    int wm = wid >> 1, wn = wid & 1;
    int row0 = blockIdx.y * 128, col0 = blockIdx.x * 128;

    int c0 = tid, c1 = tid + 256;
    int rA0 = c0 >> 2, cA0 = c0 & 3;
    int rA1 = c1 >> 2, cA1 = c1 & 3;
    int gm0 = row0 + rA0, gm1 = row0 + rA1;
    int av0 = (gm0 < M) ? 16 : 0, av1 = (gm1 < M) ? 16 : 0;
    size_t arow0 = 0, arow1 = 0;
    if (gm0 < M) arow0 = ROWMAP ? (size_t)((gm0 >> 11) * Tn + (Cn - 1) + (gm0 & (Qn - 1))) : (size_t)gm0;
    if (gm1 < M) arow1 = ROWMAP ? (size_t)((gm1 >> 11) * Tn + (Cn - 1) + (gm1 & (Qn - 1))) : (size_t)gm1;
    const __half* asrc0 = A + arow0 * KS + cA0 * 8;
    const __half* asrc1 = A + arow1 * KS + cA1 * 8;
    uint32_t adst0 = rA0 * 128 + (((cA0 + rA0) & 7) << 4);
    uint32_t adst1 = rA1 * 128 + (((cA1 + rA1) & 7) << 4);

    int rB0 = c0 >> 4, cB0 = c0 & 15;
    int rB1 = c1 >> 4, cB1 = c1 & 15;
    const __half* bsrc0 = Bw + (size_t)rB0 * N + col0 + cB0 * 8;
    const __half* bsrc1 = Bw + (size_t)rB1 * N + col0 + cB1 * 8;
    uint32_t bdst0 = rB0 * 256 + ((cB0 ^ (rB0 & 7)) << 4);
    uint32_t bdst1 = rB1 * 256 + ((cB1 ^ (rB1 & 7)) << 4);

    auto load_stage = [&](int s, int kt) {
        int k0 = kt * 32;
        uint32_t base = sb + s * STG;
        cpa16(base + OFF_AH + adst0, asrc0 + k0, av0);
        cpa16(base + OFF_AH + adst1, asrc1 + k0, av1);
        cpa16(base + OFF_AL + adst0, asrc0 + 512 + k0, av0);
        cpa16(base + OFF_AL + adst1, asrc1 + 512 + k0, av1);
        cpa16(base + OFF_BH + bdst0, bsrc0 + (size_t)k0 * N, 16);
        cpa16(base + OFF_BH + bdst1, bsrc1 + (size_t)k0 * N, 16);
        cpa16(base + OFF_BL + bdst0, bsrc0 + (size_t)(512 + k0) * N, 16);
        cpa16(base + OFF_BL + bdst1, bsrc1 + (size_t)(512 + k0) * N, 16);
        cp_commit();
    };

    constexpr int KT = 512 / 32;   // 16
    load_stage(0, 0);
    load_stage(1, 1);
    load_stage(2, 2);

    float accf[2][8][4] = {};
    uint32_t acch[2][8][2] = {};

    int la_r0 = wm * 32 + (lane & 15);
    int la_cbase = (lane >> 4);
    int lb_rbase = (lane & 15);
    int lb_cbase = wn * 8 + (lane >> 4);

    for (int kt = 0; kt < KT; kt++) {
        cp_wait<2>();
        __syncthreads();
        int s = kt & (NSTAGE - 1);
        uint32_t base = sb + s * STG;
#pragma unroll
        for (int kk = 0; kk < 2; kk++) {
            uint32_t ah[2][4], al[2][4];
#pragma unroll
            for (int mf = 0; mf < 2; mf++) {
                int r = la_r0 + mf * 16;
                int c = la_cbase + kk * 2;
                uint32_t off = r * 128 + (((c + r) & 7) << 4);
                ldsm4(ah[mf], base + OFF_AH + off);
                ldsm4(al[mf], base + OFF_AL + off);
            }
            uint32_t bh[4][4], bl[4][4];
#pragma unroll
            for (int nf = 0; nf < 4; nf++) {
                int r = lb_rbase + kk * 16;
                int c = lb_cbase + nf * 2;
                uint32_t off = r * 256 + ((c ^ (r & 7)) << 4);
                ldsm4t(bh[nf], base + OFF_BH + off);
                ldsm4t(bl[nf], base + OFF_BL + off);
            }
#pragma unroll
            for (int mf = 0; mf < 2; mf++)
#pragma unroll
                for (int nf = 0; nf < 4; nf++) {
                    mma_f32(accf[mf][nf * 2],     ah[mf], bh[nf][0], bh[nf][1]);
                    mma_f32(accf[mf][nf * 2 + 1], ah[mf], bh[nf][2], bh[nf][3]);
                    mma_f16(acch[mf][nf * 2],     al[mf], bh[nf][0], bh[nf][1]);
                    mma_f16(acch[mf][nf * 2 + 1], al[mf], bh[nf][2], bh[nf][3]);
                    mma_f16(acch[mf][nf * 2],     ah[mf], bl[nf][0], bl[nf][1]);
                    mma_f16(acch[mf][nf * 2 + 1], ah[mf], bl[nf][2], bl[nf][3]);
                }
        }
        if (kt + 3 < KT) load_stage((kt + 3) & (NSTAGE - 1), kt + 3);
        else cp_commit();
    }

    // ---- epilogue: combine f32 + f16/2048 (+bias), single write ----
#pragma unroll
    for (int mf = 0; mf < 2; mf++) {
        int rb = row0 + wm * 32 + mf * 16 + (lane >> 2);
#pragma unroll
        for (int nf = 0; nf < 8; nf++) {
            int cb = col0 + wn * 64 + nf * 8 + (lane & 3) * 2;
            float* a4 = accf[mf][nf];
            float2 lo = __half22float2(*(__half2*)&acch[mf][nf][0]);
            float2 hi = __half22float2(*(__half2*)&acch[mf][nf][1]);
            float bx = 0.f, by = 0.f;
            if (BIAS) { bx = bias[cb]; by = bias[cb + 1]; }
            if (rb < M)
                *(float2*)(C + (size_t)rb * N + cb) =
                    make_float2(a4[0] + lo.x * INV_SCALE + bx, a4[1] + lo.y * INV_SCALE + by);
            if (rb + 8 < M)
                *(float2*)(C + (size_t)(rb + 8) * N + cb) =
                    make_float2(a4[2] + hi.x * INV_SCALE + bx, a4[3] + hi.y * INV_SCALE + by);
        }
    }
}

// ===========================================================================
// split-fp16 conversion kernels: [hi | lo*2048]
// ===========================================================================
__global__ void convX_kernel(const float* __restrict__ src, __half* __restrict__ dst, int rows) {
    int idx = blockIdx.x * 256 + threadIdx.x;
    if (idx >= rows * 128) return;
    int m = idx >> 7, k4 = (idx & 127) << 2;
    float4 v = *(const float4*)(src + (size_t)m * 512 + k4);
    __half2 h0 = __floats2half2_rn(v.x, v.y);
    __half2 h1 = __floats2half2_rn(v.z, v.w);
    __half2 l0 = __floats2half2_rn((v.x - __low2float(h0)) * 2048.f, (v.y - __high2float(h0)) * 2048.f);
    __half2 l1 = __floats2half2_rn((v.z - __low2float(h1)) * 2048.f, (v.w - __high2float(h1)) * 2048.f);
    __half* rb = dst + (size_t)m * KS;
    *(__half2*)(rb + k4) = h0;        *(__half2*)(rb + k4 + 2) = h1;
    *(__half2*)(rb + 512 + k4) = l0;  *(__half2*)(rb + 512 + k4 + 2) = l1;
}

__global__ void convW_kernel(const float* __restrict__ W, __half* __restrict__ dst, int N) {
    int idx = blockIdx.x * 256 + threadIdx.x;
    int nq = N >> 2;
    if (idx >= 512 * nq) return;
    int k = idx / nq, n4 = (idx - k * nq) << 2;
    float4 v = *(const float4*)(W + (size_t)k * N + n4);
    __half2 h0 = __floats2half2_rn(v.x, v.y);
    __half2 h1 = __floats2half2_rn(v.z, v.w);
    __half2 l0 = __floats2half2_rn((v.x - __low2float(h0)) * 2048.f, (v.y - __high2float(h0)) * 2048.f);
    __half2 l1 = __floats2half2_rn((v.z - __low2float(h1)) * 2048.f, (v.w - __high2float(h1)) * 2048.f);
    __half* d0 = dst + (size_t)k * N + n4;
    __half* d1 = dst + (size_t)(512 + k) * N + n4;
    *(__half2*)(d0) = h0; *(__half2*)(d0 + 2) = h1;
    *(__half2*)(d1) = l0; *(__half2*)(d1 + 2) = l1;
}

// ---------------------------------------------------------------------------
// hr = r @ Wr in fp32 SIMT, split-K 8, deterministic two-phase.
// ---------------------------------------------------------------------------
__global__ void hr_partial_kernel(const float* __restrict__ r, const float* __restrict__ Wr) {
    int cb = blockIdx.x;
    int ks = blockIdx.y;
    int t = threadIdx.x;
    int row = t & 63, cg = t >> 6;
    int k0 = ks * 64;
    float acc[32] = {};
    const float* rrow = r + row * 512 + k0;
    const float* wbase = Wr + (size_t)k0 * 512 + cb * 128 + cg * 32;
#pragma unroll 4
    for (int k = 0; k < 64; k++) {
        float a = __ldg(rrow + k);
        const float* wr = wbase + (size_t)k * 512;
#pragma unroll
        for (int c = 0; c < 32; c++) acc[c] = fmaf(a, __ldg(wr + c), acc[c]);
    }
    float* dst = g_hrp + ((size_t)ks * 64 + row) * 512 + cb * 128 + cg * 32;
#pragma unroll
    for (int c = 0; c < 32; c++) dst[c] = acc[c];
}

__global__ void hr_reduce_kernel() {
    int idx = blockIdx.x * 256 + threadIdx.x;
    if (idx >= 64 * 512) return;
    float s = 0.f;
#pragma unroll
    for (int k = 0; k < 8; k++) s += g_hrp[k * 64 * 512 + idx];
    g_hr[idx] = s;
}

// ---------------------------------------------------------------------------
// pad mask
// ---------------------------------------------------------------------------
__global__ void mask_kernel(const float* __restrict__ x) {
    int t = blockIdx.x, b = blockIdx.y;
    const float* row = x + ((size_t)b * Tn + t) * DMn;
    int zero = 1;
    for (int i = threadIdx.x; i < DMn; i += blockDim.x)
        if (row[i] != 0.f) zero = 0;
    int all = __syncthreads_and(zero);
    if (threadIdx.x == 0) g_mask[b * (Cn - 1) + t] = (unsigned char)(all != 0);
}

// ---------------------------------------------------------------------------
// Sliding-window attention (SIMT fp32); epilogue writes split-fp16 directly.
// ---------------------------------------------------------------------------
constexpr int S_HQ = 0;
constexpr int S_KT = S_HQ + 64 * 68;
constexpr int S_V  = S_KT + 64 * 196;
constexpr int S_S  = S_V + 128 * 68;
constexpr int S_WT = S_S + 64 * 196;
constexpr int ATT_SMEM_FLOATS = S_WT + 128 * 68;

__global__ __launch_bounds__(256) void attn_kernel() {
    extern __shared__ __align__(16) float sm[];
    float* sHqT = sm + S_HQ;
    float* sKT  = sm + S_KT;
    float* sV   = sm + S_V;
    float* sS   = sm + S_S;
    float* sWT  = sm + S_WT;

    int q0 = blockIdx.x * 64;
    int h = blockIdx.y, b = blockIdx.z;
    int tid = threadIdx.x;

    for (int i = tid; i < 128 * 68; i += 256) sWT[i] = 0.f;

    for (int li = tid; li < 1024; li += 256) {
        int q = li >> 4, d4 = (li & 15) << 2;
        float4 v = *(const float4*)(g_hq + (size_t)(b * Qn + q0 + q) * 512 + h * 64 + d4);
        sHqT[(d4 + 0) * 68 + q] = v.x; sHqT[(d4 + 1) * 68 + q] = v.y;
        sHqT[(d4 + 2) * 68 + q] = v.z; sHqT[(d4 + 3) * 68 + q] = v.w;
    }
    for (int li = tid; li < 2048; li += 256) {
        int j = li >> 4, d4 = (li & 15) << 2;
        float4 v = make_float4(0.f, 0.f, 0.f, 0.f);
        if (j < 127) v = *(const float4*)(g_kv + (size_t)(b * Tn + q0 + j) * 1024 + h * 64 + d4);
        sKT[(d4 + 0) * 196 + j] = v.x; sKT[(d4 + 1) * 196 + j] = v.y;
        sKT[(d4 + 2) * 196 + j] = v.z; sKT[(d4 + 3) * 196 + j] = v.w;
    }
    for (int li = tid; li < 1024; li += 256) {
        int c = li >> 4, d4 = (li & 15) << 2;
        float4 v = *(const float4*)(g_hr + (size_t)c * 512 + h * 64 + d4);
        sKT[(d4 + 0) * 196 + 128 + c] = v.x; sKT[(d4 + 1) * 196 + 128 + c] = v.y;
        sKT[(d4 + 2) * 196 + 128 + c] = v.z; sKT[(d4 + 3) * 196 + 128 + c] = v.w;
    }
    for (int li = tid; li < 2048; li += 256) {
        int j = li >> 4, d4 = (li & 15) << 2;
        float4 v = make_float4(0.f, 0.f, 0.f, 0.f);
        if (j < 127) v = *(const float4*)(g_kv + (size_t)(b * Tn + q0 + j) * 1024 + 512 + h * 64 + d4);
        *(float4*)(sV + j * 68 + d4) = v;
    }
    __syncthreads();

    int tr = tid >> 4, tc = tid & 15;

    {
        float acc[4][12] = {};
#pragma unroll 4
        for (int d = 0; d < 64; d++) {
            float4 av = *(const float4*)(sHqT + d * 68 + tr * 4);
            float a[4] = {av.x, av.y, av.z, av.w};
            float bb[12];
#pragma unroll
            for (int m = 0; m < 3; m++) {
                float4 bv = *(const float4*)(sKT + d * 196 + tc * 12 + m * 4);
                bb[m * 4 + 0] = bv.x; bb[m * 4 + 1] = bv.y;
                bb[m * 4 + 2] = bv.z; bb[m * 4 + 3] = bv.w;
            }
#pragma unroll
            for (int i = 0; i < 4; i++)
#pragma unroll
                for (int j = 0; j < 12; j++)
                    acc[i][j] = fmaf(a[i], bb[j], acc[i][j]);
        }
#pragma unroll
        for (int i = 0; i < 4; i++)
#pragma unroll
            for (int m = 0; m < 3; m++)
                *(float4*)(sS + (tr * 4 + i) * 196 + tc * 12 + m * 4) =
                    make_float4(acc[i][m * 4 + 0], acc[i][m * 4 + 1],
                                acc[i][m * 4 + 2], acc[i][m * 4 + 3]);
    }
    __syncthreads();

    {
        int lane = tid & 31, w = tid >> 5;
#pragma unroll
        for (int r = 0; r < 8; r++) {
            int q = w * 8 + r;
            int c0 = lane, c1 = lane + 32;
            float s0 = (sS[q * 196 + q + c0] + sS[q * 196 + 128 + c0]) * 0.125f;
            float s1 = (sS[q * 196 + q + c1] + sS[q * 196 + 128 + c1]) * 0.125f;
            int jg0 = q0 + q + c0, jg1 = q0 + q + c1;
            if (jg0 < Cn - 1 && g_mask[b * (Cn - 1) + jg0]) s0 = -1e30f;
            if (jg1 < Cn - 1 && g_mask[b * (Cn - 1) + jg1]) s1 = -1e30f;
            float mx = fmaxf(s0, s1);
#pragma unroll
            for (int o = 16; o; o >>= 1) mx = fmaxf(mx, __shfl_xor_sync(0xffffffffu, mx, o));
            float e0 = __expf(s0 - mx), e1 = __expf(s1 - mx);
            float sum = e0 + e1;
#pragma unroll
            for (int o = 16; o; o >>= 1) sum += __shfl_xor_sync(0xffffffffu, sum, o);
            float inv = 1.f / sum;
            sWT[(q + c0) * 68 + q] = e0 * inv;
            sWT[(q + c1) * 68 + q] = e1 * inv;
        }
    }
    __syncthreads();

    {
        float o[4][4] = {};
#pragma unroll 4
        for (int j = 0; j < 128; j++) {
            float4 av = *(const float4*)(sWT + j * 68 + tr * 4);
            float4 bv = *(const float4*)(sV + j * 68 + tc * 4);
            float a[4] = {av.x, av.y, av.z, av.w};
            float bb[4] = {bv.x, bv.y, bv.z, bv.w};
#pragma unroll
            for (int i = 0; i < 4; i++)
#pragma unroll
                for (int jj = 0; jj < 4; jj++)
                    o[i][jj] = fmaf(a[i], bb[jj], o[i][jj]);
        }
#pragma unroll
        for (int i = 0; i < 4; i++) {
            int q = tr * 4 + i;
            __half2 h0 = __floats2half2_rn(o[i][0], o[i][1]);
            __half2 h1 = __floats2half2_rn(o[i][2], o[i][3]);
            __half2 l0 = __floats2half2_rn((o[i][0] - __low2float(h0)) * 2048.f,
                                           (o[i][1] - __high2float(h0)) * 2048.f);
            __half2 l1 = __floats2half2_rn((o[i][2] - __low2float(h1)) * 2048.f,
                                           (o[i][3] - __high2float(h1)) * 2048.f);
            __half* rb = g_atth + (size_t)(b * Qn + q0 + q) * KS + h * 64 + tc * 4;
            *(__half2*)(rb) = h0;        *(__half2*)(rb + 2) = h1;
            *(__half2*)(rb + 512) = l0;  *(__half2*)(rb + 512 + 2) = l1;
        }
    }
}

}  // namespace

// ---------------------------------------------------------------------------
extern "C" void kernel_launch(void* const* d_in, const int* in_sizes, int n_in,
                              void* d_out, int out_size) {
    const float* x   = (const float*)d_in[0];
    const float* r   = (const float*)d_in[1];
    const float* Wkv = (const float*)d_in[2];
    const float* Wq  = (const float*)d_in[3];
    const float* bq  = (const float*)d_in[4];
    const float* Wr  = (const float*)d_in[5];
    const float* Wo  = (const float*)d_in[6];
    float* out = (float*)d_out;

    float *kvp, *hqp;
    __half *xh, *atth, *Wkvh, *Wqh, *Woh;
    cudaGetSymbolAddress((void**)&kvp,  g_kv);
    cudaGetSymbolAddress((void**)&hqp,  g_hq);
    cudaGetSymbolAddress((void**)&xh,   g_xh);
    cudaGetSymbolAddress((void**)&atth, g_atth);
    cudaGetSymbolAddress((void**)&Wkvh, g_Wkvh);
    cudaGetSymbolAddress((void**)&Wqh,  g_Wqh);
    cudaGetSymbolAddress((void**)&Woh,  g_Woh);

    cudaFuncSetAttribute(attn_kernel, cudaFuncAttributeMaxDynamicSharedMemorySize,
                         ATT_SMEM_FLOATS * (int)sizeof(float));
    cudaFuncSetAttribute(hgemm_fused_kernel<false, false>,
                         cudaFuncAttributeMaxDynamicSharedMemorySize, HG_SMEM);
    cudaFuncSetAttribute(hgemm_fused_kernel<true, true>,
                         cudaFuncAttributeMaxDynamicSharedMemorySize, HG_SMEM);

    // launches 1-3: conversions + mask (kv GEMM lands at launch 4 for ncu)
    convX_kernel<<<(Bn * Tn * 128 + 255) / 256, 256>>>(x, xh, Bn * Tn);
    convW_kernel<<<(512 * 256 + 255) / 256, 256>>>(Wkv, Wkvh, 1024);
    mask_kernel<<<dim3(Cn - 1, Bn), 128>>>(x);
    // 4: kv = x @ Wkv   [4222 x (512|512) x 1024]   <-- ncu profile target
    hgemm_fused_kernel<false, false><<<dim3(8, 33), 256, HG_SMEM>>>(
        xh, Wkvh, nullptr, kvp, Bn * Tn, 1024);
    // 5-6: hr = r @ Wr (fp32 split-K)
    hr_partial_kernel<<<dim3(4, 8), 256>>>(r, Wr);
    hr_reduce_kernel<<<128, 256>>>();
    // 7-8: hq = x[:,63:] @ Wq + bq
    convW_kernel<<<(512 * 128 + 255) / 256, 256>>>(Wq, Wqh, 512);
    hgemm_fused_kernel<true, true><<<dim3(4, 32), 256, HG_SMEM>>>(
        xh, Wqh, bq, hqp, Bn * Qn, 512);
    // 9: attention -> split-fp16 att
    attn_kernel<<<dim3(Qn / 64, Hn, Bn), 256, ATT_SMEM_FLOATS * sizeof(float)>>>();
    // 10-11: out = att @ Wo
    convW_kernel<<<(512 * 128 + 255) / 256, 256>>>(Wo, Woh, 512);
    hgemm_fused_kernel<false, false><<<dim3(4, 32), 256, HG_SMEM>>>(
        atth, Woh, nullptr, out, Bn * Qn, 512);
}

// round 6
// speedup vs baseline: 1.7166x; 1.0004x over previous
#include <cuda_runtime.h>
#include <cuda_fp16.h>
#include <cstdint>

namespace {

constexpr int Bn = 2, Tn = 2111, Qn = 2048, Cn = 64, Hn = 8, DMn = 512;
constexpr int KS = 1024;   // stored K width: [hi(512) | lo*2048(512)]
constexpr float INV_SCALE = 1.0f / 2048.0f;

// Scratch (device globals)
__device__ float g_kv[Bn * Tn * 1024];
__device__ float g_hq[Bn * Qn * 512];
__device__ float g_hr[Cn * 512];
__device__ float g_hrp[8 * Cn * 512];
__device__ unsigned char g_mask[Bn * (Cn - 1)];
__device__ __half g_xh[(size_t)Bn * Tn * KS];
__device__ __half g_atth[(size_t)Bn * Qn * KS];
__device__ __half g_Wkvh[KS * 1024];
__device__ __half g_Wqh[KS * 512];
__device__ __half g_Woh[KS * 512];

// ===========================================================================
// PTX helpers
// ===========================================================================
__device__ __forceinline__ uint32_t smem_u32(const void* p) {
    uint32_t a;
    asm("{ .reg .u64 t; cvta.to.shared.u64 t, %1; cvt.u32.u64 %0, t; }" : "=r"(a) : "l"(p));
    return a;
}
__device__ __forceinline__ void cpa16(uint32_t d, const void* s, int sz) {
    asm volatile("cp.async.cg.shared.global [%0], [%1], 16, %2;" :: "r"(d), "l"(s), "r"(sz));
}
__device__ __forceinline__ void cp_commit() { asm volatile("cp.async.commit_group;"); }
template <int N> __device__ __forceinline__ void cp_wait() {
    asm volatile("cp.async.wait_group %0;" :: "n"(N));
}
__device__ __forceinline__ void ldsm4(uint32_t* r, uint32_t a) {
    asm volatile("ldmatrix.sync.aligned.m8n8.x4.shared.b16 {%0,%1,%2,%3}, [%4];"
                 : "=r"(r[0]), "=r"(r[1]), "=r"(r[2]), "=r"(r[3]) : "r"(a));
}
__device__ __forceinline__ void ldsm4t(uint32_t* r, uint32_t a) {
    asm volatile("ldmatrix.sync.aligned.m8n8.x4.trans.shared.b16 {%0,%1,%2,%3}, [%4];"
                 : "=r"(r[0]), "=r"(r[1]), "=r"(r[2]), "=r"(r[3]) : "r"(a));
}
__device__ __forceinline__ void mma_f32(float* d, const uint32_t* a, uint32_t b0, uint32_t b1) {
    asm volatile(
        "mma.sync.aligned.m16n8k16.row.col.f32.f16.f16.f32 "
        "{%0,%1,%2,%3}, {%4,%5,%6,%7}, {%8,%9}, {%0,%1,%2,%3};"
        : "+f"(d[0]), "+f"(d[1]), "+f"(d[2]), "+f"(d[3])
        : "r"(a[0]), "r"(a[1]), "r"(a[2]), "r"(a[3]), "r"(b0), "r"(b1));
}
__device__ __forceinline__ void mma_f16(uint32_t* d, const uint32_t* a, uint32_t b0, uint32_t b1) {
    asm volatile(
        "mma.sync.aligned.m16n8k16.row.col.f16.f16.f16.f16 "
        "{%0,%1}, {%2,%3,%4,%5}, {%6,%7}, {%0,%1};"
        : "+r"(d[0]), "+r"(d[1])
        : "r"(a[0]), "r"(a[1]), "r"(a[2]), "r"(a[3]), "r"(b0), "r"(b1));
}

// ===========================================================================
// Fused split-fp16 HGEMM, 128x64 tile, 2 CTAs/SM:
//   C = Ahi@Bhi (fp32 acc) + (Alo'@Bhi + Ahi@Blo')/2048 (fp16 acc)
// A stored [M][1024] = [hi | lo*2048]; B stored [1024][N] = [hi ; lo*2048].
// 256 threads = 8 warps (4m x 2n), warp tile 32x32, 4-stage cp.async.
// A smem: 128 rows x 64B, swizzle unit'=(unit+(r>>1))&3 (conflict-free).
// B smem: 32 rows x 128B, swizzle unit'=unit^(r&7) (canonical).
// ===========================================================================
constexpr int OFF_AH = 0;
constexpr int OFF_AL = 8192;
constexpr int OFF_BH = 16384;
constexpr int OFF_BL = 20480;
constexpr int STG = 24576;
constexpr int NSTAGE = 4;
constexpr int HG_SMEM = STG * NSTAGE;  // 98304 (96KB) -> 2 CTAs/SM

template <bool ROWMAP, bool BIAS>
__global__ __launch_bounds__(256, 2) void hgemm_fused_kernel(
    const __half* __restrict__ A, const __half* __restrict__ Bw,
    const float* __restrict__ bias, float* __restrict__ C, int M, int N)
{
    extern __shared__ char smm[];
    uint32_t sb = smem_u32(smm);
    int tid = threadIdx.x, lane = tid & 31, wid = tid >> 5;
    int wm = wid >> 1, wn = wid & 1;
    int row0 = blockIdx.y * 128, col0 = blockIdx.x * 64;

    // A staging: 512 16B-chunks per matrix -> 2 per thread (ids tid, tid+256)
    int idA0 = tid, idA1 = tid + 256;
    int rA0 = idA0 >> 2, cA0 = idA0 & 3;
    int rA1 = idA1 >> 2, cA1 = idA1 & 3;
    int gm0 = row0 + rA0, gm1 = row0 + rA1;
    int av0 = (gm0 < M) ? 16 : 0, av1 = (gm1 < M) ? 16 : 0;
    size_t arow0 = 0, arow1 = 0;
    if (gm0 < M) arow0 = ROWMAP ? (size_t)((gm0 >> 11) * Tn + (Cn - 1) + (gm0 & (Qn - 1))) : (size_t)gm0;
    if (gm1 < M) arow1 = ROWMAP ? (size_t)((gm1 >> 11) * Tn + (Cn - 1) + (gm1 & (Qn - 1))) : (size_t)gm1;
    const __half* asrc0 = A + arow0 * KS + cA0 * 8;
    const __half* asrc1 = A + arow1 * KS + cA1 * 8;
    uint32_t adst0 = rA0 * 64 + (((cA0 + (rA0 >> 1)) & 3) << 4);
    uint32_t adst1 = rA1 * 64 + (((cA1 + (rA1 >> 1)) & 3) << 4);

    // B staging: 256 chunks per matrix -> 1 per thread
    int rB = tid >> 3, cB = tid & 7;
    const __half* bsrc = Bw + (size_t)rB * N + col0 + cB * 8;
    uint32_t bdst = rB * 128 + ((cB ^ (rB & 7)) << 4);

    auto load_stage = [&](int s, int kt) {
        int k0 = kt * 32;
        uint32_t base = sb + s * STG;
        cpa16(base + OFF_AH + adst0, asrc0 + k0, av0);
        cpa16(base + OFF_AH + adst1, asrc1 + k0, av1);
        cpa16(base + OFF_AL + adst0, asrc0 + 512 + k0, av0);
        cpa16(base + OFF_AL + adst1, asrc1 + 512 + k0, av1);
        cpa16(base + OFF_BH + bdst, bsrc + (size_t)k0 * N, 16);
        cpa16(base + OFF_BL + bdst, bsrc + (size_t)(512 + k0) * N, 16);
        cp_commit();
    };

    constexpr int KT = 512 / 32;   // 16
    load_stage(0, 0);
    load_stage(1, 1);
    load_stage(2, 2);

    float accf[2][4][4] = {};
    uint32_t acch[2][4][2] = {};

    int la_r0 = wm * 32 + (lane & 15);      // + mf*16
    int la_c0 = (lane >> 4);                // + kk*2
    int lb_r0 = (lane & 15);                // + kk*16
    int lb_c0 = wn * 4 + (lane >> 4);       // + nf*2

    for (int kt = 0; kt < KT; kt++) {
        cp_wait<2>();
        __syncthreads();
        int s = kt & (NSTAGE - 1);
        uint32_t base = sb + s * STG;
#pragma unroll
        for (int kk = 0; kk < 2; kk++) {
            uint32_t ah[2][4], al[2][4];
#pragma unroll
            for (int mf = 0; mf < 2; mf++) {
                int r = la_r0 + mf * 16;
                int c = la_c0 + kk * 2;
                uint32_t off = r * 64 + (((c + (r >> 1)) & 3) << 4);
                ldsm4(ah[mf], base + OFF_AH + off);
                ldsm4(al[mf], base + OFF_AL + off);
            }
            uint32_t bh[2][4], bl[2][4];
#pragma unroll
            for (int nf = 0; nf < 2; nf++) {
                int r = lb_r0 + kk * 16;
                int c = lb_c0 + nf * 2;
                uint32_t off = r * 128 + ((c ^ (r & 7)) << 4);
                ldsm4t(bh[nf], base + OFF_BH + off);
                ldsm4t(bl[nf], base + OFF_BL + off);
            }
#pragma unroll
            for (int mf = 0; mf < 2; mf++)
#pragma unroll
                for (int n = 0; n < 4; n++) {
                    int bi = n >> 1, br = (n & 1) * 2;
                    mma_f32(accf[mf][n], ah[mf], bh[bi][br], bh[bi][br + 1]);
                    mma_f16(acch[mf][n], al[mf], bh[bi][br], bh[bi][br + 1]);
                    mma_f16(acch[mf][n], ah[mf], bl[bi][br], bl[bi][br + 1]);
                }
        }
        if (kt + 3 < KT) load_stage((kt + 3) & (NSTAGE - 1), kt + 3);
        else cp_commit();
    }

    // ---- epilogue: combine f32 + f16/2048 (+bias), single write ----
#pragma unroll
    for (int mf = 0; mf < 2; mf++) {
        int rb = row0 + wm * 32 + mf * 16 + (lane >> 2);
#pragma unroll
        for (int n = 0; n < 4; n++) {
            int cb = col0 + wn * 32 + n * 8 + (lane & 3) * 2;
            float* a4 = accf[mf][n];
            float2 lo = __half22float2(*(__half2*)&acch[mf][n][0]);
            float2 hi = __half22float2(*(__half2*)&acch[mf][n][1]);
            float bx = 0.f, by = 0.f;
            if (BIAS) { bx = bias[cb]; by = bias[cb + 1]; }
            if (rb < M)
                *(float2*)(C + (size_t)rb * N + cb) =
                    make_float2(a4[0] + lo.x * INV_SCALE + bx, a4[1] + lo.y * INV_SCALE + by);
            if (rb + 8 < M)
                *(float2*)(C + (size_t)(rb + 8) * N + cb) =
                    make_float2(a4[2] + hi.x * INV_SCALE + bx, a4[3] + hi.y * INV_SCALE + by);
        }
    }
}

// ===========================================================================
// split-fp16 conversion kernels: [hi | lo*2048]
// ===========================================================================
__global__ void convX_kernel(const float* __restrict__ src, __half* __restrict__ dst, int rows) {
    int idx = blockIdx.x * 256 + threadIdx.x;
    if (idx >= rows * 128) return;
    int m = idx >> 7, k4 = (idx & 127) << 2;
    float4 v = *(const float4*)(src + (size_t)m * 512 + k4);
    __half2 h0 = __floats2half2_rn(v.x, v.y);
    __half2 h1 = __floats2half2_rn(v.z, v.w);
    __half2 l0 = __floats2half2_rn((v.x - __low2float(h0)) * 2048.f, (v.y - __high2float(h0)) * 2048.f);
    __half2 l1 = __floats2half2_rn((v.z - __low2float(h1)) * 2048.f, (v.w - __high2float(h1)) * 2048.f);
    __half* rb = dst + (size_t)m * KS;
    *(__half2*)(rb + k4) = h0;        *(__half2*)(rb + k4 + 2) = h1;
    *(__half2*)(rb + 512 + k4) = l0;  *(__half2*)(rb + 512 + k4 + 2) = l1;
}

__global__ void convW_kernel(const float* __restrict__ W, __half* __restrict__ dst, int N) {
    int idx = blockIdx.x * 256 + threadIdx.x;
    int nq = N >> 2;
    if (idx >= 512 * nq) return;
    int k = idx / nq, n4 = (idx - k * nq) << 2;
    float4 v = *(const float4*)(W + (size_t)k * N + n4);
    __half2 h0 = __floats2half2_rn(v.x, v.y);
    __half2 h1 = __floats2half2_rn(v.z, v.w);
    __half2 l0 = __floats2half2_rn((v.x - __low2float(h0)) * 2048.f, (v.y - __high2float(h0)) * 2048.f);
    __half2 l1 = __floats2half2_rn((v.z - __low2float(h1)) * 2048.f, (v.w - __high2float(h1)) * 2048.f);
    __half* d0 = dst + (size_t)k * N + n4;
    __half* d1 = dst + (size_t)(512 + k) * N + n4;
    *(__half2*)(d0) = h0; *(__half2*)(d0 + 2) = h1;
    *(__half2*)(d1) = l0; *(__half2*)(d1 + 2) = l1;
}

// ---------------------------------------------------------------------------
// hr = r @ Wr in fp32 SIMT, split-K 8, deterministic two-phase.
// ---------------------------------------------------------------------------
__global__ void hr_partial_kernel(const float* __restrict__ r, const float* __restrict__ Wr) {
    int cb = blockIdx.x;
    int ks = blockIdx.y;
    int t = threadIdx.x;
    int row = t & 63, cg = t >> 6;
    int k0 = ks * 64;
    float acc[32] = {};
    const float* rrow = r + row * 512 + k0;
    const float* wbase = Wr + (size_t)k0 * 512 + cb * 128 + cg * 32;
#pragma unroll 4
    for (int k = 0; k < 64; k++) {
        float a = __ldg(rrow + k);
        const float* wr = wbase + (size_t)k * 512;
#pragma unroll
        for (int c = 0; c < 32; c++) acc[c] = fmaf(a, __ldg(wr + c), acc[c]);
    }
    float* dst = g_hrp + ((size_t)ks * 64 + row) * 512 + cb * 128 + cg * 32;
#pragma unroll
    for (int c = 0; c < 32; c++) dst[c] = acc[c];
}

__global__ void hr_reduce_kernel() {
    int idx = blockIdx.x * 256 + threadIdx.x;
    if (idx >= 64 * 512) return;
    float s = 0.f;
#pragma unroll
    for (int k = 0; k < 8; k++) s += g_hrp[k * 64 * 512 + idx];
    g_hr[idx] = s;
}

// ---------------------------------------------------------------------------
// pad mask
// ---------------------------------------------------------------------------
__global__ void mask_kernel(const float* __restrict__ x) {
    int t = blockIdx.x, b = blockIdx.y;
    const float* row = x + ((size_t)b * Tn + t) * DMn;
    int zero = 1;
    for (int i = threadIdx.x; i < DMn; i += blockDim.x)
        if (row[i] != 0.f) zero = 0;
    int all = __syncthreads_and(zero);
    if (threadIdx.x == 0) g_mask[b * (Cn - 1) + t] = (unsigned char)(all != 0);
}

// ---------------------------------------------------------------------------
// Sliding-window attention (SIMT fp32); epilogue writes split-fp16 directly.
// ---------------------------------------------------------------------------
constexpr int S_HQ = 0;
constexpr int S_KT = S_HQ + 64 * 68;
constexpr int S_V  = S_KT + 64 * 196;
constexpr int S_S  = S_V + 128 * 68;
constexpr int S_WT = S_S + 64 * 196;
constexpr int ATT_SMEM_FLOATS = S_WT + 128 * 68;

__global__ __launch_bounds__(256) void attn_kernel() {
    extern __shared__ __align__(16) float sm[];
    float* sHqT = sm + S_HQ;
    float* sKT  = sm + S_KT;
    float* sV   = sm + S_V;
    float* sS   = sm + S_S;
    float* sWT  = sm + S_WT;

    int q0 = blockIdx.x * 64;
    int h = blockIdx.y, b = blockIdx.z;
    int tid = threadIdx.x;

    for (int i = tid; i < 128 * 68; i += 256) sWT[i] = 0.f;

    for (int li = tid; li < 1024; li += 256) {
        int q = li >> 4, d4 = (li & 15) << 2;
        float4 v = *(const float4*)(g_hq + (size_t)(b * Qn + q0 + q) * 512 + h * 64 + d4);
        sHqT[(d4 + 0) * 68 + q] = v.x; sHqT[(d4 + 1) * 68 + q] = v.y;
        sHqT[(d4 + 2) * 68 + q] = v.z; sHqT[(d4 + 3) * 68 + q] = v.w;
    }
    for (int li = tid; li < 2048; li += 256) {
        int j = li >> 4, d4 = (li & 15) << 2;
        float4 v = make_float4(0.f, 0.f, 0.f, 0.f);
        if (j < 127) v = *(const float4*)(g_kv + (size_t)(b * Tn + q0 + j) * 1024 + h * 64 + d4);
        sKT[(d4 + 0) * 196 + j] = v.x; sKT[(d4 + 1) * 196 + j] = v.y;
        sKT[(d4 + 2) * 196 + j] = v.z; sKT[(d4 + 3) * 196 + j] = v.w;
    }
    for (int li = tid; li < 1024; li += 256) {
        int c = li >> 4, d4 = (li & 15) << 2;
        float4 v = *(const float4*)(g_hr + (size_t)c * 512 + h * 64 + d4);
        sKT[(d4 + 0) * 196 + 128 + c] = v.x; sKT[(d4 + 1) * 196 + 128 + c] = v.y;
        sKT[(d4 + 2) * 196 + 128 + c] = v.z; sKT[(d4 + 3) * 196 + 128 + c] = v.w;
    }
    for (int li = tid; li < 2048; li += 256) {
        int j = li >> 4, d4 = (li & 15) << 2;
        float4 v = make_float4(0.f, 0.f, 0.f, 0.f);
        if (j < 127) v = *(const float4*)(g_kv + (size_t)(b * Tn + q0 + j) * 1024 + 512 + h * 64 + d4);
        *(float4*)(sV + j * 68 + d4) = v;
    }
    __syncthreads();

    int tr = tid >> 4, tc = tid & 15;

    {
        float acc[4][12] = {};
#pragma unroll 4
        for (int d = 0; d < 64; d++) {
            float4 av = *(const float4*)(sHqT + d * 68 + tr * 4);
            float a[4] = {av.x, av.y, av.z, av.w};
            float bb[12];
#pragma unroll
            for (int m = 0; m < 3; m++) {
                float4 bv = *(const float4*)(sKT + d * 196 + tc * 12 + m * 4);
                bb[m * 4 + 0] = bv.x; bb[m * 4 + 1] = bv.y;
                bb[m * 4 + 2] = bv.z; bb[m * 4 + 3] = bv.w;
            }
#pragma unroll
            for (int i = 0; i < 4; i++)
#pragma unroll
                for (int j = 0; j < 12; j++)
                    acc[i][j] = fmaf(a[i], bb[j], acc[i][j]);
        }
#pragma unroll
        for (int i = 0; i < 4; i++)
#pragma unroll
            for (int m = 0; m < 3; m++)
                *(float4*)(sS + (tr * 4 + i) * 196 + tc * 12 + m * 4) =
                    make_float4(acc[i][m * 4 + 0], acc[i][m * 4 + 1],
                                acc[i][m * 4 + 2], acc[i][m * 4 + 3]);
    }
    __syncthreads();

    {
        int lane = tid & 31, w = tid >> 5;
#pragma unroll
        for (int r = 0; r < 8; r++) {
            int q = w * 8 + r;
            int c0 = lane, c1 = lane + 32;
            float s0 = (sS[q * 196 + q + c0] + sS[q * 196 + 128 + c0]) * 0.125f;
            float s1 = (sS[q * 196 + q + c1] + sS[q * 196 + 128 + c1]) * 0.125f;
            int jg0 = q0 + q + c0, jg1 = q0 + q + c1;
            if (jg0 < Cn - 1 && g_mask[b * (Cn - 1) + jg0]) s0 = -1e30f;
            if (jg1 < Cn - 1 && g_mask[b * (Cn - 1) + jg1]) s1 = -1e30f;
            float mx = fmaxf(s0, s1);
#pragma unroll
            for (int o = 16; o; o >>= 1) mx = fmaxf(mx, __shfl_xor_sync(0xffffffffu, mx, o));
            float e0 = __expf(s0 - mx), e1 = __expf(s1 - mx);
            float sum = e0 + e1;
#pragma unroll
            for (int o = 16; o; o >>= 1) sum += __shfl_xor_sync(0xffffffffu, sum, o);
            float inv = 1.f / sum;
            sWT[(q + c0) * 68 + q] = e0 * inv;
            sWT[(q + c1) * 68 + q] = e1 * inv;
        }
    }
    __syncthreads();

    {
        float o[4][4] = {};
#pragma unroll 4
        for (int j = 0; j < 128; j++) {
            float4 av = *(const float4*)(sWT + j * 68 + tr * 4);
            float4 bv = *(const float4*)(sV + j * 68 + tc * 4);
            float a[4] = {av.x, av.y, av.z, av.w};
            float bb[4] = {bv.x, bv.y, bv.z, bv.w};
#pragma unroll
            for (int i = 0; i < 4; i++)
#pragma unroll
                for (int jj = 0; jj < 4; jj++)
                    o[i][jj] = fmaf(a[i], bb[jj], o[i][jj]);
        }
#pragma unroll
        for (int i = 0; i < 4; i++) {
            int q = tr * 4 + i;
            __half2 h0 = __floats2half2_rn(o[i][0], o[i][1]);
            __half2 h1 = __floats2half2_rn(o[i][2], o[i][3]);
            __half2 l0 = __floats2half2_rn((o[i][0] - __low2float(h0)) * 2048.f,
                                           (o[i][1] - __high2float(h0)) * 2048.f);
            __half2 l1 = __floats2half2_rn((o[i][2] - __low2float(h1)) * 2048.f,
                                           (o[i][3] - __high2float(h1)) * 2048.f);
            __half* rb = g_atth + (size_t)(b * Qn + q0 + q) * KS + h * 64 + tc * 4;
            *(__half2*)(rb) = h0;        *(__half2*)(rb + 2) = h1;
            *(__half2*)(rb + 512) = l0;  *(__half2*)(rb + 512 + 2) = l1;
        }
    }
}

}  // namespace

// ---------------------------------------------------------------------------
extern "C" void kernel_launch(void* const* d_in, const int* in_sizes, int n_in,
                              void* d_out, int out_size) {
    const float* x   = (const float*)d_in[0];
    const float* r   = (const float*)d_in[1];
    const float* Wkv = (const float*)d_in[2];
    const float* Wq  = (const float*)d_in[3];
    const float* bq  = (const float*)d_in[4];
    const float* Wr  = (const float*)d_in[5];
    const float* Wo  = (const float*)d_in[6];
    float* out = (float*)d_out;

    float *kvp, *hqp;
    __half *xh, *atth, *Wkvh, *Wqh, *Woh;
    cudaGetSymbolAddress((void**)&kvp,  g_kv);
    cudaGetSymbolAddress((void**)&hqp,  g_hq);
    cudaGetSymbolAddress((void**)&xh,   g_xh);
    cudaGetSymbolAddress((void**)&atth, g_atth);
    cudaGetSymbolAddress((void**)&Wkvh, g_Wkvh);
    cudaGetSymbolAddress((void**)&Wqh,  g_Wqh);
    cudaGetSymbolAddress((void**)&Woh,  g_Woh);

    cudaFuncSetAttribute(attn_kernel, cudaFuncAttributeMaxDynamicSharedMemorySize,
                         ATT_SMEM_FLOATS * (int)sizeof(float));
    cudaFuncSetAttribute(hgemm_fused_kernel<false, false>,
                         cudaFuncAttributeMaxDynamicSharedMemorySize, HG_SMEM);
    cudaFuncSetAttribute(hgemm_fused_kernel<true, true>,
                         cudaFuncAttributeMaxDynamicSharedMemorySize, HG_SMEM);

    // launches 1-3: conversions + mask (kv GEMM lands at launch 4 for ncu)
    convX_kernel<<<(Bn * Tn * 128 + 255) / 256, 256>>>(x, xh, Bn * Tn);
    convW_kernel<<<(512 * 256 + 255) / 256, 256>>>(Wkv, Wkvh, 1024);
    mask_kernel<<<dim3(Cn - 1, Bn), 128>>>(x);
    // 4: kv = x @ Wkv   [4222 x (512|512) x 1024]   <-- ncu profile target
    hgemm_fused_kernel<false, false><<<dim3(16, 33), 256, HG_SMEM>>>(
        xh, Wkvh, nullptr, kvp, Bn * Tn, 1024);
    // 5-6: hr = r @ Wr (fp32 split-K)
    hr_partial_kernel<<<dim3(4, 8), 256>>>(r, Wr);
    hr_reduce_kernel<<<128, 256>>>();
    // 7-8: hq = x[:,63:] @ Wq + bq
    convW_kernel<<<(512 * 128 + 255) / 256, 256>>>(Wq, Wqh, 512);
    hgemm_fused_kernel<true, true><<<dim3(8, 32), 256, HG_SMEM>>>(
        xh, Wqh, bq, hqp, Bn * Qn, 512);
    // 9: attention -> split-fp16 att
    attn_kernel<<<dim3(Qn / 64, Hn, Bn), 256, ATT_SMEM_FLOATS * sizeof(float)>>>();
    // 10-11: out = att @ Wo
    convW_kernel<<<(512 * 128 + 255) / 256, 256>>>(Wo, Woh, 512);
    hgemm_fused_kernel<false, false><<<dim3(8, 32), 256, HG_SMEM>>>(
        atth, Woh, nullptr, out, Bn * Qn, 512);
}

// round 7
// speedup vs baseline: 1.8559x; 1.0811x over previous
#include <cuda_runtime.h>
#include <cuda_fp16.h>
#include <cstdint>

namespace {

constexpr int Bn = 2, Tn = 2111, Qn = 2048, Cn = 64, Hn = 8, DMn = 512;
constexpr int KS = 1024;   // stored A width: [hi(512) | lo*2048(512)]
constexpr float INV_SCALE = 1.0f / 2048.0f;

// Scratch (device globals)
__device__ float g_kv[Bn * Tn * 1024];
__device__ float g_hq[Bn * Qn * 512];
__device__ float g_hr[Cn * 512];
__device__ float g_hrp[8 * Cn * 512];
__device__ unsigned char g_mask[Bn * (Cn - 1)];
__device__ __half g_xh[(size_t)Bn * Tn * KS];
__device__ __half g_atth[(size_t)Bn * Qn * KS];
__device__ __half g_Wkvh[512 * 1024];      // hi only
__device__ __half g_Wqh[512 * 512];        // hi only
__device__ __half g_Woh[512 * 512];        // hi only

// ===========================================================================
// PTX helpers
// ===========================================================================
__device__ __forceinline__ uint32_t smem_u32(const void* p) {
    uint32_t a;
    asm("{ .reg .u64 t; cvta.to.shared.u64 t, %1; cvt.u32.u64 %0, t; }" : "=r"(a) : "l"(p));
    return a;
}
__device__ __forceinline__ void cpa16(uint32_t d, const void* s, int sz) {
    asm volatile("cp.async.cg.shared.global [%0], [%1], 16, %2;" :: "r"(d), "l"(s), "r"(sz));
}
__device__ __forceinline__ void cp_commit() { asm volatile("cp.async.commit_group;"); }
template <int N> __device__ __forceinline__ void cp_wait() {
    asm volatile("cp.async.wait_group %0;" :: "n"(N));
}
__device__ __forceinline__ void ldsm4(uint32_t* r, uint32_t a) {
    asm volatile("ldmatrix.sync.aligned.m8n8.x4.shared.b16 {%0,%1,%2,%3}, [%4];"
                 : "=r"(r[0]), "=r"(r[1]), "=r"(r[2]), "=r"(r[3]) : "r"(a));
}
__device__ __forceinline__ void ldsm4t(uint32_t* r, uint32_t a) {
    asm volatile("ldmatrix.sync.aligned.m8n8.x4.trans.shared.b16 {%0,%1,%2,%3}, [%4];"
                 : "=r"(r[0]), "=r"(r[1]), "=r"(r[2]), "=r"(r[3]) : "r"(a));
}
__device__ __forceinline__ void mma_f32(float* d, const uint32_t* a, uint32_t b0, uint32_t b1) {
    asm volatile(
        "mma.sync.aligned.m16n8k16.row.col.f32.f16.f16.f32 "
        "{%0,%1,%2,%3}, {%4,%5,%6,%7}, {%8,%9}, {%0,%1,%2,%3};"
        : "+f"(d[0]), "+f"(d[1]), "+f"(d[2]), "+f"(d[3])
        : "r"(a[0]), "r"(a[1]), "r"(a[2]), "r"(a[3]), "r"(b0), "r"(b1));
}
__device__ __forceinline__ void mma_f16(uint32_t* d, const uint32_t* a, uint32_t b0, uint32_t b1) {
    asm volatile(
        "mma.sync.aligned.m16n8k16.row.col.f16.f16.f16.f16 "
        "{%0,%1}, {%2,%3,%4,%5}, {%6,%7}, {%0,%1};"
        : "+r"(d[0]), "+r"(d[1])
        : "r"(a[0]), "r"(a[1]), "r"(a[2]), "r"(a[3]), "r"(b0), "r"(b1));
}

// ===========================================================================
// 2-term split HGEMM, 128x64 tile, 2 CTAs/SM:
//   C = Ahi@Bhi (fp32 acc) + (Alo' @ Bhi)/2048 (fp16 acc)
// A stored [M][1024] = [hi | lo*2048]; B stored [512][N] = hi only.
// 256 threads = 8 warps (4m x 2n), warp tile 32x32, 4-stage cp.async.
// A smem: 128 rows x 64B, swizzle unit'=(unit+(r>>1))&3.
// B smem: 32 rows x 128B, swizzle unit'=unit^(r&7).
// ===========================================================================
constexpr int OFF_AH = 0;
constexpr int OFF_AL = 8192;
constexpr int OFF_BH = 16384;
constexpr int STG = 20480;
constexpr int NSTAGE = 4;
constexpr int HG_SMEM = STG * NSTAGE;  // 81920 (80KB) -> 2 CTAs/SM

template <bool ROWMAP, bool BIAS>
__global__ __launch_bounds__(256, 2) void hgemm_fused_kernel(
    const __half* __restrict__ A, const __half* __restrict__ Bw,
    const float* __restrict__ bias, float* __restrict__ C, int M, int N)
{
    extern __shared__ char smm[];
    uint32_t sb = smem_u32(smm);
    int tid = threadIdx.x, lane = tid & 31, wid = tid >> 5;
    int wm = wid >> 1, wn = wid & 1;
    int row0 = blockIdx.y * 128, col0 = blockIdx.x * 64;

    // A staging: 512 16B-chunks per matrix -> 2 per thread
    int idA0 = tid, idA1 = tid + 256;
    int rA0 = idA0 >> 2, cA0 = idA0 & 3;
    int rA1 = idA1 >> 2, cA1 = idA1 & 3;
    int gm0 = row0 + rA0, gm1 = row0 + rA1;
    int av0 = (gm0 < M) ? 16 : 0, av1 = (gm1 < M) ? 16 : 0;
    size_t arow0 = 0, arow1 = 0;
    if (gm0 < M) arow0 = ROWMAP ? (size_t)((gm0 >> 11) * Tn + (Cn - 1) + (gm0 & (Qn - 1))) : (size_t)gm0;
    if (gm1 < M) arow1 = ROWMAP ? (size_t)((gm1 >> 11) * Tn + (Cn - 1) + (gm1 & (Qn - 1))) : (size_t)gm1;
    const __half* asrc0 = A + arow0 * KS + cA0 * 8;
    const __half* asrc1 = A + arow1 * KS + cA1 * 8;
    uint32_t adst0 = rA0 * 64 + (((cA0 + (rA0 >> 1)) & 3) << 4);
    uint32_t adst1 = rA1 * 64 + (((cA1 + (rA1 >> 1)) & 3) << 4);

    // B staging: 256 chunks -> 1 per thread
    int rB = tid >> 3, cB = tid & 7;
    const __half* bsrc = Bw + (size_t)rB * N + col0 + cB * 8;
    uint32_t bdst = rB * 128 + ((cB ^ (rB & 7)) << 4);

    auto load_stage = [&](int s, int kt) {
        int k0 = kt * 32;
        uint32_t base = sb + s * STG;
        cpa16(base + OFF_AH + adst0, asrc0 + k0, av0);
        cpa16(base + OFF_AH + adst1, asrc1 + k0, av1);
        cpa16(base + OFF_AL + adst0, asrc0 + 512 + k0, av0);
        cpa16(base + OFF_AL + adst1, asrc1 + 512 + k0, av1);
        cpa16(base + OFF_BH + bdst, bsrc + (size_t)k0 * N, 16);
        cp_commit();
    };

    constexpr int KT = 512 / 32;   // 16
    load_stage(0, 0);
    load_stage(1, 1);
    load_stage(2, 2);

    float accf[2][4][4] = {};
    uint32_t acch[2][4][2] = {};

    int la_r0 = wm * 32 + (lane & 15);      // + mf*16
    int la_c0 = (lane >> 4);                // + kk*2
    int lb_r0 = (lane & 15);                // + kk*16
    int lb_c0 = wn * 4 + (lane >> 4);       // + nf*2

    for (int kt = 0; kt < KT; kt++) {
        cp_wait<2>();
        __syncthreads();
        int s = kt & (NSTAGE - 1);
        uint32_t base = sb + s * STG;
#pragma unroll
        for (int kk = 0; kk < 2; kk++) {
            uint32_t ah[2][4], al[2][4];
#pragma unroll
            for (int mf = 0; mf < 2; mf++) {
                int r = la_r0 + mf * 16;
                int c = la_c0 + kk * 2;
                uint32_t off = r * 64 + (((c + (r >> 1)) & 3) << 4);
                ldsm4(ah[mf], base + OFF_AH + off);
                ldsm4(al[mf], base + OFF_AL + off);
            }
            uint32_t bh[2][4];
#pragma unroll
            for (int nf = 0; nf < 2; nf++) {
                int r = lb_r0 + kk * 16;
                int c = lb_c0 + nf * 2;
                uint32_t off = r * 128 + ((c ^ (r & 7)) << 4);
                ldsm4t(bh[nf], base + OFF_BH + off);
            }
#pragma unroll
            for (int mf = 0; mf < 2; mf++)
#pragma unroll
                for (int n = 0; n < 4; n++) {
                    int bi = n >> 1, br = (n & 1) * 2;
                    mma_f32(accf[mf][n], ah[mf], bh[bi][br], bh[bi][br + 1]);
                    mma_f16(acch[mf][n], al[mf], bh[bi][br], bh[bi][br + 1]);
                }
        }
        if (kt + 3 < KT) load_stage((kt + 3) & (NSTAGE - 1), kt + 3);
        else cp_commit();
    }

    // ---- epilogue: combine f32 + f16/2048 (+bias), single write ----
#pragma unroll
    for (int mf = 0; mf < 2; mf++) {
        int rb = row0 + wm * 32 + mf * 16 + (lane >> 2);
#pragma unroll
        for (int n = 0; n < 4; n++) {
            int cb = col0 + wn * 32 + n * 8 + (lane & 3) * 2;
            float* a4 = accf[mf][n];
            float2 lo = __half22float2(*(__half2*)&acch[mf][n][0]);
            float2 hi = __half22float2(*(__half2*)&acch[mf][n][1]);
            float bx = 0.f, by = 0.f;
            if (BIAS) { bx = bias[cb]; by = bias[cb + 1]; }
            if (rb < M)
                *(float2*)(C + (size_t)rb * N + cb) =
                    make_float2(a4[0] + lo.x * INV_SCALE + bx, a4[1] + lo.y * INV_SCALE + by);
            if (rb + 8 < M)
                *(float2*)(C + (size_t)(rb + 8) * N + cb) =
                    make_float2(a4[2] + hi.x * INV_SCALE + bx, a4[3] + hi.y * INV_SCALE + by);
        }
    }
}

// ===========================================================================
// conversion kernels: A -> [hi | lo*2048]; W -> hi only
// ===========================================================================
__global__ void convX_kernel(const float* __restrict__ src, __half* __restrict__ dst, int rows) {
    int idx = blockIdx.x * 256 + threadIdx.x;
    if (idx >= rows * 128) return;
    int m = idx >> 7, k4 = (idx & 127) << 2;
    float4 v = *(const float4*)(src + (size_t)m * 512 + k4);
    __half2 h0 = __floats2half2_rn(v.x, v.y);
    __half2 h1 = __floats2half2_rn(v.z, v.w);
    __half2 l0 = __floats2half2_rn((v.x - __low2float(h0)) * 2048.f, (v.y - __high2float(h0)) * 2048.f);
    __half2 l1 = __floats2half2_rn((v.z - __low2float(h1)) * 2048.f, (v.w - __high2float(h1)) * 2048.f);
    __half* rb = dst + (size_t)m * KS;
    *(__half2*)(rb + k4) = h0;        *(__half2*)(rb + k4 + 2) = h1;
    *(__half2*)(rb + 512 + k4) = l0;  *(__half2*)(rb + 512 + k4 + 2) = l1;
}

__global__ void convW_kernel(const float* __restrict__ W, __half* __restrict__ dst, int N) {
    int idx = blockIdx.x * 256 + threadIdx.x;
    int nq = N >> 2;
    if (idx >= 512 * nq) return;
    int k = idx / nq, n4 = (idx - k * nq) << 2;
    float4 v = *(const float4*)(W + (size_t)k * N + n4);
    __half2 h0 = __floats2half2_rn(v.x, v.y);
    __half2 h1 = __floats2half2_rn(v.z, v.w);
    __half* d0 = dst + (size_t)k * N + n4;
    *(__half2*)(d0) = h0; *(__half2*)(d0 + 2) = h1;
}

// ---------------------------------------------------------------------------
// hr = r @ Wr in fp32 SIMT, split-K 8, deterministic two-phase.
// ---------------------------------------------------------------------------
__global__ void hr_partial_kernel(const float* __restrict__ r, const float* __restrict__ Wr) {
    int cb = blockIdx.x;
    int ks = blockIdx.y;
    int t = threadIdx.x;
    int row = t & 63, cg = t >> 6;
    int k0 = ks * 64;
    float acc[32] = {};
    const float* rrow = r + row * 512 + k0;
    const float* wbase = Wr + (size_t)k0 * 512 + cb * 128 + cg * 32;
#pragma unroll 4
    for (int k = 0; k < 64; k++) {
        float a = __ldg(rrow + k);
        const float* wr = wbase + (size_t)k * 512;
#pragma unroll
        for (int c = 0; c < 32; c++) acc[c] = fmaf(a, __ldg(wr + c), acc[c]);
    }
    float* dst = g_hrp + ((size_t)ks * 64 + row) * 512 + cb * 128 + cg * 32;
#pragma unroll
    for (int c = 0; c < 32; c++) dst[c] = acc[c];
}

__global__ void hr_reduce_kernel() {
    int idx = blockIdx.x * 256 + threadIdx.x;
    if (idx >= 64 * 512) return;
    float s = 0.f;
#pragma unroll
    for (int k = 0; k < 8; k++) s += g_hrp[k * 64 * 512 + idx];
    g_hr[idx] = s;
}

// ---------------------------------------------------------------------------
// pad mask
// ---------------------------------------------------------------------------
__global__ void mask_kernel(const float* __restrict__ x) {
    int t = blockIdx.x, b = blockIdx.y;
    const float* row = x + ((size_t)b * Tn + t) * DMn;
    int zero = 1;
    for (int i = threadIdx.x; i < DMn; i += blockDim.x)
        if (row[i] != 0.f) zero = 0;
    int all = __syncthreads_and(zero);
    if (threadIdx.x == 0) g_mask[b * (Cn - 1) + t] = (unsigned char)(all != 0);
}

// ---------------------------------------------------------------------------
// Sliding-window attention (SIMT fp32); epilogue writes split-fp16 directly.
// ---------------------------------------------------------------------------
constexpr int S_HQ = 0;
constexpr int S_KT = S_HQ + 64 * 68;
constexpr int S_V  = S_KT + 64 * 196;
constexpr int S_S  = S_V + 128 * 68;
constexpr int S_WT = S_S + 64 * 196;
constexpr int ATT_SMEM_FLOATS = S_WT + 128 * 68;

__global__ __launch_bounds__(256) void attn_kernel() {
    extern __shared__ __align__(16) float sm[];
    float* sHqT = sm + S_HQ;
    float* sKT  = sm + S_KT;
    float* sV   = sm + S_V;
    float* sS   = sm + S_S;
    float* sWT  = sm + S_WT;

    int q0 = blockIdx.x * 64;
    int h = blockIdx.y, b = blockIdx.z;
    int tid = threadIdx.x;

    for (int i = tid; i < 128 * 68; i += 256) sWT[i] = 0.f;

    for (int li = tid; li < 1024; li += 256) {
        int q = li >> 4, d4 = (li & 15) << 2;
        float4 v = *(const float4*)(g_hq + (size_t)(b * Qn + q0 + q) * 512 + h * 64 + d4);
        sHqT[(d4 + 0) * 68 + q] = v.x; sHqT[(d4 + 1) * 68 + q] = v.y;
        sHqT[(d4 + 2) * 68 + q] = v.z; sHqT[(d4 + 3) * 68 + q] = v.w;
    }
    for (int li = tid; li < 2048; li += 256) {
        int j = li >> 4, d4 = (li & 15) << 2;
        float4 v = make_float4(0.f, 0.f, 0.f, 0.f);
        if (j < 127) v = *(const float4*)(g_kv + (size_t)(b * Tn + q0 + j) * 1024 + h * 64 + d4);
        sKT[(d4 + 0) * 196 + j] = v.x; sKT[(d4 + 1) * 196 + j] = v.y;
        sKT[(d4 + 2) * 196 + j] = v.z; sKT[(d4 + 3) * 196 + j] = v.w;
    }
    for (int li = tid; li < 1024; li += 256) {
        int c = li >> 4, d4 = (li & 15) << 2;
        float4 v = *(const float4*)(g_hr + (size_t)c * 512 + h * 64 + d4);
        sKT[(d4 + 0) * 196 + 128 + c] = v.x; sKT[(d4 + 1) * 196 + 128 + c] = v.y;
        sKT[(d4 + 2) * 196 + 128 + c] = v.z; sKT[(d4 + 3) * 196 + 128 + c] = v.w;
    }
    for (int li = tid; li < 2048; li += 256) {
        int j = li >> 4, d4 = (li & 15) << 2;
        float4 v = make_float4(0.f, 0.f, 0.f, 0.f);
        if (j < 127) v = *(const float4*)(g_kv + (size_t)(b * Tn + q0 + j) * 1024 + 512 + h * 64 + d4);
        *(float4*)(sV + j * 68 + d4) = v;
    }
    __syncthreads();

    int tr = tid >> 4, tc = tid & 15;

    {
        float acc[4][12] = {};
#pragma unroll 4
        for (int d = 0; d < 64; d++) {
            float4 av = *(const float4*)(sHqT + d * 68 + tr * 4);
            float a[4] = {av.x, av.y, av.z, av.w};
            float bb[12];
#pragma unroll
            for (int m = 0; m < 3; m++) {
                float4 bv = *(const float4*)(sKT + d * 196 + tc * 12 + m * 4);
                bb[m * 4 + 0] = bv.x; bb[m * 4 + 1] = bv.y;
                bb[m * 4 + 2] = bv.z; bb[m * 4 + 3] = bv.w;
            }
#pragma unroll
            for (int i = 0; i < 4; i++)
#pragma unroll
                for (int j = 0; j < 12; j++)
                    acc[i][j] = fmaf(a[i], bb[j], acc[i][j]);
        }
#pragma unroll
        for (int i = 0; i < 4; i++)
#pragma unroll
            for (int m = 0; m < 3; m++)
                *(float4*)(sS + (tr * 4 + i) * 196 + tc * 12 + m * 4) =
                    make_float4(acc[i][m * 4 + 0], acc[i][m * 4 + 1],
                                acc[i][m * 4 + 2], acc[i][m * 4 + 3]);
    }
    __syncthreads();

    {
        int lane = tid & 31, w = tid >> 5;
#pragma unroll
        for (int r = 0; r < 8; r++) {
            int q = w * 8 + r;
            int c0 = lane, c1 = lane + 32;
            float s0 = (sS[q * 196 + q + c0] + sS[q * 196 + 128 + c0]) * 0.125f;
            float s1 = (sS[q * 196 + q + c1] + sS[q * 196 + 128 + c1]) * 0.125f;
            int jg0 = q0 + q + c0, jg1 = q0 + q + c1;
            if (jg0 < Cn - 1 && g_mask[b * (Cn - 1) + jg0]) s0 = -1e30f;
            if (jg1 < Cn - 1 && g_mask[b * (Cn - 1) + jg1]) s1 = -1e30f;
            float mx = fmaxf(s0, s1);
#pragma unroll
            for (int o = 16; o; o >>= 1) mx = fmaxf(mx, __shfl_xor_sync(0xffffffffu, mx, o));
            float e0 = __expf(s0 - mx), e1 = __expf(s1 - mx);
            float sum = e0 + e1;
#pragma unroll
            for (int o = 16; o; o >>= 1) sum += __shfl_xor_sync(0xffffffffu, sum, o);
            float inv = 1.f / sum;
            sWT[(q + c0) * 68 + q] = e0 * inv;
            sWT[(q + c1) * 68 + q] = e1 * inv;
        }
    }
    __syncthreads();

    {
        float o[4][4] = {};
#pragma unroll 4
        for (int j = 0; j < 128; j++) {
            float4 av = *(const float4*)(sWT + j * 68 + tr * 4);
            float4 bv = *(const float4*)(sV + j * 68 + tc * 4);
            float a[4] = {av.x, av.y, av.z, av.w};
            float bb[4] = {bv.x, bv.y, bv.z, bv.w};
#pragma unroll
            for (int i = 0; i < 4; i++)
#pragma unroll
                for (int jj = 0; jj < 4; jj++)
                    o[i][jj] = fmaf(a[i], bb[jj], o[i][jj]);
        }
#pragma unroll
        for (int i = 0; i < 4; i++) {
            int q = tr * 4 + i;
            __half2 h0 = __floats2half2_rn(o[i][0], o[i][1]);
            __half2 h1 = __floats2half2_rn(o[i][2], o[i][3]);
            __half2 l0 = __floats2half2_rn((o[i][0] - __low2float(h0)) * 2048.f,
                                           (o[i][1] - __high2float(h0)) * 2048.f);
            __half2 l1 = __floats2half2_rn((o[i][2] - __low2float(h1)) * 2048.f,
                                           (o[i][3] - __high2float(h1)) * 2048.f);
            __half* rb = g_atth + (size_t)(b * Qn + q0 + q) * KS + h * 64 + tc * 4;
            *(__half2*)(rb) = h0;        *(__half2*)(rb + 2) = h1;
            *(__half2*)(rb + 512) = l0;  *(__half2*)(rb + 512 + 2) = l1;
        }
    }
}

}  // namespace

// ---------------------------------------------------------------------------
extern "C" void kernel_launch(void* const* d_in, const int* in_sizes, int n_in,
                              void* d_out, int out_size) {
    const float* x   = (const float*)d_in[0];
    const float* r   = (const float*)d_in[1];
    const float* Wkv = (const float*)d_in[2];
    const float* Wq  = (const float*)d_in[3];
    const float* bq  = (const float*)d_in[4];
    const float* Wr  = (const float*)d_in[5];
    const float* Wo  = (const float*)d_in[6];
    float* out = (float*)d_out;

    float *kvp, *hqp;
    __half *xh, *atth, *Wkvh, *Wqh, *Woh;
    cudaGetSymbolAddress((void**)&kvp,  g_kv);
    cudaGetSymbolAddress((void**)&hqp,  g_hq);
    cudaGetSymbolAddress((void**)&xh,   g_xh);
    cudaGetSymbolAddress((void**)&atth, g_atth);
    cudaGetSymbolAddress((void**)&Wkvh, g_Wkvh);
    cudaGetSymbolAddress((void**)&Wqh,  g_Wqh);
    cudaGetSymbolAddress((void**)&Woh,  g_Woh);

    cudaFuncSetAttribute(attn_kernel, cudaFuncAttributeMaxDynamicSharedMemorySize,
                         ATT_SMEM_FLOATS * (int)sizeof(float));
    cudaFuncSetAttribute(hgemm_fused_kernel<false, false>,
                         cudaFuncAttributeMaxDynamicSharedMemorySize, HG_SMEM);
    cudaFuncSetAttribute(hgemm_fused_kernel<true, true>,
                         cudaFuncAttributeMaxDynamicSharedMemorySize, HG_SMEM);

    // launches 1-3: conversions + mask (kv GEMM lands at launch 4 for ncu)
    convX_kernel<<<(Bn * Tn * 128 + 255) / 256, 256>>>(x, xh, Bn * Tn);
    convW_kernel<<<(512 * 256 + 255) / 256, 256>>>(Wkv, Wkvh, 1024);
    mask_kernel<<<dim3(Cn - 1, Bn), 128>>>(x);
    // 4: kv = x @ Wkv   <-- ncu profile target
    hgemm_fused_kernel<false, false><<<dim3(16, 33), 256, HG_SMEM>>>(
        xh, Wkvh, nullptr, kvp, Bn * Tn, 1024);
    // 5-6: hr = r @ Wr (fp32 split-K)
    hr_partial_kernel<<<dim3(4, 8), 256>>>(r, Wr);
    hr_reduce_kernel<<<128, 256>>>();
    // 7-8: hq = x[:,63:] @ Wq + bq
    convW_kernel<<<(512 * 128 + 255) / 256, 256>>>(Wq, Wqh, 512);
    hgemm_fused_kernel<true, true><<<dim3(8, 32), 256, HG_SMEM>>>(
        xh, Wqh, bq, hqp, Bn * Qn, 512);
    // 9: attention -> split-fp16 att
    attn_kernel<<<dim3(Qn / 64, Hn, Bn), 256, ATT_SMEM_FLOATS * sizeof(float)>>>();
    // 10-11: out = att @ Wo
    convW_kernel<<<(512 * 128 + 255) / 256, 256>>>(Wo, Woh, 512);
    hgemm_fused_kernel<false, false><<<dim3(8, 32), 256, HG_SMEM>>>(
        atth, Woh, nullptr, out, Bn * Qn, 512);
}

// round 8
// speedup vs baseline: 2.4988x; 1.3465x over previous
#include <cuda_runtime.h>
#include <cuda_fp16.h>
#include <cstdint>

namespace {

constexpr int Bn = 2, Tn = 2111, Qn = 2048, Cn = 64, Hn = 8, DMn = 512;
constexpr int KS = 1024;   // stored A width: [hi(512) | lo*2048(512)]
constexpr float INV_SCALE = 1.0f / 2048.0f;

// Scratch (device globals)
__device__ float g_proj[(size_t)Bn * Tn * 1536];   // [k(512)|v(512)|hq(512)]
__device__ float g_hr[Cn * 512];
__device__ float g_hrp[8 * Cn * 512];
__device__ float g_bias[1536];
__device__ unsigned char g_mask[Bn * (Cn - 1)];
__device__ __half g_xh[(size_t)Bn * Tn * KS];
__device__ __half g_atth[(size_t)Bn * Qn * KS];
__device__ __half g_Wh[512 * 1536];                // [Wkv | Wq] hi
__device__ __half g_Woh[512 * 512];                // Wo hi

// ===========================================================================
// PTX helpers
// ===========================================================================
__device__ __forceinline__ uint32_t smem_u32(const void* p) {
    uint32_t a;
    asm("{ .reg .u64 t; cvta.to.shared.u64 t, %1; cvt.u32.u64 %0, t; }" : "=r"(a) : "l"(p));
    return a;
}
__device__ __forceinline__ void cpa16(uint32_t d, const void* s, int sz) {
    asm volatile("cp.async.cg.shared.global [%0], [%1], 16, %2;" :: "r"(d), "l"(s), "r"(sz));
}
__device__ __forceinline__ void cp_commit() { asm volatile("cp.async.commit_group;"); }
template <int N> __device__ __forceinline__ void cp_wait() {
    asm volatile("cp.async.wait_group %0;" :: "n"(N));
}
__device__ __forceinline__ void ldsm4(uint32_t* r, uint32_t a) {
    asm volatile("ldmatrix.sync.aligned.m8n8.x4.shared.b16 {%0,%1,%2,%3}, [%4];"
                 : "=r"(r[0]), "=r"(r[1]), "=r"(r[2]), "=r"(r[3]) : "r"(a));
}
__device__ __forceinline__ void ldsm4t(uint32_t* r, uint32_t a) {
    asm volatile("ldmatrix.sync.aligned.m8n8.x4.trans.shared.b16 {%0,%1,%2,%3}, [%4];"
                 : "=r"(r[0]), "=r"(r[1]), "=r"(r[2]), "=r"(r[3]) : "r"(a));
}
__device__ __forceinline__ void mma_f32(float* d, const uint32_t* a, uint32_t b0, uint32_t b1) {
    asm volatile(
        "mma.sync.aligned.m16n8k16.row.col.f32.f16.f16.f32 "
        "{%0,%1,%2,%3}, {%4,%5,%6,%7}, {%8,%9}, {%0,%1,%2,%3};"
        : "+f"(d[0]), "+f"(d[1]), "+f"(d[2]), "+f"(d[3])
        : "r"(a[0]), "r"(a[1]), "r"(a[2]), "r"(a[3]), "r"(b0), "r"(b1));
}
__device__ __forceinline__ void mma_f16(uint32_t* d, const uint32_t* a, uint32_t b0, uint32_t b1) {
    asm volatile(
        "mma.sync.aligned.m16n8k16.row.col.f16.f16.f16.f16 "
        "{%0,%1}, {%2,%3,%4,%5}, {%6,%7}, {%0,%1};"
        : "+r"(d[0]), "+r"(d[1])
        : "r"(a[0]), "r"(a[1]), "r"(a[2]), "r"(a[3]), "r"(b0), "r"(b1));
}

// ===========================================================================
// 2-term split HGEMM, 128x64 tile, 2 CTAs/SM:
//   C = Ahi@Bhi (fp32 acc) + (Alo' @ Bhi)/2048 (fp16 acc) [+bias]
// ===========================================================================
constexpr int OFF_AH = 0;
constexpr int OFF_AL = 8192;
constexpr int OFF_BH = 16384;
constexpr int STG = 20480;
constexpr int NSTAGE = 4;
constexpr int HG_SMEM = STG * NSTAGE;  // 80KB -> 2 CTAs/SM

template <bool BIAS>
__global__ __launch_bounds__(256, 2) void hgemm_fused_kernel(
    const __half* __restrict__ A, const __half* __restrict__ Bw,
    const float* __restrict__ bias, float* __restrict__ C, int M, int N)
{
    extern __shared__ char smm[];
    uint32_t sb = smem_u32(smm);
    int tid = threadIdx.x, lane = tid & 31, wid = tid >> 5;
    int wm = wid >> 1, wn = wid & 1;
    int row0 = blockIdx.y * 128, col0 = blockIdx.x * 64;

    int idA0 = tid, idA1 = tid + 256;
    int rA0 = idA0 >> 2, cA0 = idA0 & 3;
    int rA1 = idA1 >> 2, cA1 = idA1 & 3;
    int gm0 = row0 + rA0, gm1 = row0 + rA1;
    int av0 = (gm0 < M) ? 16 : 0, av1 = (gm1 < M) ? 16 : 0;
    size_t arow0 = (gm0 < M) ? (size_t)gm0 : 0;
    size_t arow1 = (gm1 < M) ? (size_t)gm1 : 0;
    const __half* asrc0 = A + arow0 * KS + cA0 * 8;
    const __half* asrc1 = A + arow1 * KS + cA1 * 8;
    uint32_t adst0 = rA0 * 64 + (((cA0 + (rA0 >> 1)) & 3) << 4);
    uint32_t adst1 = rA1 * 64 + (((cA1 + (rA1 >> 1)) & 3) << 4);

    int rB = tid >> 3, cB = tid & 7;
    const __half* bsrc = Bw + (size_t)rB * N + col0 + cB * 8;
    uint32_t bdst = rB * 128 + ((cB ^ (rB & 7)) << 4);

    auto load_stage = [&](int s, int kt) {
        int k0 = kt * 32;
        uint32_t base = sb + s * STG;
        cpa16(base + OFF_AH + adst0, asrc0 + k0, av0);
        cpa16(base + OFF_AH + adst1, asrc1 + k0, av1);
        cpa16(base + OFF_AL + adst0, asrc0 + 512 + k0, av0);
        cpa16(base + OFF_AL + adst1, asrc1 + 512 + k0, av1);
        cpa16(base + OFF_BH + bdst, bsrc + (size_t)k0 * N, 16);
        cp_commit();
    };

    constexpr int KT = 512 / 32;   // 16
    load_stage(0, 0);
    load_stage(1, 1);
    load_stage(2, 2);

    float accf[2][4][4] = {};
    uint32_t acch[2][4][2] = {};

    int la_r0 = wm * 32 + (lane & 15);
    int la_c0 = (lane >> 4);
    int lb_r0 = (lane & 15);
    int lb_c0 = wn * 4 + (lane >> 4);

    for (int kt = 0; kt < KT; kt++) {
        cp_wait<2>();
        __syncthreads();
        int s = kt & (NSTAGE - 1);
        uint32_t base = sb + s * STG;
#pragma unroll
        for (int kk = 0; kk < 2; kk++) {
            uint32_t ah[2][4], al[2][4];
#pragma unroll
            for (int mf = 0; mf < 2; mf++) {
                int r = la_r0 + mf * 16;
                int c = la_c0 + kk * 2;
                uint32_t off = r * 64 + (((c + (r >> 1)) & 3) << 4);
                ldsm4(ah[mf], base + OFF_AH + off);
                ldsm4(al[mf], base + OFF_AL + off);
            }
            uint32_t bh[2][4];
#pragma unroll
            for (int nf = 0; nf < 2; nf++) {
                int r = lb_r0 + kk * 16;
                int c = lb_c0 + nf * 2;
                uint32_t off = r * 128 + ((c ^ (r & 7)) << 4);
                ldsm4t(bh[nf], base + OFF_BH + off);
            }
#pragma unroll
            for (int mf = 0; mf < 2; mf++)
#pragma unroll
                for (int n = 0; n < 4; n++) {
                    int bi = n >> 1, br = (n & 1) * 2;
                    mma_f32(accf[mf][n], ah[mf], bh[bi][br], bh[bi][br + 1]);
                    mma_f16(acch[mf][n], al[mf], bh[bi][br], bh[bi][br + 1]);
                }
        }
        if (kt + 3 < KT) load_stage((kt + 3) & (NSTAGE - 1), kt + 3);
        else cp_commit();
    }

#pragma unroll
    for (int mf = 0; mf < 2; mf++) {
        int rb = row0 + wm * 32 + mf * 16 + (lane >> 2);
#pragma unroll
        for (int n = 0; n < 4; n++) {
            int cb = col0 + wn * 32 + n * 8 + (lane & 3) * 2;
            float* a4 = accf[mf][n];
            float2 lo = __half22float2(*(__half2*)&acch[mf][n][0]);
            float2 hi = __half22float2(*(__half2*)&acch[mf][n][1]);
            float bx = 0.f, by = 0.f;
            if (BIAS) { bx = bias[cb]; by = bias[cb + 1]; }
            if (rb < M)
                *(float2*)(C + (size_t)rb * N + cb) =
                    make_float2(a4[0] + lo.x * INV_SCALE + bx, a4[1] + lo.y * INV_SCALE + by);
            if (rb + 8 < M)
                *(float2*)(C + (size_t)(rb + 8) * N + cb) =
                    make_float2(a4[2] + hi.x * INV_SCALE + bx, a4[3] + hi.y * INV_SCALE + by);
        }
    }
}

// ===========================================================================
// conversions
// ===========================================================================
__global__ void convX_kernel(const float* __restrict__ src, __half* __restrict__ dst, int rows) {
    int idx = blockIdx.x * 256 + threadIdx.x;
    if (idx >= rows * 128) return;
    int m = idx >> 7, k4 = (idx & 127) << 2;
    float4 v = *(const float4*)(src + (size_t)m * 512 + k4);
    __half2 h0 = __floats2half2_rn(v.x, v.y);
    __half2 h1 = __floats2half2_rn(v.z, v.w);
    __half2 l0 = __floats2half2_rn((v.x - __low2float(h0)) * 2048.f, (v.y - __high2float(h0)) * 2048.f);
    __half2 l1 = __floats2half2_rn((v.z - __low2float(h1)) * 2048.f, (v.w - __high2float(h1)) * 2048.f);
    __half* rb = dst + (size_t)m * KS;
    *(__half2*)(rb + k4) = h0;        *(__half2*)(rb + k4 + 2) = h1;
    *(__half2*)(rb + 512 + k4) = l0;  *(__half2*)(rb + 512 + k4 + 2) = l1;
}

// [Wkv | Wq] -> g_Wh [512][1536] (hi only) + g_bias [0(1024) | bq(512)]
__global__ void convW2_kernel(const float* __restrict__ Wkv, const float* __restrict__ Wq,
                              const float* __restrict__ bq) {
    int idx = blockIdx.x * 256 + threadIdx.x;
    if (idx < 384) {
        float4 v = make_float4(0.f, 0.f, 0.f, 0.f);
        int n4 = idx * 4;
        if (n4 >= 1024) v = *(const float4*)(bq + n4 - 1024);
        *(float4*)(g_bias + n4) = v;
    }
    if (idx >= 512 * 384) return;
    int k = idx / 384, n4 = (idx - k * 384) * 4;
    float4 v = (n4 < 1024) ? *(const float4*)(Wkv + (size_t)k * 1024 + n4)
                           : *(const float4*)(Wq + (size_t)k * 512 + n4 - 1024);
    __half* d0 = g_Wh + (size_t)k * 1536 + n4;
    *(__half2*)(d0) = __floats2half2_rn(v.x, v.y);
    *(__half2*)(d0 + 2) = __floats2half2_rn(v.z, v.w);
}

__global__ void convWo_kernel(const float* __restrict__ W) {
    int idx = blockIdx.x * 256 + threadIdx.x;
    if (idx >= 512 * 128) return;
    int k = idx >> 7, n4 = (idx & 127) << 2;
    float4 v = *(const float4*)(W + (size_t)k * 512 + n4);
    __half* d0 = g_Woh + (size_t)k * 512 + n4;
    *(__half2*)(d0) = __floats2half2_rn(v.x, v.y);
    *(__half2*)(d0 + 2) = __floats2half2_rn(v.z, v.w);
}

// ---------------------------------------------------------------------------
// hr = r @ Wr fp32 split-K
// ---------------------------------------------------------------------------
__global__ void hr_partial_kernel(const float* __restrict__ r, const float* __restrict__ Wr) {
    int cb = blockIdx.x, ks = blockIdx.y, t = threadIdx.x;
    int row = t & 63, cg = t >> 6;
    int k0 = ks * 64;
    float acc[32] = {};
    const float* rrow = r + row * 512 + k0;
    const float* wbase = Wr + (size_t)k0 * 512 + cb * 128 + cg * 32;
#pragma unroll 4
    for (int k = 0; k < 64; k++) {
        float a = __ldg(rrow + k);
        const float* wr = wbase + (size_t)k * 512;
#pragma unroll
        for (int c = 0; c < 32; c++) acc[c] = fmaf(a, __ldg(wr + c), acc[c]);
    }
    float* dst = g_hrp + ((size_t)ks * 64 + row) * 512 + cb * 128 + cg * 32;
#pragma unroll
    for (int c = 0; c < 32; c++) dst[c] = acc[c];
}

__global__ void hr_reduce_kernel() {
    int idx = blockIdx.x * 256 + threadIdx.x;
    if (idx >= 64 * 512) return;
    float s = 0.f;
#pragma unroll
    for (int k = 0; k < 8; k++) s += g_hrp[k * 64 * 512 + idx];
    g_hr[idx] = s;
}

// ---------------------------------------------------------------------------
// pad mask
// ---------------------------------------------------------------------------
__global__ void mask_kernel(const float* __restrict__ x) {
    int t = blockIdx.x, b = blockIdx.y;
    const float* row = x + ((size_t)b * Tn + t) * DMn;
    int zero = 1;
    for (int i = threadIdx.x; i < DMn; i += blockDim.x)
        if (row[i] != 0.f) zero = 0;
    int all = __syncthreads_and(zero);
    if (threadIdx.x == 0) g_mask[b * (Cn - 1) + t] = (unsigned char)(all != 0);
}

// ---------------------------------------------------------------------------
// Tensor-core attention. One block per (b, h, 64-query tile), 256 thr, 2/SM.
// Scores: S[64q][192n] = hq[64][64] @ KC^T  (fp16 in, f32 acc -> fp16 smem)
// Out:    O[64q][64d]  = W[64][128] @ (Vhi + Vlo/2048)   (f32 + f16 acc)
// Layout strides chosen so row-stride ≡ 1 (mod 8) 16B units => conflict-free.
// ---------------------------------------------------------------------------
constexpr int AS_HQ = 0;                  // [64][72]  A scores (ldsm4)
constexpr int AS_KC = AS_HQ + 64 * 72;    // [64][200] B scores [d][j] (ldsm4t)
constexpr int AS_S  = AS_KC + 64 * 200;   // [64][200] scores fp16
constexpr int AS_W  = AS_S + 64 * 200;    // [64][136] A out (ldsm4)
constexpr int AS_VH = AS_W + 64 * 136;    // [128][72] B out hi (ldsm4t)
constexpr int AS_VL = AS_VH + 128 * 72;   // [128][72] B out lo (ldsm4t)
constexpr int AS_TOTAL = AS_VL + 128 * 72;        // 57344 halves
constexpr int ATT_SMEM = AS_TOTAL * 2;            // 114688 B

__global__ __launch_bounds__(256, 2) void attn_kernel() {
    extern __shared__ __align__(16) __half sm[];
    __half* sHq = sm + AS_HQ;
    __half* sKC = sm + AS_KC;
    __half* sS  = sm + AS_S;
    __half* sW  = sm + AS_W;
    __half* sVh = sm + AS_VH;
    __half* sVl = sm + AS_VL;

    int q0 = blockIdx.x * 64;
    int h = blockIdx.y, b = blockIdx.z;
    int tid = threadIdx.x, lane = tid & 31, wid = tid >> 5;
    int wm = wid >> 1, wn = wid & 1;

    // zero weight matrix
    for (int i = tid; i < 64 * 136 / 2; i += 256) ((uint32_t*)sW)[i] = 0;

    const float* pbase = g_proj + (size_t)(b * Tn + q0) * 1536;

    // hq tile: [q][d] fp16
    for (int li = tid; li < 1024; li += 256) {
        int q = li >> 4, d4 = (li & 15) << 2;
        float4 v = *(const float4*)(pbase + (size_t)(63 + q) * 1536 + 1024 + h * 64 + d4);
        *(__half2*)(sHq + q * 72 + d4) = __floats2half2_rn(v.x, v.y);
        *(__half2*)(sHq + q * 72 + d4 + 2) = __floats2half2_rn(v.z, v.w);
    }
    // K window transposed: sKC[d][j], j=127 zero
    for (int li = tid; li < 2048; li += 256) {
        int j = li >> 4, d4 = (li & 15) << 2;
        float4 v = make_float4(0.f, 0.f, 0.f, 0.f);
        if (j < 127) v = *(const float4*)(pbase + (size_t)j * 1536 + h * 64 + d4);
        sKC[(d4 + 0) * 200 + j] = __float2half_rn(v.x);
        sKC[(d4 + 1) * 200 + j] = __float2half_rn(v.y);
        sKC[(d4 + 2) * 200 + j] = __float2half_rn(v.z);
        sKC[(d4 + 3) * 200 + j] = __float2half_rn(v.w);
    }
    // hr transposed: sKC[d][128+c]
    for (int li = tid; li < 1024; li += 256) {
        int c = li >> 4, d4 = (li & 15) << 2;
        float4 v = *(const float4*)(g_hr + (size_t)c * 512 + h * 64 + d4);
        sKC[(d4 + 0) * 200 + 128 + c] = __float2half_rn(v.x);
        sKC[(d4 + 1) * 200 + 128 + c] = __float2half_rn(v.y);
        sKC[(d4 + 2) * 200 + 128 + c] = __float2half_rn(v.z);
        sKC[(d4 + 3) * 200 + 128 + c] = __float2half_rn(v.w);
    }
    // V window split: sVh/sVl [j][d], j=127 zero
    for (int li = tid; li < 2048; li += 256) {
        int j = li >> 4, d4 = (li & 15) << 2;
        float4 v = make_float4(0.f, 0.f, 0.f, 0.f);
        if (j < 127) v = *(const float4*)(pbase + (size_t)j * 1536 + 512 + h * 64 + d4);
        __half2 h0 = __floats2half2_rn(v.x, v.y);
        __half2 h1 = __floats2half2_rn(v.z, v.w);
        __half2 l0 = __floats2half2_rn((v.x - __low2float(h0)) * 2048.f,
                                       (v.y - __high2float(h0)) * 2048.f);
        __half2 l1 = __floats2half2_rn((v.z - __low2float(h1)) * 2048.f,
                                       (v.w - __high2float(h1)) * 2048.f);
        *(__half2*)(sVh + j * 72 + d4) = h0; *(__half2*)(sVh + j * 72 + d4 + 2) = h1;
        *(__half2*)(sVl + j * 72 + d4) = l0; *(__half2*)(sVl + j * 72 + d4 + 2) = l1;
    }
    __syncthreads();

    // ---- score MMA: warp tile 16q x 96n, K=64 ----
    uint32_t uHq = smem_u32(sHq), uKC = smem_u32(sKC);
    {
        float sacc[6][2][4] = {};
#pragma unroll
        for (int ks = 0; ks < 4; ks++) {
            uint32_t a[4];
            {
                int r = wm * 16 + (lane & 15);
                int c = (lane >> 4) + ks * 2;
                ldsm4(a, uHq + r * 144 + c * 16);
            }
#pragma unroll
            for (int nf = 0; nf < 6; nf++) {
                uint32_t bb[4];
                int r = (lane & 15) + ks * 16;
                int c = wn * 12 + nf * 2 + (lane >> 4);
                ldsm4t(bb, uKC + r * 400 + c * 16);
                mma_f32(sacc[nf][0], a, bb[0], bb[1]);
                mma_f32(sacc[nf][1], a, bb[2], bb[3]);
            }
        }
        int row = wm * 16 + (lane >> 2);
#pragma unroll
        for (int nf = 0; nf < 6; nf++)
#pragma unroll
            for (int sub = 0; sub < 2; sub++) {
                int col = wn * 96 + nf * 16 + sub * 8 + (lane & 3) * 2;
                float* c4 = sacc[nf][sub];
                *(__half2*)(sS + row * 200 + col) = __floats2half2_rn(c4[0], c4[1]);
                *(__half2*)(sS + (row + 8) * 200 + col) = __floats2half2_rn(c4[2], c4[3]);
            }
    }
    __syncthreads();

    // ---- softmax (fp32 math on fp16 scores) ----
    {
        int w = tid >> 5;
#pragma unroll
        for (int r = 0; r < 8; r++) {
            int q = w * 8 + r;
            int c0 = lane, c1 = lane + 32;
            float s0 = (__half2float(sS[q * 200 + q + c0]) +
                        __half2float(sS[q * 200 + 128 + c0])) * 0.125f;
            float s1 = (__half2float(sS[q * 200 + q + c1]) +
                        __half2float(sS[q * 200 + 128 + c1])) * 0.125f;
            int jg0 = q0 + q + c0, jg1 = q0 + q + c1;
            if (jg0 < Cn - 1 && g_mask[b * (Cn - 1) + jg0]) s0 = -1e30f;
            if (jg1 < Cn - 1 && g_mask[b * (Cn - 1) + jg1]) s1 = -1e30f;
            float mx = fmaxf(s0, s1);
#pragma unroll
            for (int o = 16; o; o >>= 1) mx = fmaxf(mx, __shfl_xor_sync(0xffffffffu, mx, o));
            float e0 = __expf(s0 - mx), e1 = __expf(s1 - mx);
            float sum = e0 + e1;
#pragma unroll
            for (int o = 16; o; o >>= 1) sum += __shfl_xor_sync(0xffffffffu, sum, o);
            float inv = 1.f / sum;
            sW[q * 136 + q + c0] = __float2half_rn(e0 * inv);
            sW[q * 136 + q + c1] = __float2half_rn(e1 * inv);
        }
    }
    __syncthreads();

    // ---- out MMA: warp tile 16q x 32d, K=128 ----
    uint32_t uW = smem_u32(sW), uVh = smem_u32(sVh), uVl = smem_u32(sVl);
    {
        float ohi[4][4] = {};
        uint32_t olo[4][2] = {};
#pragma unroll
        for (int ks = 0; ks < 8; ks++) {
            uint32_t a[4];
            {
                int r = wm * 16 + (lane & 15);
                int c = (lane >> 4) + ks * 2;
                ldsm4(a, uW + r * 272 + c * 16);
            }
#pragma unroll
            for (int nf = 0; nf < 2; nf++) {
                uint32_t bh[4], bl[4];
                int r = (lane & 15) + ks * 16;
                int c = wn * 4 + nf * 2 + (lane >> 4);
                ldsm4t(bh, uVh + r * 144 + c * 16);
                ldsm4t(bl, uVl + r * 144 + c * 16);
                mma_f32(ohi[nf * 2], a, bh[0], bh[1]);
                mma_f32(ohi[nf * 2 + 1], a, bh[2], bh[3]);
                mma_f16(olo[nf * 2], a, bl[0], bl[1]);
                mma_f16(olo[nf * 2 + 1], a, bl[2], bl[3]);
            }
        }
        int row = wm * 16 + (lane >> 2);
#pragma unroll
        for (int n = 0; n < 4; n++) {
            int col = wn * 32 + n * 8 + (lane & 3) * 2;
            float2 l0 = __half22float2(*(__half2*)&olo[n][0]);
            float2 l1 = __half22float2(*(__half2*)&olo[n][1]);
            float o00 = ohi[n][0] + l0.x * INV_SCALE, o01 = ohi[n][1] + l0.y * INV_SCALE;
            float o10 = ohi[n][2] + l1.x * INV_SCALE, o11 = ohi[n][3] + l1.y * INV_SCALE;
#pragma unroll
            for (int rr = 0; rr < 2; rr++) {
                float ox = rr ? o10 : o00, oy = rr ? o11 : o01;
                int q = row + rr * 8;
                __half2 hh = __floats2half2_rn(ox, oy);
                __half2 ll = __floats2half2_rn((ox - __low2float(hh)) * 2048.f,
                                               (oy - __high2float(hh)) * 2048.f);
                __half* dst = g_atth + (size_t)(b * Qn + q0 + q) * KS + h * 64 + col;
                *(__half2*)(dst) = hh;
                *(__half2*)(dst + 512) = ll;
            }
        }
    }
}

}  // namespace

// ---------------------------------------------------------------------------
extern "C" void kernel_launch(void* const* d_in, const int* in_sizes, int n_in,
                              void* d_out, int out_size) {
    const float* x   = (const float*)d_in[0];
    const float* r   = (const float*)d_in[1];
    const float* Wkv = (const float*)d_in[2];
    const float* Wq  = (const float*)d_in[3];
    const float* bq  = (const float*)d_in[4];
    const float* Wr  = (const float*)d_in[5];
    const float* Wo  = (const float*)d_in[6];
    float* out = (float*)d_out;

    float *projp, *biasp;
    __half *xh, *atth, *Wh, *Woh;
    cudaGetSymbolAddress((void**)&projp, g_proj);
    cudaGetSymbolAddress((void**)&biasp, g_bias);
    cudaGetSymbolAddress((void**)&xh,    g_xh);
    cudaGetSymbolAddress((void**)&atth,  g_atth);
    cudaGetSymbolAddress((void**)&Wh,    g_Wh);
    cudaGetSymbolAddress((void**)&Woh,   g_Woh);

    cudaFuncSetAttribute(attn_kernel, cudaFuncAttributeMaxDynamicSharedMemorySize, ATT_SMEM);
    cudaFuncSetAttribute(hgemm_fused_kernel<true>,
                         cudaFuncAttributeMaxDynamicSharedMemorySize, HG_SMEM);
    cudaFuncSetAttribute(hgemm_fused_kernel<false>,
                         cudaFuncAttributeMaxDynamicSharedMemorySize, HG_SMEM);

    // 1-3: conversions + mask (proj GEMM is launch 4 for ncu)
    convX_kernel<<<(Bn * Tn * 128 + 255) / 256, 256>>>(x, xh, Bn * Tn);
    convW2_kernel<<<768, 256>>>(Wkv, Wq, bq);
    mask_kernel<<<dim3(Cn - 1, Bn), 128>>>(x);
    // 4: proj = x @ [Wkv|Wq] + [0|bq]    [4222 x 512 x 1536]
    hgemm_fused_kernel<true><<<dim3(24, 33), 256, HG_SMEM>>>(
        xh, Wh, biasp, projp, Bn * Tn, 1536);
    // 5-6: hr = r @ Wr
    hr_partial_kernel<<<dim3(4, 8), 256>>>(r, Wr);
    hr_reduce_kernel<<<128, 256>>>();
    // 7: tensor-core attention -> split-fp16 att
    attn_kernel<<<dim3(Qn / 64, Hn, Bn), 256, ATT_SMEM>>>();
    // 8-9: out = att @ Wo
    convWo_kernel<<<256, 256>>>(Wo);
    hgemm_fused_kernel<false><<<dim3(8, 32), 256, HG_SMEM>>>(
        atth, Woh, nullptr, out, Bn * Qn, 512);
}

// round 9
// speedup vs baseline: 2.7386x; 1.0960x over previous
#include <cuda_runtime.h>
#include <cuda_fp16.h>
#include <cstdint>

namespace {

constexpr int Bn = 2, Tn = 2111, Qn = 2048, Cn = 64, Hn = 8, DMn = 512;
constexpr int KS = 1024;   // stored A width: [hi(512) | lo*2048(512)]
constexpr float INV_SCALE = 1.0f / 2048.0f;

// Scratch (device globals)
__device__ __half g_projh[(size_t)Bn * Tn * 2048];  // [k.hi|v.hi|hq.hi|v.lo]
__device__ __half g_hrh[Cn * 512];
__device__ float g_bias[1536];
__device__ unsigned char g_mask[Bn * (Cn - 1)];
__device__ __half g_xh[(size_t)Bn * Tn * KS];
__device__ __half g_atth[(size_t)Bn * Qn * KS];
__device__ __half g_Wh[512 * 1536];                 // [Wkv | Wq] hi
__device__ __half g_Woh[512 * 512];                 // Wo hi

// ===========================================================================
// PTX helpers
// ===========================================================================
__device__ __forceinline__ uint32_t smem_u32(const void* p) {
    uint32_t a;
    asm("{ .reg .u64 t; cvta.to.shared.u64 t, %1; cvt.u32.u64 %0, t; }" : "=r"(a) : "l"(p));
    return a;
}
__device__ __forceinline__ void cpa16(uint32_t d, const void* s, int sz) {
    asm volatile("cp.async.cg.shared.global [%0], [%1], 16, %2;" :: "r"(d), "l"(s), "r"(sz));
}
__device__ __forceinline__ void cp_commit() { asm volatile("cp.async.commit_group;"); }
template <int N> __device__ __forceinline__ void cp_wait() {
    asm volatile("cp.async.wait_group %0;" :: "n"(N));
}
__device__ __forceinline__ void ldsm4(uint32_t* r, uint32_t a) {
    asm volatile("ldmatrix.sync.aligned.m8n8.x4.shared.b16 {%0,%1,%2,%3}, [%4];"
                 : "=r"(r[0]), "=r"(r[1]), "=r"(r[2]), "=r"(r[3]) : "r"(a));
}
__device__ __forceinline__ void ldsm4t(uint32_t* r, uint32_t a) {
    asm volatile("ldmatrix.sync.aligned.m8n8.x4.trans.shared.b16 {%0,%1,%2,%3}, [%4];"
                 : "=r"(r[0]), "=r"(r[1]), "=r"(r[2]), "=r"(r[3]) : "r"(a));
}
__device__ __forceinline__ void mma_f32(float* d, const uint32_t* a, uint32_t b0, uint32_t b1) {
    asm volatile(
        "mma.sync.aligned.m16n8k16.row.col.f32.f16.f16.f32 "
        "{%0,%1,%2,%3}, {%4,%5,%6,%7}, {%8,%9}, {%0,%1,%2,%3};"
        : "+f"(d[0]), "+f"(d[1]), "+f"(d[2]), "+f"(d[3])
        : "r"(a[0]), "r"(a[1]), "r"(a[2]), "r"(a[3]), "r"(b0), "r"(b1));
}
__device__ __forceinline__ void mma_f16(uint32_t* d, const uint32_t* a, uint32_t b0, uint32_t b1) {
    asm volatile(
        "mma.sync.aligned.m16n8k16.row.col.f16.f16.f16.f16 "
        "{%0,%1}, {%2,%3,%4,%5}, {%6,%7}, {%0,%1};"
        : "+r"(d[0]), "+r"(d[1])
        : "r"(a[0]), "r"(a[1]), "r"(a[2]), "r"(a[3]), "r"(b0), "r"(b1));
}

// ===========================================================================
// 2-term split HGEMM, 128x64 tile, 2 CTAs/SM:
//   C = Ahi@Bhi (fp32 acc) + (Alo' @ Bhi)/2048 (fp16 acc) [+bias]
// PROJ=true: write __half split layout into Ch [row][2048]
//            (hi at col; v-section cols [512,1024) also write lo at col+1024)
// PROJ=false: write fp32 into Cf [row][N]
// ===========================================================================
constexpr int OFF_AH = 0;
constexpr int OFF_AL = 8192;
constexpr int OFF_BH = 16384;
constexpr int STG = 20480;
constexpr int NSTAGE = 4;
constexpr int HG_SMEM = STG * NSTAGE;  // 80KB -> 2 CTAs/SM

template <bool PROJ, bool BIAS>
__global__ __launch_bounds__(256, 2) void hgemm_fused_kernel(
    const __half* __restrict__ A, const __half* __restrict__ Bw,
    const float* __restrict__ bias, float* __restrict__ Cf,
    __half* __restrict__ Ch, int M, int N)
{
    extern __shared__ char smm[];
    uint32_t sb = smem_u32(smm);
    int tid = threadIdx.x, lane = tid & 31, wid = tid >> 5;
    int wm = wid >> 1, wn = wid & 1;
    int row0 = blockIdx.y * 128, col0 = blockIdx.x * 64;

    int idA0 = tid, idA1 = tid + 256;
    int rA0 = idA0 >> 2, cA0 = idA0 & 3;
    int rA1 = idA1 >> 2, cA1 = idA1 & 3;
    int gm0 = row0 + rA0, gm1 = row0 + rA1;
    int av0 = (gm0 < M) ? 16 : 0, av1 = (gm1 < M) ? 16 : 0;
    size_t arow0 = (gm0 < M) ? (size_t)gm0 : 0;
    size_t arow1 = (gm1 < M) ? (size_t)gm1 : 0;
    const __half* asrc0 = A + arow0 * KS + cA0 * 8;
    const __half* asrc1 = A + arow1 * KS + cA1 * 8;
    uint32_t adst0 = rA0 * 64 + (((cA0 + (rA0 >> 1)) & 3) << 4);
    uint32_t adst1 = rA1 * 64 + (((cA1 + (rA1 >> 1)) & 3) << 4);

    int rB = tid >> 3, cB = tid & 7;
    const __half* bsrc = Bw + (size_t)rB * N + col0 + cB * 8;
    uint32_t bdst = rB * 128 + ((cB ^ (rB & 7)) << 4);

    auto load_stage = [&](int s, int kt) {
        int k0 = kt * 32;
        uint32_t base = sb + s * STG;
        cpa16(base + OFF_AH + adst0, asrc0 + k0, av0);
        cpa16(base + OFF_AH + adst1, asrc1 + k0, av1);
        cpa16(base + OFF_AL + adst0, asrc0 + 512 + k0, av0);
        cpa16(base + OFF_AL + adst1, asrc1 + 512 + k0, av1);
        cpa16(base + OFF_BH + bdst, bsrc + (size_t)k0 * N, 16);
        cp_commit();
    };

    constexpr int KT = 512 / 32;   // 16
    load_stage(0, 0);
    load_stage(1, 1);
    load_stage(2, 2);

    float accf[2][4][4] = {};
    uint32_t acch[2][4][2] = {};

    int la_r0 = wm * 32 + (lane & 15);
    int la_c0 = (lane >> 4);
    int lb_r0 = (lane & 15);
    int lb_c0 = wn * 4 + (lane >> 4);

    for (int kt = 0; kt < KT; kt++) {
        cp_wait<2>();
        __syncthreads();
        int s = kt & (NSTAGE - 1);
        uint32_t base = sb + s * STG;
#pragma unroll
        for (int kk = 0; kk < 2; kk++) {
            uint32_t ah[2][4], al[2][4];
#pragma unroll
            for (int mf = 0; mf < 2; mf++) {
                int r = la_r0 + mf * 16;
                int c = la_c0 + kk * 2;
                uint32_t off = r * 64 + (((c + (r >> 1)) & 3) << 4);
                ldsm4(ah[mf], base + OFF_AH + off);
                ldsm4(al[mf], base + OFF_AL + off);
            }
            uint32_t bh[2][4];
#pragma unroll
            for (int nf = 0; nf < 2; nf++) {
                int r = lb_r0 + kk * 16;
                int c = lb_c0 + nf * 2;
                uint32_t off = r * 128 + ((c ^ (r & 7)) << 4);
                ldsm4t(bh[nf], base + OFF_BH + off);
            }
#pragma unroll
            for (int mf = 0; mf < 2; mf++)
#pragma unroll
                for (int n = 0; n < 4; n++) {
                    int bi = n >> 1, br = (n & 1) * 2;
                    mma_f32(accf[mf][n], ah[mf], bh[bi][br], bh[bi][br + 1]);
                    mma_f16(acch[mf][n], al[mf], bh[bi][br], bh[bi][br + 1]);
                }
        }
        if (kt + 3 < KT) load_stage((kt + 3) & (NSTAGE - 1), kt + 3);
        else cp_commit();
    }

    // ---- epilogue ----
    bool vsec = PROJ && (col0 >= 512 && col0 < 1024);
#pragma unroll
    for (int mf = 0; mf < 2; mf++) {
        int rb = row0 + wm * 32 + mf * 16 + (lane >> 2);
#pragma unroll
        for (int n = 0; n < 4; n++) {
            int cb = col0 + wn * 32 + n * 8 + (lane & 3) * 2;
            float* a4 = accf[mf][n];
            float2 lo2 = __half22float2(*(__half2*)&acch[mf][n][0]);
            float2 hi2 = __half22float2(*(__half2*)&acch[mf][n][1]);
            float bx = 0.f, by = 0.f;
            if (BIAS) { bx = bias[cb]; by = bias[cb + 1]; }
            float v00 = a4[0] + lo2.x * INV_SCALE + bx, v01 = a4[1] + lo2.y * INV_SCALE + by;
            float v10 = a4[2] + hi2.x * INV_SCALE + bx, v11 = a4[3] + hi2.y * INV_SCALE + by;
            if (PROJ) {
                if (rb < M) {
                    __half2 hh = __floats2half2_rn(v00, v01);
                    *(__half2*)(Ch + (size_t)rb * 2048 + cb) = hh;
                    if (vsec)
                        *(__half2*)(Ch + (size_t)rb * 2048 + cb + 1024) =
                            __floats2half2_rn((v00 - __low2float(hh)) * 2048.f,
                                              (v01 - __high2float(hh)) * 2048.f);
                }
                if (rb + 8 < M) {
                    __half2 hh = __floats2half2_rn(v10, v11);
                    *(__half2*)(Ch + (size_t)(rb + 8) * 2048 + cb) = hh;
                    if (vsec)
                        *(__half2*)(Ch + (size_t)(rb + 8) * 2048 + cb + 1024) =
                            __floats2half2_rn((v10 - __low2float(hh)) * 2048.f,
                                              (v11 - __high2float(hh)) * 2048.f);
                }
            } else {
                if (rb < M)
                    *(float2*)(Cf + (size_t)rb * N + cb) = make_float2(v00, v01);
                if (rb + 8 < M)
                    *(float2*)(Cf + (size_t)(rb + 8) * N + cb) = make_float2(v10, v11);
            }
        }
    }
}

// ===========================================================================
// prep kernel: convX + convW2 + convWo + mask + hr in one launch.
// Block ranges: [0,2111) convX, [2111,2879) convW2, [2879,3135) convWo,
//               [3135,3261) mask, [3261,3269) hr.
// ===========================================================================
constexpr int PREP_BLOCKS = 3269;

__global__ __launch_bounds__(256) void prep_kernel(
    const float* __restrict__ x, const float* __restrict__ r,
    const float* __restrict__ Wkv, const float* __restrict__ Wq,
    const float* __restrict__ bq, const float* __restrict__ Wr,
    const float* __restrict__ Wo)
{
    int bid = blockIdx.x, tid = threadIdx.x;
    if (bid < 2111) {
        // convX: x -> g_xh [hi | lo*2048]
        int idx = bid * 256 + tid;
        int m = idx >> 7, k4 = (idx & 127) << 2;
        float4 v = *(const float4*)(x + (size_t)m * 512 + k4);
        __half2 h0 = __floats2half2_rn(v.x, v.y);
        __half2 h1 = __floats2half2_rn(v.z, v.w);
        __half2 l0 = __floats2half2_rn((v.x - __low2float(h0)) * 2048.f,
                                       (v.y - __high2float(h0)) * 2048.f);
        __half2 l1 = __floats2half2_rn((v.z - __low2float(h1)) * 2048.f,
                                       (v.w - __high2float(h1)) * 2048.f);
        __half* rb = g_xh + (size_t)m * KS;
        *(__half2*)(rb + k4) = h0;        *(__half2*)(rb + k4 + 2) = h1;
        *(__half2*)(rb + 512 + k4) = l0;  *(__half2*)(rb + 512 + k4 + 2) = l1;
    } else if (bid < 2879) {
        // convW2: [Wkv|Wq] -> g_Wh hi; bias [0(1024)|bq(512)]
        int idx = (bid - 2111) * 256 + tid;
        if (idx < 384) {
            float4 v = make_float4(0.f, 0.f, 0.f, 0.f);
            int n4 = idx * 4;
            if (n4 >= 1024) v = *(const float4*)(bq + n4 - 1024);
            *(float4*)(g_bias + n4) = v;
        }
        int k = idx / 384, n4 = (idx - k * 384) * 4;
        float4 v = (n4 < 1024) ? *(const float4*)(Wkv + (size_t)k * 1024 + n4)
                               : *(const float4*)(Wq + (size_t)k * 512 + n4 - 1024);
        __half* d0 = g_Wh + (size_t)k * 1536 + n4;
        *(__half2*)(d0) = __floats2half2_rn(v.x, v.y);
        *(__half2*)(d0 + 2) = __floats2half2_rn(v.z, v.w);
    } else if (bid < 3135) {
        // convWo
        int idx = (bid - 2879) * 256 + tid;
        int k = idx >> 7, n4 = (idx & 127) << 2;
        float4 v = *(const float4*)(Wo + (size_t)k * 512 + n4);
        __half* d0 = g_Woh + (size_t)k * 512 + n4;
        *(__half2*)(d0) = __floats2half2_rn(v.x, v.y);
        *(__half2*)(d0 + 2) = __floats2half2_rn(v.z, v.w);
    } else if (bid < 3261) {
        // mask: one block per (t, b)
        int mb = bid - 3135;
        int t = mb % (Cn - 1), b = mb / (Cn - 1);
        const float* row = x + ((size_t)b * Tn + t) * DMn;
        int zero = 1;
        for (int i = tid; i < DMn; i += 256)
            if (row[i] != 0.f) zero = 0;
        int all = __syncthreads_and(zero);
        if (tid == 0) g_mask[b * (Cn - 1) + t] = (unsigned char)(all != 0);
    } else {
        // hr: block cb computes hr[:, cb*64 : cb*64+64] = r @ Wr slice (fp32 -> fp16)
        __shared__ float sa[64][33];
        __shared__ float sw[32][64];
        int cb = bid - 3261;
        int row = tid & 63, cg = tid >> 6;
        float acc[16] = {};
        for (int k0 = 0; k0 < 512; k0 += 32) {
            for (int i = tid; i < 2048; i += 256) {
                int rr = i >> 5, kk = i & 31;
                sa[rr][kk] = r[rr * 512 + k0 + kk];
            }
            for (int i = tid; i < 2048; i += 256) {
                int kk = i >> 6, cc = i & 63;
                sw[kk][cc] = Wr[(size_t)(k0 + kk) * 512 + cb * 64 + cc];
            }
            __syncthreads();
#pragma unroll 8
            for (int kk = 0; kk < 32; kk++) {
                float a = sa[row][kk];
#pragma unroll
                for (int c = 0; c < 16; c++)
                    acc[c] = fmaf(a, sw[kk][cg * 16 + c], acc[c]);
            }
            __syncthreads();
        }
        __half* dst = g_hrh + row * 512 + cb * 64 + cg * 16;
#pragma unroll
        for (int c = 0; c < 16; c += 2)
            *(__half2*)(dst + c) = __floats2half2_rn(acc[c], acc[c + 1]);
    }
}

// ---------------------------------------------------------------------------
// Tensor-core attention, 3 CTAs/SM via phase overlay.
// smem (halves): sVh[128][72] | sVl[128][72] | DYN(17408):
//   phase1: sHq[64][72] + sKC[64][200]
//   phase2: sS[64][130] (band-compact scores) + sW[64][136]
// ---------------------------------------------------------------------------
constexpr int AS_VH = 0;
constexpr int AS_VL = 9216;
constexpr int AS_DYN = 18432;
constexpr int AS_TOTAL = AS_DYN + 17408;          // 35840 halves
constexpr int ATT_SMEM = AS_TOTAL * 2;            // 71680 B

__global__ __launch_bounds__(256, 3) void attn_kernel() {
    extern __shared__ __align__(16) __half sm[];
    __half* sVh = sm + AS_VH;
    __half* sVl = sm + AS_VL;
    __half* sHq = sm + AS_DYN;
    __half* sKC = sm + AS_DYN + 4608;
    __half* sS  = sm + AS_DYN;            // overlays sHq/sKC after score MMA
    __half* sW  = sm + AS_DYN + 8320;

    int q0 = blockIdx.x * 64;
    int h = blockIdx.y, b = blockIdx.z;
    int tid = threadIdx.x, lane = tid & 31, wid = tid >> 5;
    int wm = wid >> 1, wn = wid & 1;

    const __half* pb = g_projh + (size_t)(b * Tn + q0) * 2048;

    // ---- staging (all fp16 loads) ----
    for (int li = tid; li < 1024; li += 256) {
        int q = li >> 4, d4 = (li & 15) << 2;
        *(uint2*)(sHq + q * 72 + d4) =
            *(const uint2*)(pb + (size_t)(63 + q) * 2048 + 1024 + h * 64 + d4);
    }
    for (int li = tid; li < 2048; li += 256) {
        int j = li >> 4, d4 = (li & 15) << 2;
        __half hv[4];
        if (j < 127) *(uint2*)hv = *(const uint2*)(pb + (size_t)j * 2048 + h * 64 + d4);
        else { hv[0] = hv[1] = hv[2] = hv[3] = __half(0.f); }
        sKC[(d4 + 0) * 200 + j] = hv[0];
        sKC[(d4 + 1) * 200 + j] = hv[1];
        sKC[(d4 + 2) * 200 + j] = hv[2];
        sKC[(d4 + 3) * 200 + j] = hv[3];
    }
    for (int li = tid; li < 1024; li += 256) {
        int c = li >> 4, d4 = (li & 15) << 2;
        __half hv[4];
        *(uint2*)hv = *(const uint2*)(g_hrh + c * 512 + h * 64 + d4);
        sKC[(d4 + 0) * 200 + 128 + c] = hv[0];
        sKC[(d4 + 1) * 200 + 128 + c] = hv[1];
        sKC[(d4 + 2) * 200 + 128 + c] = hv[2];
        sKC[(d4 + 3) * 200 + 128 + c] = hv[3];
    }
    for (int li = tid; li < 2048; li += 256) {
        int j = li >> 4, d4 = (li & 15) << 2;
        uint2 hv = make_uint2(0, 0), lv = make_uint2(0, 0);
        if (j < 127) {
            hv = *(const uint2*)(pb + (size_t)j * 2048 + 512 + h * 64 + d4);
            lv = *(const uint2*)(pb + (size_t)j * 2048 + 1536 + h * 64 + d4);
        }
        *(uint2*)(sVh + j * 72 + d4) = hv;
        *(uint2*)(sVl + j * 72 + d4) = lv;
    }
    __syncthreads();

    // ---- score MMA: warp tile 16q x 96n, K=64 (regs persist across overlay) ----
    uint32_t uHq = smem_u32(sHq), uKC = smem_u32(sKC);
    float sacc[6][2][4] = {};
#pragma unroll
    for (int ks = 0; ks < 4; ks++) {
        uint32_t a[4];
        {
            int r = wm * 16 + (lane & 15);
            int c = (lane >> 4) + ks * 2;
            ldsm4(a, uHq + r * 144 + c * 16);
        }
#pragma unroll
        for (int nf = 0; nf < 6; nf++) {
            uint32_t bb[4];
            int r = (lane & 15) + ks * 16;
            int c = wn * 12 + nf * 2 + (lane >> 4);
            ldsm4t(bb, uKC + r * 400 + c * 16);
            mma_f32(sacc[nf][0], a, bb[0], bb[1]);
            mma_f32(sacc[nf][1], a, bb[2], bb[3]);
        }
    }
    __syncthreads();   // all reads of sHq/sKC done -> overlay region writable

    // ---- zero sW + scatter band-compacted scores into sS ----
    for (int i = tid; i < 64 * 136 / 2; i += 256) ((uint32_t*)sW)[i] = 0;
    {
        int row = wm * 16 + (lane >> 2);
        auto put = [&](int rr, int cc, float v) {
            int rel = cc - rr;
            if (rel >= 0 && rel < 64) sS[rr * 130 + rel] = __float2half_rn(v);
            else if (cc >= 128) sS[rr * 130 + 64 + (cc - 128)] = __float2half_rn(v);
        };
#pragma unroll
        for (int nf = 0; nf < 6; nf++)
#pragma unroll
            for (int sub = 0; sub < 2; sub++) {
                int col = wn * 96 + nf * 16 + sub * 8 + (lane & 3) * 2;
                float* c4 = sacc[nf][sub];
                put(row, col, c4[0]);     put(row, col + 1, c4[1]);
                put(row + 8, col, c4[2]); put(row + 8, col + 1, c4[3]);
            }
    }
    __syncthreads();

    // ---- softmax ----
    {
        int w = tid >> 5;
#pragma unroll
        for (int rr = 0; rr < 8; rr++) {
            int q = w * 8 + rr;
            int c0 = lane, c1 = lane + 32;
            float s0 = (__half2float(sS[q * 130 + c0]) +
                        __half2float(sS[q * 130 + 64 + c0])) * 0.125f;
            float s1 = (__half2float(sS[q * 130 + c1]) +
                        __half2float(sS[q * 130 + 64 + c1])) * 0.125f;
            int jg0 = q0 + q + c0, jg1 = q0 + q + c1;
            if (jg0 < Cn - 1 && g_mask[b * (Cn - 1) + jg0]) s0 = -1e30f;
            if (jg1 < Cn - 1 && g_mask[b * (Cn - 1) + jg1]) s1 = -1e30f;
            float mx = fmaxf(s0, s1);
#pragma unroll
            for (int o = 16; o; o >>= 1) mx = fmaxf(mx, __shfl_xor_sync(0xffffffffu, mx, o));
            float e0 = __expf(s0 - mx), e1 = __expf(s1 - mx);
            float sum = e0 + e1;
#pragma unroll
            for (int o = 16; o; o >>= 1) sum += __shfl_xor_sync(0xffffffffu, sum, o);
            float inv = 1.f / sum;
            sW[q * 136 + q + c0] = __float2half_rn(e0 * inv);
            sW[q * 136 + q + c1] = __float2half_rn(e1 * inv);
        }
    }
    __syncthreads();

    // ---- out MMA: warp tile 16q x 32d, K=128 ----
    uint32_t uW = smem_u32(sW), uVh = smem_u32(sVh), uVl = smem_u32(sVl);
    {
        float ohi[4][4] = {};
        uint32_t olo[4][2] = {};
#pragma unroll
        for (int ks = 0; ks < 8; ks++) {
            uint32_t a[4];
            {
                int r = wm * 16 + (lane & 15);
                int c = (lane >> 4) + ks * 2;
                ldsm4(a, uW + r * 272 + c * 16);
            }
#pragma unroll
            for (int nf = 0; nf < 2; nf++) {
                uint32_t bh[4], bl[4];
                int r = (lane & 15) + ks * 16;
                int c = wn * 4 + nf * 2 + (lane >> 4);
                ldsm4t(bh, uVh + r * 144 + c * 16);
                ldsm4t(bl, uVl + r * 144 + c * 16);
                mma_f32(ohi[nf * 2], a, bh[0], bh[1]);
                mma_f32(ohi[nf * 2 + 1], a, bh[2], bh[3]);
                mma_f16(olo[nf * 2], a, bl[0], bl[1]);
                mma_f16(olo[nf * 2 + 1], a, bl[2], bl[3]);
            }
        }
        int row = wm * 16 + (lane >> 2);
#pragma unroll
        for (int n = 0; n < 4; n++) {
            int col = wn * 32 + n * 8 + (lane & 3) * 2;
            float2 l0 = __half22float2(*(__half2*)&olo[n][0]);
            float2 l1 = __half22float2(*(__half2*)&olo[n][1]);
            float o00 = ohi[n][0] + l0.x * INV_SCALE, o01 = ohi[n][1] + l0.y * INV_SCALE;
            float o10 = ohi[n][2] + l1.x * INV_SCALE, o11 = ohi[n][3] + l1.y * INV_SCALE;
#pragma unroll
            for (int rr = 0; rr < 2; rr++) {
                float ox = rr ? o10 : o00, oy = rr ? o11 : o01;
                int q = row + rr * 8;
                __half2 hh = __floats2half2_rn(ox, oy);
                __half2 ll = __floats2half2_rn((ox - __low2float(hh)) * 2048.f,
                                               (oy - __high2float(hh)) * 2048.f);
                __half* dst = g_atth + (size_t)(b * Qn + q0 + q) * KS + h * 64 + col;
                *(__half2*)(dst) = hh;
                *(__half2*)(dst + 512) = ll;
            }
        }
    }
}

}  // namespace

// ---------------------------------------------------------------------------
extern "C" void kernel_launch(void* const* d_in, const int* in_sizes, int n_in,
                              void* d_out, int out_size) {
    const float* x   = (const float*)d_in[0];
    const float* r   = (const float*)d_in[1];
    const float* Wkv = (const float*)d_in[2];
    const float* Wq  = (const float*)d_in[3];
    const float* bq  = (const float*)d_in[4];
    const float* Wr  = (const float*)d_in[5];
    const float* Wo  = (const float*)d_in[6];
    float* out = (float*)d_out;

    float* biasp;
    __half *xh, *atth, *Wh, *Woh, *projh;
    cudaGetSymbolAddress((void**)&biasp, g_bias);
    cudaGetSymbolAddress((void**)&xh,    g_xh);
    cudaGetSymbolAddress((void**)&atth,  g_atth);
    cudaGetSymbolAddress((void**)&Wh,    g_Wh);
    cudaGetSymbolAddress((void**)&Woh,   g_Woh);
    cudaGetSymbolAddress((void**)&projh, g_projh);

    cudaFuncSetAttribute(attn_kernel, cudaFuncAttributeMaxDynamicSharedMemorySize, ATT_SMEM);
    cudaFuncSetAttribute(hgemm_fused_kernel<true, true>,
                         cudaFuncAttributeMaxDynamicSharedMemorySize, HG_SMEM);
    cudaFuncSetAttribute(hgemm_fused_kernel<false, false>,
                         cudaFuncAttributeMaxDynamicSharedMemorySize, HG_SMEM);

    // 1: prep (convX + convW2 + convWo + mask + hr)
    prep_kernel<<<PREP_BLOCKS, 256>>>(x, r, Wkv, Wq, bq, Wr, Wo);
    // 2: proj = x @ [Wkv|Wq] + [0|bq] -> fp16 split layout [4222 x 512 x 1536]
    hgemm_fused_kernel<true, true><<<dim3(24, 33), 256, HG_SMEM>>>(
        xh, Wh, biasp, nullptr, projh, Bn * Tn, 1536);
    // 3: tensor-core attention -> split-fp16 att
    attn_kernel<<<dim3(Qn / 64, Hn, Bn), 256, ATT_SMEM>>>();
    // 4: out = att @ Wo  (fp32 output)
    hgemm_fused_kernel<false, false><<<dim3(8, 32), 256, HG_SMEM>>>(
        atth, Woh, nullptr, out, nullptr, Bn * Qn, 512);
}

// round 10
// speedup vs baseline: 2.8159x; 1.0282x over previous
#include <cuda_runtime.h>
#include <cuda_fp16.h>
#include <cstdint>

namespace {

constexpr int Bn = 2, Tn = 2111, Qn = 2048, Cn = 64, Hn = 8, DMn = 512;
constexpr int KS = 1024;   // stored A width: [hi(512) | lo*2048(512)]
constexpr float INV_SCALE = 1.0f / 2048.0f;

// Scratch (device globals)
__device__ __half g_projh[(size_t)Bn * Tn * 2048];  // [k.hi|v.hi|hq.hi|v.lo]
__device__ __half g_hrh[Cn * 512];
__device__ float g_bias[1536];
__device__ unsigned char g_mask[Bn * (Cn - 1)];
__device__ __half g_xh[(size_t)Bn * Tn * KS];
__device__ __half g_atth[(size_t)Bn * Qn * KS];
__device__ __half g_Wh[512 * 1536];                 // [Wkv | Wq] hi
__device__ __half g_Woh[512 * 512];                 // Wo hi

// ===========================================================================
// PTX helpers
// ===========================================================================
__device__ __forceinline__ uint32_t smem_u32(const void* p) {
    uint32_t a;
    asm("{ .reg .u64 t; cvta.to.shared.u64 t, %1; cvt.u32.u64 %0, t; }" : "=r"(a) : "l"(p));
    return a;
}
__device__ __forceinline__ void cpa16(uint32_t d, const void* s, int sz) {
    asm volatile("cp.async.cg.shared.global [%0], [%1], 16, %2;" :: "r"(d), "l"(s), "r"(sz));
}
__device__ __forceinline__ void cp_commit() { asm volatile("cp.async.commit_group;"); }
template <int N> __device__ __forceinline__ void cp_wait() {
    asm volatile("cp.async.wait_group %0;" :: "n"(N));
}
__device__ __forceinline__ void ldsm4(uint32_t* r, uint32_t a) {
    asm volatile("ldmatrix.sync.aligned.m8n8.x4.shared.b16 {%0,%1,%2,%3}, [%4];"
                 : "=r"(r[0]), "=r"(r[1]), "=r"(r[2]), "=r"(r[3]) : "r"(a));
}
__device__ __forceinline__ void ldsm4t(uint32_t* r, uint32_t a) {
    asm volatile("ldmatrix.sync.aligned.m8n8.x4.trans.shared.b16 {%0,%1,%2,%3}, [%4];"
                 : "=r"(r[0]), "=r"(r[1]), "=r"(r[2]), "=r"(r[3]) : "r"(a));
}
__device__ __forceinline__ void mma_f32(float* d, const uint32_t* a, uint32_t b0, uint32_t b1) {
    asm volatile(
        "mma.sync.aligned.m16n8k16.row.col.f32.f16.f16.f32 "
        "{%0,%1,%2,%3}, {%4,%5,%6,%7}, {%8,%9}, {%0,%1,%2,%3};"
        : "+f"(d[0]), "+f"(d[1]), "+f"(d[2]), "+f"(d[3])
        : "r"(a[0]), "r"(a[1]), "r"(a[2]), "r"(a[3]), "r"(b0), "r"(b1));
}
__device__ __forceinline__ void mma_f16(uint32_t* d, const uint32_t* a, uint32_t b0, uint32_t b1) {
    asm volatile(
        "mma.sync.aligned.m16n8k16.row.col.f16.f16.f16.f16 "
        "{%0,%1}, {%2,%3,%4,%5}, {%6,%7}, {%0,%1};"
        : "+r"(d[0]), "+r"(d[1])
        : "r"(a[0]), "r"(a[1]), "r"(a[2]), "r"(a[3]), "r"(b0), "r"(b1));
}

// ===========================================================================
// 2-term split HGEMM, 128x64 tile, 2 CTAs/SM:
//   C = Ahi@Bhi (fp32 acc) [+ (Alo' @ Bhi)/2048 (fp16 acc) when needed] [+bias]
// PROJ=true: fp16 split output; lo-stream ONLY for v-section cols [512,1024)
//            (k/hq sections are consumed as fp16 -> lo refinement wasted).
// PROJ=false (Wo): fp32 output, lo-stream always on.
// ===========================================================================
constexpr int OFF_AH = 0;
constexpr int OFF_AL = 8192;
constexpr int OFF_BH = 16384;
constexpr int STG = 20480;
constexpr int NSTAGE = 4;
constexpr int HG_SMEM = STG * NSTAGE;  // 80KB -> 2 CTAs/SM

template <bool PROJ, bool BIAS>
__global__ __launch_bounds__(256, 2) void hgemm_fused_kernel(
    const __half* __restrict__ A, const __half* __restrict__ Bw,
    const float* __restrict__ bias, float* __restrict__ Cf,
    __half* __restrict__ Ch, int M, int N)
{
    extern __shared__ char smm[];
    uint32_t sb = smem_u32(smm);
    int tid = threadIdx.x, lane = tid & 31, wid = tid >> 5;
    int wm = wid >> 1, wn = wid & 1;
    int row0 = blockIdx.y * 128, col0 = blockIdx.x * 64;

    const bool need_lo = PROJ ? (col0 >= 512 && col0 < 1024) : true;

    int idA0 = tid, idA1 = tid + 256;
    int rA0 = idA0 >> 2, cA0 = idA0 & 3;
    int rA1 = idA1 >> 2, cA1 = idA1 & 3;
    int gm0 = row0 + rA0, gm1 = row0 + rA1;
    int av0 = (gm0 < M) ? 16 : 0, av1 = (gm1 < M) ? 16 : 0;
    size_t arow0 = (gm0 < M) ? (size_t)gm0 : 0;
    size_t arow1 = (gm1 < M) ? (size_t)gm1 : 0;
    const __half* asrc0 = A + arow0 * KS + cA0 * 8;
    const __half* asrc1 = A + arow1 * KS + cA1 * 8;
    uint32_t adst0 = rA0 * 64 + (((cA0 + (rA0 >> 1)) & 3) << 4);
    uint32_t adst1 = rA1 * 64 + (((cA1 + (rA1 >> 1)) & 3) << 4);

    int rB = tid >> 3, cB = tid & 7;
    const __half* bsrc = Bw + (size_t)rB * N + col0 + cB * 8;
    uint32_t bdst = rB * 128 + ((cB ^ (rB & 7)) << 4);

    auto load_stage = [&](int s, int kt) {
        int k0 = kt * 32;
        uint32_t base = sb + s * STG;
        cpa16(base + OFF_AH + adst0, asrc0 + k0, av0);
        cpa16(base + OFF_AH + adst1, asrc1 + k0, av1);
        if (need_lo) {
            cpa16(base + OFF_AL + adst0, asrc0 + 512 + k0, av0);
            cpa16(base + OFF_AL + adst1, asrc1 + 512 + k0, av1);
        }
        cpa16(base + OFF_BH + bdst, bsrc + (size_t)k0 * N, 16);
        cp_commit();
    };

    constexpr int KT = 512 / 32;   // 16
    load_stage(0, 0);
    load_stage(1, 1);
    load_stage(2, 2);

    float accf[2][4][4] = {};
    uint32_t acch[2][4][2] = {};

    int la_r0 = wm * 32 + (lane & 15);
    int la_c0 = (lane >> 4);
    int lb_r0 = (lane & 15);
    int lb_c0 = wn * 4 + (lane >> 4);

    for (int kt = 0; kt < KT; kt++) {
        cp_wait<2>();
        __syncthreads();
        int s = kt & (NSTAGE - 1);
        uint32_t base = sb + s * STG;
#pragma unroll
        for (int kk = 0; kk < 2; kk++) {
            uint32_t ah[2][4], al[2][4];
#pragma unroll
            for (int mf = 0; mf < 2; mf++) {
                int r = la_r0 + mf * 16;
                int c = la_c0 + kk * 2;
                uint32_t off = r * 64 + (((c + (r >> 1)) & 3) << 4);
                ldsm4(ah[mf], base + OFF_AH + off);
                if (need_lo) ldsm4(al[mf], base + OFF_AL + off);
            }
            uint32_t bh[2][4];
#pragma unroll
            for (int nf = 0; nf < 2; nf++) {
                int r = lb_r0 + kk * 16;
                int c = lb_c0 + nf * 2;
                uint32_t off = r * 128 + ((c ^ (r & 7)) << 4);
                ldsm4t(bh[nf], base + OFF_BH + off);
            }
#pragma unroll
            for (int mf = 0; mf < 2; mf++)
#pragma unroll
                for (int n = 0; n < 4; n++) {
                    int bi = n >> 1, br = (n & 1) * 2;
                    mma_f32(accf[mf][n], ah[mf], bh[bi][br], bh[bi][br + 1]);
                    if (need_lo)
                        mma_f16(acch[mf][n], al[mf], bh[bi][br], bh[bi][br + 1]);
                }
        }
        if (kt + 3 < KT) load_stage((kt + 3) & (NSTAGE - 1), kt + 3);
        else cp_commit();
    }

    // ---- epilogue ----
    bool vsec = PROJ && (col0 >= 512 && col0 < 1024);
#pragma unroll
    for (int mf = 0; mf < 2; mf++) {
        int rb = row0 + wm * 32 + mf * 16 + (lane >> 2);
#pragma unroll
        for (int n = 0; n < 4; n++) {
            int cb = col0 + wn * 32 + n * 8 + (lane & 3) * 2;
            float* a4 = accf[mf][n];
            float2 lo2 = __half22float2(*(__half2*)&acch[mf][n][0]);
            float2 hi2 = __half22float2(*(__half2*)&acch[mf][n][1]);
            float bx = 0.f, by = 0.f;
            if (BIAS) { bx = bias[cb]; by = bias[cb + 1]; }
            float v00 = a4[0] + lo2.x * INV_SCALE + bx, v01 = a4[1] + lo2.y * INV_SCALE + by;
            float v10 = a4[2] + hi2.x * INV_SCALE + bx, v11 = a4[3] + hi2.y * INV_SCALE + by;
            if (PROJ) {
                if (rb < M) {
                    __half2 hh = __floats2half2_rn(v00, v01);
                    *(__half2*)(Ch + (size_t)rb * 2048 + cb) = hh;
                    if (vsec)
                        *(__half2*)(Ch + (size_t)rb * 2048 + cb + 1024) =
                            __floats2half2_rn((v00 - __low2float(hh)) * 2048.f,
                                              (v01 - __high2float(hh)) * 2048.f);
                }
                if (rb + 8 < M) {
                    __half2 hh = __floats2half2_rn(v10, v11);
                    *(__half2*)(Ch + (size_t)(rb + 8) * 2048 + cb) = hh;
                    if (vsec)
                        *(__half2*)(Ch + (size_t)(rb + 8) * 2048 + cb + 1024) =
                            __floats2half2_rn((v10 - __low2float(hh)) * 2048.f,
                                              (v11 - __high2float(hh)) * 2048.f);
                }
            } else {
                if (rb < M)
                    *(float2*)(Cf + (size_t)rb * N + cb) = make_float2(v00, v01);
                if (rb + 8 < M)
                    *(float2*)(Cf + (size_t)(rb + 8) * N + cb) = make_float2(v10, v11);
            }
        }
    }
}

// ===========================================================================
// prep kernel: convX + convW2 + convWo + mask + hr in one launch.
// ===========================================================================
constexpr int PREP_BLOCKS = 3269;

__global__ __launch_bounds__(256) void prep_kernel(
    const float* __restrict__ x, const float* __restrict__ r,
    const float* __restrict__ Wkv, const float* __restrict__ Wq,
    const float* __restrict__ bq, const float* __restrict__ Wr,
    const float* __restrict__ Wo)
{
    int bid = blockIdx.x, tid = threadIdx.x;
    if (bid < 2111) {
        int idx = bid * 256 + tid;
        int m = idx >> 7, k4 = (idx & 127) << 2;
        float4 v = *(const float4*)(x + (size_t)m * 512 + k4);
        __half2 h0 = __floats2half2_rn(v.x, v.y);
        __half2 h1 = __floats2half2_rn(v.z, v.w);
        __half2 l0 = __floats2half2_rn((v.x - __low2float(h0)) * 2048.f,
                                       (v.y - __high2float(h0)) * 2048.f);
        __half2 l1 = __floats2half2_rn((v.z - __low2float(h1)) * 2048.f,
                                       (v.w - __high2float(h1)) * 2048.f);
        __half* rb = g_xh + (size_t)m * KS;
        *(__half2*)(rb + k4) = h0;        *(__half2*)(rb + k4 + 2) = h1;
        *(__half2*)(rb + 512 + k4) = l0;  *(__half2*)(rb + 512 + k4 + 2) = l1;
    } else if (bid < 2879) {
        int idx = (bid - 2111) * 256 + tid;
        if (idx < 384) {
            float4 v = make_float4(0.f, 0.f, 0.f, 0.f);
            int n4 = idx * 4;
            if (n4 >= 1024) v = *(const float4*)(bq + n4 - 1024);
            *(float4*)(g_bias + n4) = v;
        }
        int k = idx / 384, n4 = (idx - k * 384) * 4;
        float4 v = (n4 < 1024) ? *(const float4*)(Wkv + (size_t)k * 1024 + n4)
                               : *(const float4*)(Wq + (size_t)k * 512 + n4 - 1024);
        __half* d0 = g_Wh + (size_t)k * 1536 + n4;
        *(__half2*)(d0) = __floats2half2_rn(v.x, v.y);
        *(__half2*)(d0 + 2) = __floats2half2_rn(v.z, v.w);
    } else if (bid < 3135) {
        int idx = (bid - 2879) * 256 + tid;
        int k = idx >> 7, n4 = (idx & 127) << 2;
        float4 v = *(const float4*)(Wo + (size_t)k * 512 + n4);
        __half* d0 = g_Woh + (size_t)k * 512 + n4;
        *(__half2*)(d0) = __floats2half2_rn(v.x, v.y);
        *(__half2*)(d0 + 2) = __floats2half2_rn(v.z, v.w);
    } else if (bid < 3261) {
        int mb = bid - 3135;
        int t = mb % (Cn - 1), b = mb / (Cn - 1);
        const float* row = x + ((size_t)b * Tn + t) * DMn;
        int zero = 1;
        for (int i = tid; i < DMn; i += 256)
            if (row[i] != 0.f) zero = 0;
        int all = __syncthreads_and(zero);
        if (tid == 0) g_mask[b * (Cn - 1) + t] = (unsigned char)(all != 0);
    } else {
        __shared__ float sa[64][33];
        __shared__ float sw[32][64];
        int cb = bid - 3261;
        int row = tid & 63, cg = tid >> 6;
        float acc[16] = {};
        for (int k0 = 0; k0 < 512; k0 += 32) {
            for (int i = tid; i < 2048; i += 256) {
                int rr = i >> 5, kk = i & 31;
                sa[rr][kk] = r[rr * 512 + k0 + kk];
            }
            for (int i = tid; i < 2048; i += 256) {
                int kk = i >> 6, cc = i & 63;
                sw[kk][cc] = Wr[(size_t)(k0 + kk) * 512 + cb * 64 + cc];
            }
            __syncthreads();
#pragma unroll 8
            for (int kk = 0; kk < 32; kk++) {
                float a = sa[row][kk];
#pragma unroll
                for (int c = 0; c < 16; c++)
                    acc[c] = fmaf(a, sw[kk][cg * 16 + c], acc[c]);
            }
            __syncthreads();
        }
        __half* dst = g_hrh + row * 512 + cb * 64 + cg * 16;
#pragma unroll
        for (int c = 0; c < 16; c += 2)
            *(__half2*)(dst + c) = __floats2half2_rn(acc[c], acc[c + 1]);
    }
}

// ---------------------------------------------------------------------------
// Tensor-core attention, 3 CTAs/SM via phase overlay.
// ---------------------------------------------------------------------------
constexpr int AS_VH = 0;
constexpr int AS_VL = 9216;
constexpr int AS_DYN = 18432;
constexpr int AS_TOTAL = AS_DYN + 17408;
constexpr int ATT_SMEM = AS_TOTAL * 2;            // 71680 B

__global__ __launch_bounds__(256, 3) void attn_kernel() {
    extern __shared__ __align__(16) __half sm[];
    __half* sVh = sm + AS_VH;
    __half* sVl = sm + AS_VL;
    __half* sHq = sm + AS_DYN;
    __half* sKC = sm + AS_DYN + 4608;
    __half* sS  = sm + AS_DYN;
    __half* sW  = sm + AS_DYN + 8320;

    int q0 = blockIdx.x * 64;
    int h = blockIdx.y, b = blockIdx.z;
    int tid = threadIdx.x, lane = tid & 31, wid = tid >> 5;
    int wm = wid >> 1, wn = wid & 1;

    const __half* pb = g_projh + (size_t)(b * Tn + q0) * 2048;

    for (int li = tid; li < 1024; li += 256) {
        int q = li >> 4, d4 = (li & 15) << 2;
        *(uint2*)(sHq + q * 72 + d4) =
            *(const uint2*)(pb + (size_t)(63 + q) * 2048 + 1024 + h * 64 + d4);
    }
    for (int li = tid; li < 2048; li += 256) {
        int j = li >> 4, d4 = (li & 15) << 2;
        __half hv[4];
        if (j < 127) *(uint2*)hv = *(const uint2*)(pb + (size_t)j * 2048 + h * 64 + d4);
        else { hv[0] = hv[1] = hv[2] = hv[3] = __half(0.f); }
        sKC[(d4 + 0) * 200 + j] = hv[0];
        sKC[(d4 + 1) * 200 + j] = hv[1];
        sKC[(d4 + 2) * 200 + j] = hv[2];
        sKC[(d4 + 3) * 200 + j] = hv[3];
    }
    for (int li = tid; li < 1024; li += 256) {
        int c = li >> 4, d4 = (li & 15) << 2;
        __half hv[4];
        *(uint2*)hv = *(const uint2*)(g_hrh + c * 512 + h * 64 + d4);
        sKC[(d4 + 0) * 200 + 128 + c] = hv[0];
        sKC[(d4 + 1) * 200 + 128 + c] = hv[1];
        sKC[(d4 + 2) * 200 + 128 + c] = hv[2];
        sKC[(d4 + 3) * 200 + 128 + c] = hv[3];
    }
    for (int li = tid; li < 2048; li += 256) {
        int j = li >> 4, d4 = (li & 15) << 2;
        uint2 hv = make_uint2(0, 0), lv = make_uint2(0, 0);
        if (j < 127) {
            hv = *(const uint2*)(pb + (size_t)j * 2048 + 512 + h * 64 + d4);
            lv = *(const uint2*)(pb + (size_t)j * 2048 + 1536 + h * 64 + d4);
        }
        *(uint2*)(sVh + j * 72 + d4) = hv;
        *(uint2*)(sVl + j * 72 + d4) = lv;
    }
    __syncthreads();

    uint32_t uHq = smem_u32(sHq), uKC = smem_u32(sKC);
    float sacc[6][2][4] = {};
#pragma unroll
    for (int ks = 0; ks < 4; ks++) {
        uint32_t a[4];
        {
            int r = wm * 16 + (lane & 15);
            int c = (lane >> 4) + ks * 2;
            ldsm4(a, uHq + r * 144 + c * 16);
        }
#pragma unroll
        for (int nf = 0; nf < 6; nf++) {
            uint32_t bb[4];
            int r = (lane & 15) + ks * 16;
            int c = wn * 12 + nf * 2 + (lane >> 4);
            ldsm4t(bb, uKC + r * 400 + c * 16);
            mma_f32(sacc[nf][0], a, bb[0], bb[1]);
            mma_f32(sacc[nf][1], a, bb[2], bb[3]);
        }
    }
    __syncthreads();

    for (int i = tid; i < 64 * 136 / 2; i += 256) ((uint32_t*)sW)[i] = 0;
    {
        int row = wm * 16 + (lane >> 2);
        auto put = [&](int rr, int cc, float v) {
            int rel = cc - rr;
            if (rel >= 0 && rel < 64) sS[rr * 130 + rel] = __float2half_rn(v);
            else if (cc >= 128) sS[rr * 130 + 64 + (cc - 128)] = __float2half_rn(v);
        };
#pragma unroll
        for (int nf = 0; nf < 6; nf++)
#pragma unroll
            for (int sub = 0; sub < 2; sub++) {
                int col = wn * 96 + nf * 16 + sub * 8 + (lane & 3) * 2;
                float* c4 = sacc[nf][sub];
                put(row, col, c4[0]);     put(row, col + 1, c4[1]);
                put(row + 8, col, c4[2]); put(row + 8, col + 1, c4[3]);
            }
    }
    __syncthreads();

    {
        int w = tid >> 5;
#pragma unroll
        for (int rr = 0; rr < 8; rr++) {
            int q = w * 8 + rr;
            int c0 = lane, c1 = lane + 32;
            float s0 = (__half2float(sS[q * 130 + c0]) +
                        __half2float(sS[q * 130 + 64 + c0])) * 0.125f;
            float s1 = (__half2float(sS[q * 130 + c1]) +
                        __half2float(sS[q * 130 + 64 + c1])) * 0.125f;
            int jg0 = q0 + q + c0, jg1 = q0 + q + c1;
            if (jg0 < Cn - 1 && g_mask[b * (Cn - 1) + jg0]) s0 = -1e30f;
            if (jg1 < Cn - 1 && g_mask[b * (Cn - 1) + jg1]) s1 = -1e30f;
            float mx = fmaxf(s0, s1);
#pragma unroll
            for (int o = 16; o; o >>= 1) mx = fmaxf(mx, __shfl_xor_sync(0xffffffffu, mx, o));
            float e0 = __expf(s0 - mx), e1 = __expf(s1 - mx);
            float sum = e0 + e1;
#pragma unroll
            for (int o = 16; o; o >>= 1) sum += __shfl_xor_sync(0xffffffffu, sum, o);
            float inv = 1.f / sum;
            sW[q * 136 + q + c0] = __float2half_rn(e0 * inv);
            sW[q * 136 + q + c1] = __float2half_rn(e1 * inv);
        }
    }
    __syncthreads();

    uint32_t uW = smem_u32(sW), uVh = smem_u32(sVh), uVl = smem_u32(sVl);
    {
        float ohi[4][4] = {};
        uint32_t olo[4][2] = {};
#pragma unroll
        for (int ks = 0; ks < 8; ks++) {
            uint32_t a[4];
            {
                int r = wm * 16 + (lane & 15);
                int c = (lane >> 4) + ks * 2;
                ldsm4(a, uW + r * 272 + c * 16);
            }
#pragma unroll
            for (int nf = 0; nf < 2; nf++) {
                uint32_t bh[4], bl[4];
                int r = (lane & 15) + ks * 16;
                int c = wn * 4 + nf * 2 + (lane >> 4);
                ldsm4t(bh, uVh + r * 144 + c * 16);
                ldsm4t(bl, uVl + r * 144 + c * 16);
                mma_f32(ohi[nf * 2], a, bh[0], bh[1]);
                mma_f32(ohi[nf * 2 + 1], a, bh[2], bh[3]);
                mma_f16(olo[nf * 2], a, bl[0], bl[1]);
                mma_f16(olo[nf * 2 + 1], a, bl[2], bl[3]);
            }
        }
        int row = wm * 16 + (lane >> 2);
#pragma unroll
        for (int n = 0; n < 4; n++) {
            int col = wn * 32 + n * 8 + (lane & 3) * 2;
            float2 l0 = __half22float2(*(__half2*)&olo[n][0]);
            float2 l1 = __half22float2(*(__half2*)&olo[n][1]);
            float o00 = ohi[n][0] + l0.x * INV_SCALE, o01 = ohi[n][1] + l0.y * INV_SCALE;
            float o10 = ohi[n][2] + l1.x * INV_SCALE, o11 = ohi[n][3] + l1.y * INV_SCALE;
#pragma unroll
            for (int rr = 0; rr < 2; rr++) {
                float ox = rr ? o10 : o00, oy = rr ? o11 : o01;
                int q = row + rr * 8;
                __half2 hh = __floats2half2_rn(ox, oy);
                __half2 ll = __floats2half2_rn((ox - __low2float(hh)) * 2048.f,
                                               (oy - __high2float(hh)) * 2048.f);
                __half* dst = g_atth + (size_t)(b * Qn + q0 + q) * KS + h * 64 + col;
                *(__half2*)(dst) = hh;
                *(__half2*)(dst + 512) = ll;
            }
        }
    }
}

}  // namespace

// ---------------------------------------------------------------------------
extern "C" void kernel_launch(void* const* d_in, const int* in_sizes, int n_in,
                              void* d_out, int out_size) {
    const float* x   = (const float*)d_in[0];
    const float* r   = (const float*)d_in[1];
    const float* Wkv = (const float*)d_in[2];
    const float* Wq  = (const float*)d_in[3];
    const float* bq  = (const float*)d_in[4];
    const float* Wr  = (const float*)d_in[5];
    const float* Wo  = (const float*)d_in[6];
    float* out = (float*)d_out;

    float* biasp;
    __half *xh, *atth, *Wh, *Woh, *projh;
    cudaGetSymbolAddress((void**)&biasp, g_bias);
    cudaGetSymbolAddress((void**)&xh,    g_xh);
    cudaGetSymbolAddress((void**)&atth,  g_atth);
    cudaGetSymbolAddress((void**)&Wh,    g_Wh);
    cudaGetSymbolAddress((void**)&Woh,   g_Woh);
    cudaGetSymbolAddress((void**)&projh, g_projh);

    cudaFuncSetAttribute(attn_kernel, cudaFuncAttributeMaxDynamicSharedMemorySize, ATT_SMEM);
    cudaFuncSetAttribute(hgemm_fused_kernel<true, true>,
                         cudaFuncAttributeMaxDynamicSharedMemorySize, HG_SMEM);
    cudaFuncSetAttribute(hgemm_fused_kernel<false, false>,
                         cudaFuncAttributeMaxDynamicSharedMemorySize, HG_SMEM);

    // 1: prep (convX + convW2 + convWo + mask + hr)
    prep_kernel<<<PREP_BLOCKS, 256>>>(x, r, Wkv, Wq, bq, Wr, Wo);
    // 2: proj = x @ [Wkv|Wq] + [0|bq] -> fp16 split layout (lo only for v)
    hgemm_fused_kernel<true, true><<<dim3(24, 33), 256, HG_SMEM>>>(
        xh, Wh, biasp, nullptr, projh, Bn * Tn, 1536);
    // 3: tensor-core attention -> split-fp16 att
    attn_kernel<<<dim3(Qn / 64, Hn, Bn), 256, ATT_SMEM>>>();
    // 4: out = att @ Wo  (fp32 output)
    hgemm_fused_kernel<false, false><<<dim3(8, 32), 256, HG_SMEM>>>(
        atth, Woh, nullptr, out, nullptr, Bn * Qn, 512);
}